// round 2
// baseline (speedup 1.0000x reference)
#include <cuda_runtime.h>
#include <cuda_bf16.h>
#include <math.h>

// Problem constants
#define BB 4
#define TT 1024
#define VV 32000
#define DD 1024
#define HH 16
#define DKK 64
#define BT 4096            // B*T
#define N3 3072            // 3*D (q|k|v)
#define BHN 64             // B*H
#define BTV 131072000LL    // BT*VV

// ---------------- scratch (device globals; no allocation) ----------------
__device__ float g_x[BT * DD];                 // 16 MB  embedded input
__device__ float g_w[DD * N3];                 // 12 MB  repacked [D, 3D] weights
__device__ float g_b3[N3];                     //        repacked bias
__device__ float g_qkv[BT * N3];               // 48 MB  [token][h*64+k | +1024 | +2048]
__device__ float g_scores[(long long)BHN * TT * TT]; // 256 MB scores / probs (in place)
__device__ float g_ao[BT * DD];                // 16 MB  attention out, concat-head layout
__device__ float g_rowloss[BT];

// ---------------- embed: x = tok_emb[ids]*sqrt(D) + pos_emb[t] ----------------
__global__ void k_embed(const int* __restrict__ ids,
                        const float* __restrict__ tok_emb,
                        const float* __restrict__ pos_emb)
{
    int tok = blockIdx.x;              // 0..4095
    int t = tok & (TT - 1);
    int v = ids[tok];
    const float* te = tok_emb + (size_t)v * DD;
    const float* pe = pos_emb + (size_t)t * DD;
    float* xo = g_x + (size_t)tok * DD;
    for (int d = threadIdx.x; d < DD; d += blockDim.x)
        xo[d] = te[d] * 32.0f + pe[d];     // sqrt(1024)=32
}

// ---------------- repack Wq/Wk/Wv [H,D,DK] -> g_w [D, 3D] ----------------
__global__ void k_repack_w(const float* __restrict__ Wq,
                           const float* __restrict__ Wk,
                           const float* __restrict__ Wv)
{
    int idx = blockIdx.x * blockDim.x + threadIdx.x;   // over 1024*3072
    if (idx >= DD * N3) return;
    int d   = idx / N3;
    int col = idx - d * N3;
    int sel = col >> 10;          // 0,1,2
    int c   = col & 1023;
    int h   = c >> 6;
    int k   = c & 63;
    const float* src = (sel == 0) ? Wq : (sel == 1) ? Wk : Wv;
    g_w[idx] = src[(size_t)h * (DD * DKK) + (size_t)d * DKK + k];
}

__global__ void k_repack_b(const float* __restrict__ bq,
                           const float* __restrict__ bk,
                           const float* __restrict__ bv)
{
    int col = blockIdx.x * blockDim.x + threadIdx.x;
    if (col >= N3) return;
    int sel = col >> 10;
    int c   = col & 1023;           // bq is [H,DK] flat = h*64+k = c
    const float* src = (sel == 0) ? bq : (sel == 1) ? bk : bv;
    g_b3[col] = src[c];
}

// ---------------- generic fp32 SGEMM, NN, C = A*B + bias ----------------
// A[M,K] row-major, B[K,N] row-major, C[M,N] row-major.
// BM=BN=128, BK=16, 256 threads, 8x8 per thread. M%128==0, N%128==0, K%16==0.
template<bool HAS_BIAS>
__global__ __launch_bounds__(256, 2)
void k_gemm_nn(int M, int N, int K,
               const float* __restrict__ A, int lda,
               const float* __restrict__ B, int ldb,
               float* __restrict__ C, int ldc,
               const float* __restrict__ bias)
{
    __shared__ __align__(16) float As[16][128];
    __shared__ __align__(16) float Bs[16][128];

    const int tid = threadIdx.x;
    const int tx = tid & 15;        // 0..15  -> N micro
    const int ty = tid >> 4;        // 0..15  -> M micro
    const int bm = blockIdx.y * 128;
    const int bn = blockIdx.x * 128;

    // A load mapping: 2048 elems, 8/thread: row = tid>>1, 8 consecutive cols
    const int arow = tid >> 1;
    const int acol = (tid & 1) * 8;
    // B load mapping: row = tid>>4 (0..15), 8 consecutive cols
    const int brow = tid >> 4;
    const int bcol = (tid & 15) * 8;

    float acc[8][8];
    #pragma unroll
    for (int i = 0; i < 8; i++)
        #pragma unroll
        for (int j = 0; j < 8; j++) acc[i][j] = 0.0f;

    for (int k0 = 0; k0 < K; k0 += 16) {
        // load A tile (transposed into As[k][m])
        const float* ag = A + (size_t)(bm + arow) * lda + k0 + acol;
        #pragma unroll
        for (int i = 0; i < 8; i++)
            As[acol + i][arow] = ag[i];
        // load B tile
        const float* bg = B + (size_t)(k0 + brow) * ldb + bn + bcol;
        #pragma unroll
        for (int i = 0; i < 8; i++)
            Bs[brow][bcol + i] = bg[i];
        __syncthreads();

        #pragma unroll
        for (int kk = 0; kk < 16; kk++) {
            float a[8], b[8];
            *(float4*)&a[0] = *(const float4*)&As[kk][ty * 8];
            *(float4*)&a[4] = *(const float4*)&As[kk][ty * 8 + 4];
            *(float4*)&b[0] = *(const float4*)&Bs[kk][tx * 8];
            *(float4*)&b[4] = *(const float4*)&Bs[kk][tx * 8 + 4];
            #pragma unroll
            for (int i = 0; i < 8; i++)
                #pragma unroll
                for (int j = 0; j < 8; j++)
                    acc[i][j] = fmaf(a[i], b[j], acc[i][j]);
        }
        __syncthreads();
    }

    // epilogue
    #pragma unroll
    for (int i = 0; i < 8; i++) {
        int row = bm + ty * 8 + i;
        float* cr = C + (size_t)row * ldc + bn + tx * 8;
        float4 v0 = make_float4(acc[i][0], acc[i][1], acc[i][2], acc[i][3]);
        float4 v1 = make_float4(acc[i][4], acc[i][5], acc[i][6], acc[i][7]);
        if (HAS_BIAS) {
            const float* bb = bias + bn + tx * 8;
            v0.x += bb[0]; v0.y += bb[1]; v0.z += bb[2]; v0.w += bb[3];
            v1.x += bb[4]; v1.y += bb[5]; v1.z += bb[6]; v1.w += bb[7];
        }
        *(float4*)cr = v0;
        *(float4*)(cr + 4) = v1;
    }
}

// ---------------- scores: S[bh][t][s] = q(b,h,t,:) . k(b,h,s,:) ----------------
// grid: (sTiles=16, tTiles=16, bh=64), 256 threads, 64x64 tile, 4x4 per thread.
__global__ __launch_bounds__(256)
void k_scores()
{
    const int sT = blockIdx.x, tT = blockIdx.y, bh = blockIdx.z;
    if (sT > tT) return;                       // strictly above diagonal: all masked
    const int b = bh >> 4, h = bh & 15;
    const int t0 = tT * 64, s0 = sT * 64;

    __shared__ float Qs[64][65];
    __shared__ float Ks[64][65];

    const int tid = threadIdx.x;
    // cooperative load: 4096 elems each, 16/thread, coalesced over k
    const size_t qbase = ((size_t)(b * TT + t0)) * N3 + h * 64;          // q
    const size_t kbase = ((size_t)(b * TT + s0)) * N3 + 1024 + h * 64;   // k
    #pragma unroll
    for (int i = 0; i < 16; i++) {
        int e = i * 256 + tid;
        int r = e >> 6, c = e & 63;
        Qs[r][c] = g_qkv[qbase + (size_t)r * N3 + c];
        Ks[r][c] = g_qkv[kbase + (size_t)r * N3 + c];
    }
    __syncthreads();

    const int tm = (tid >> 4) * 4;   // row base
    const int tn = (tid & 15) * 4;   // col base
    float acc[4][4] = {};
    #pragma unroll
    for (int kk = 0; kk < 64; kk++) {
        float a[4], bb[4];
        #pragma unroll
        for (int i = 0; i < 4; i++) a[i]  = Qs[tm + i][kk];
        #pragma unroll
        for (int j = 0; j < 4; j++) bb[j] = Ks[tn + j][kk];
        #pragma unroll
        for (int i = 0; i < 4; i++)
            #pragma unroll
            for (int j = 0; j < 4; j++)
                acc[i][j] = fmaf(a[i], bb[j], acc[i][j]);
    }

    float* S = g_scores + (size_t)bh * TT * TT;
    #pragma unroll
    for (int i = 0; i < 4; i++) {
        float* row = S + (size_t)(t0 + tm + i) * TT + s0 + tn;
        row[0] = acc[i][0]; row[1] = acc[i][1]; row[2] = acc[i][2]; row[3] = acc[i][3];
    }
}

// ---------------- softmax over each row (causal; mask->exact 0) ----------------
// grid: (T, BH), 256 threads. p = softmax(S/8) over s<=t ; p=0 for s>t.
__global__ __launch_bounds__(256)
void k_softmax()
{
    const int t = blockIdx.x, bh = blockIdx.y;
    float* row = g_scores + (size_t)bh * TT * TT + (size_t)t * TT;
    const int n = t + 1;
    const int tid = threadIdx.x;
    __shared__ float red[256];

    float m = -INFINITY;
    for (int i = tid; i < n; i += 256) m = fmaxf(m, row[i] * 0.125f);
    red[tid] = m; __syncthreads();
    for (int s = 128; s > 0; s >>= 1) {
        if (tid < s) red[tid] = fmaxf(red[tid], red[tid + s]);
        __syncthreads();
    }
    m = red[0]; __syncthreads();

    float sum = 0.0f;
    for (int i = tid; i < n; i += 256) sum += __expf(fminf(row[i] * 0.125f - m, 0.0f));
    red[tid] = sum; __syncthreads();
    for (int s = 128; s > 0; s >>= 1) {
        if (tid < s) red[tid] += red[tid + s];
        __syncthreads();
    }
    const float inv = 1.0f / red[0];

    for (int i = tid; i < n; i += 256) row[i] = __expf(fminf(row[i] * 0.125f - m, 0.0f)) * inv;
    for (int i = n + tid; i < TT; i += 256) row[i] = 0.0f;
}

// ---------------- PV: out[b,t][h*64+k] = sum_s P[t][s] * v[b,h,s,k] ----------------
// grid: (tTiles=16, bh=64), 256 threads, 64(t) x 64(k) tile, 4x4 per thread.
__global__ __launch_bounds__(256)
void k_pv()
{
    const int tT = blockIdx.x, bh = blockIdx.y;
    const int b = bh >> 4, h = bh & 15;
    const int t0 = tT * 64;

    __shared__ float Ps[64][65];
    __shared__ float Vs[64][65];

    const int tid = threadIdx.x;
    const int tm = (tid >> 4) * 4;
    const int tn = (tid & 15) * 4;
    float acc[4][4] = {};

    const float* P = g_scores + (size_t)bh * TT * TT;

    for (int s0 = 0; s0 <= t0; s0 += 64) {
        #pragma unroll
        for (int i = 0; i < 16; i++) {
            int e = i * 256 + tid;
            int r = e >> 6, c = e & 63;
            Ps[r][c] = P[(size_t)(t0 + r) * TT + s0 + c];
            Vs[r][c] = g_qkv[((size_t)(b * TT + s0 + r)) * N3 + 2048 + h * 64 + c];
        }
        __syncthreads();
        #pragma unroll
        for (int ss = 0; ss < 64; ss++) {
            float a[4], bb[4];
            #pragma unroll
            for (int i = 0; i < 4; i++) a[i]  = Ps[tm + i][ss];
            #pragma unroll
            for (int j = 0; j < 4; j++) bb[j] = Vs[ss][tn + j];
            #pragma unroll
            for (int i = 0; i < 4; i++)
                #pragma unroll
                for (int j = 0; j < 4; j++)
                    acc[i][j] = fmaf(a[i], bb[j], acc[i][j]);
        }
        __syncthreads();
    }

    #pragma unroll
    for (int i = 0; i < 4; i++) {
        float* o = g_ao + ((size_t)(b * TT + t0 + tm + i)) * DD + h * 64 + tn;
        o[0] = acc[i][0]; o[1] = acc[i][1]; o[2] = acc[i][2]; o[3] = acc[i][3];
    }
}

// ---------------- loss: per-row -log_softmax(logits)[target] ----------------
__global__ __launch_bounds__(256)
void k_loss_rows(const float* __restrict__ logits, const int* __restrict__ targets)
{
    const int r = blockIdx.x;
    const float* row = logits + (size_t)r * VV;
    const int tid = threadIdx.x;
    __shared__ float red[256];

    float m = -INFINITY;
    for (int i = tid; i < VV; i += 256) m = fmaxf(m, row[i]);
    red[tid] = m; __syncthreads();
    for (int s = 128; s > 0; s >>= 1) {
        if (tid < s) red[tid] = fmaxf(red[tid], red[tid + s]);
        __syncthreads();
    }
    m = red[0]; __syncthreads();

    float sum = 0.0f;
    for (int i = tid; i < VV; i += 256) sum += __expf(row[i] - m);
    red[tid] = sum; __syncthreads();
    for (int s = 128; s > 0; s >>= 1) {
        if (tid < s) red[tid] += red[tid + s];
        __syncthreads();
    }
    if (tid == 0) {
        int tgt = targets[r];
        float logp = row[tgt] - m - __logf(red[0]);
        g_rowloss[r] = -logp;
    }
}

__global__ void k_loss_final(float* out)
{
    const int tid = threadIdx.x;
    __shared__ float red[256];
    float s = 0.0f;
    for (int i = tid; i < BT; i += 256) s += g_rowloss[i];
    red[tid] = s; __syncthreads();
    for (int k = 128; k > 0; k >>= 1) {
        if (tid < k) red[tid] += red[tid + k];
        __syncthreads();
    }
    if (tid == 0) out[0] = red[0] * (1.0f / BT);
}

// ---------------- launch ----------------
extern "C" void kernel_launch(void* const* d_in, const int* in_sizes, int n_in,
                              void* d_out, int out_size)
{
    const int*   ids     = (const int*)  d_in[0];
    const int*   targets = (const int*)  d_in[1];
    const float* tok_emb = (const float*)d_in[2];
    const float* pos_emb = (const float*)d_in[3];
    const float* Wq      = (const float*)d_in[4];
    const float* bq      = (const float*)d_in[5];
    const float* Wk      = (const float*)d_in[6];
    const float* bk      = (const float*)d_in[7];
    const float* Wv      = (const float*)d_in[8];
    const float* bv      = (const float*)d_in[9];
    const float* Wo      = (const float*)d_in[10];
    const float* bo      = (const float*)d_in[11];
    float* out = (float*)d_out;

    float *px, *pw, *pb3, *pqkv, *pao;
    cudaGetSymbolAddress((void**)&px,   g_x);
    cudaGetSymbolAddress((void**)&pw,   g_w);
    cudaGetSymbolAddress((void**)&pb3,  g_b3);
    cudaGetSymbolAddress((void**)&pqkv, g_qkv);
    cudaGetSymbolAddress((void**)&pao,  g_ao);

    // 1. embed
    k_embed<<<BT, 256>>>(ids, tok_emb, pos_emb);

    // 2. repack weights / bias
    k_repack_w<<<(DD * N3 + 255) / 256, 256>>>(Wq, Wk, Wv);
    k_repack_b<<<(N3 + 255) / 256, 256>>>(bq, bk, bv);

    // 3. QKV projection: [4096,1024] x [1024,3072]
    k_gemm_nn<true><<<dim3(N3 / 128, BT / 128), 256>>>(
        BT, N3, DD, px, DD, pw, N3, pqkv, N3, pb3);

    // 4. attention
    k_scores <<<dim3(16, 16, BHN), 256>>>();
    k_softmax<<<dim3(TT, BHN), 256>>>();
    k_pv     <<<dim3(16, BHN), 256>>>();

    // 5. logits: [4096,1024] x [1024,32000] + bo -> d_out
    k_gemm_nn<true><<<dim3(VV / 128, BT / 128), 256>>>(
        BT, VV, DD, pao, DD, Wo, VV, out, VV, bo);

    // 6. loss
    if ((long long)out_size > BTV) {
        k_loss_rows<<<BT, 256>>>(out, targets);
        k_loss_final<<<1, 256>>>(out + BTV);
    }
}

// round 6
// speedup vs baseline: 1.6277x; 1.6277x over previous
#include <cuda_runtime.h>
#include <cuda_bf16.h>
#include <math.h>
#include <stdint.h>

// Problem constants
#define BB 4
#define TT 1024
#define VV 32000
#define DD 1024
#define HH 16
#define DKK 64
#define BT 4096            // B*T
#define N3 3072            // 3*D (q|k|v)
#define BHN 64             // B*H
#define BTV 131072000LL    // BT*VV

// ---------------- scratch (device globals; no allocation) ----------------
__device__ float g_x[BT * DD];                 // 16 MB  embedded input
__device__ float g_b3[N3];                     //        repacked qkv bias
__device__ float g_qkv[BT * N3];               // 48 MB  [token][h*64+k | +1024 | +2048]
__device__ float g_scores[(long long)BHN * TT * TT]; // 256 MB scores / probs (in place)
__device__ float g_ao[BT * DD];                // 16 MB  attention out, concat-head layout
__device__ float g_rowloss[BT];

// bf16 split operands for tensor-core GEMMs
__device__ __nv_bfloat16 g_ah[BT * DD];        // 8 MB   A hi
__device__ __nv_bfloat16 g_al[BT * DD];        // 8 MB   A lo
__device__ __nv_bfloat16 g_bh[(size_t)VV * DD];// 64 MB  B hi (K-major [N,K]) - reused
__device__ __nv_bfloat16 g_bl[(size_t)VV * DD];// 64 MB  B lo

// ================= helpers =================
__device__ __forceinline__ uint32_t smem_to_u32(const void* p) {
    uint32_t a;
    asm("{ .reg .u64 t; cvta.to.shared.u64 t, %1; cvt.u32.u64 %0, t; }" : "=r"(a) : "l"(p));
    return a;
}
__device__ __forceinline__ void cp16(uint32_t saddr, const void* gptr) {
    asm volatile("cp.async.cg.shared.global [%0], [%1], 16;" :: "r"(saddr), "l"(gptr));
}
__device__ __forceinline__ void mma16816(float* c,
                                         uint32_t a0, uint32_t a1, uint32_t a2, uint32_t a3,
                                         uint32_t b0, uint32_t b1)
{
    asm volatile(
        "mma.sync.aligned.m16n8k16.row.col.f32.bf16.bf16.f32 "
        "{%0,%1,%2,%3}, {%4,%5,%6,%7}, {%8,%9}, {%0,%1,%2,%3};"
        : "+f"(c[0]), "+f"(c[1]), "+f"(c[2]), "+f"(c[3])
        : "r"(a0), "r"(a1), "r"(a2), "r"(a3), "r"(b0), "r"(b1));
}

// ================= HMMA GEMM: C[M,N] = A[M,K] * B[N,K]^T + bias =================
// bf16x3 split: Ahi*Bhi + Ahi*Blo + Alo*Bhi, fp32 accumulate in registers.
// CTA tile 128x128, BK=32, 256 threads (8 warps of 64x32). cp.async double buffer.
// Smem stage: 4 arrays of [128 rows][80B pitch] (32 bf16 data + 16B pad).
#define PITCH 80
#define ARR_BYTES (128 * PITCH)        // 10240
#define STAGE_BYTES (4 * ARR_BYTES)    // 40960
#define GEMM_SMEM (2 * STAGE_BYTES)    // 81920
#define OFF_AH 0
#define OFF_AL ARR_BYTES
#define OFF_BH (2 * ARR_BYTES)
#define OFF_BL (3 * ARR_BYTES)

__global__ __launch_bounds__(256, 1)
void k_gemm_mma(int M, int N, int K,
                const __nv_bfloat16* __restrict__ Ahi, const __nv_bfloat16* __restrict__ Alo,
                const __nv_bfloat16* __restrict__ Bhi, const __nv_bfloat16* __restrict__ Blo,
                float* __restrict__ C, int ldc, const float* __restrict__ bias)
{
    extern __shared__ char smem[];
    const uint32_t sbase = smem_to_u32(smem);
    const int tid = threadIdx.x;
    const int wid = tid >> 5, lid = tid & 31;
    const int g = lid >> 2, tig = lid & 3;
    const int wm = (wid >> 2) * 64;      // warp M offset (0 or 64)
    const int wn = (wid & 3) * 32;       // warp N offset (0,32,64,96)
    const int bm = blockIdx.x * 128;     // M fastest -> concurrent CTAs share B tile
    const int bn = blockIdx.y * 128;

    const int nchunks = K >> 5;

    // global load base for this thread: two 16B chunks per array per stage
    // chunk id c = i*256 + tid : row = c>>2, col16 = c&3
    const int r0 = tid >> 2, c0b = (tid & 3);          // i=0
    const int r1 = (256 + tid) >> 2, c1b = tid & 3;    // i=1 (rows 64..127)

    float acc[4][4][4];
    #pragma unroll
    for (int i = 0; i < 4; i++)
        #pragma unroll
        for (int j = 0; j < 4; j++)
            #pragma unroll
            for (int q = 0; q < 4; q++) acc[i][j][q] = 0.0f;

    // ---- stage loader ----
    auto load_stage = [&](int buf, int chunk) {
        const int k0 = chunk << 5;
        const uint32_t st = sbase + buf * STAGE_BYTES;
        // A
        {
            const __nv_bfloat16* Ah = Ahi + (size_t)(bm + r0) * K + k0 + c0b * 8;
            const __nv_bfloat16* Al = Alo + (size_t)(bm + r0) * K + k0 + c0b * 8;
            uint32_t sa = st + r0 * PITCH + c0b * 16;
            cp16(sa + OFF_AH, Ah);
            cp16(sa + OFF_AL, Al);
            const __nv_bfloat16* Ah1 = Ahi + (size_t)(bm + r1) * K + k0 + c1b * 8;
            const __nv_bfloat16* Al1 = Alo + (size_t)(bm + r1) * K + k0 + c1b * 8;
            uint32_t sa1 = st + r1 * PITCH + c1b * 16;
            cp16(sa1 + OFF_AH, Ah1);
            cp16(sa1 + OFF_AL, Al1);
        }
        // B
        {
            const __nv_bfloat16* Bh = Bhi + (size_t)(bn + r0) * K + k0 + c0b * 8;
            const __nv_bfloat16* Bl = Blo + (size_t)(bn + r0) * K + k0 + c0b * 8;
            uint32_t sb = st + r0 * PITCH + c0b * 16;
            cp16(sb + OFF_BH, Bh);
            cp16(sb + OFF_BL, Bl);
            const __nv_bfloat16* Bh1 = Bhi + (size_t)(bn + r1) * K + k0 + c1b * 8;
            const __nv_bfloat16* Bl1 = Blo + (size_t)(bn + r1) * K + k0 + c1b * 8;
            uint32_t sb1 = st + r1 * PITCH + c1b * 16;
            cp16(sb1 + OFF_BH, Bh1);
            cp16(sb1 + OFF_BL, Bl1);
        }
    };

    load_stage(0, 0);
    asm volatile("cp.async.commit_group;");

    for (int chunk = 0; chunk < nchunks; chunk++) {
        const int buf = chunk & 1;
        if (chunk + 1 < nchunks) {
            load_stage(buf ^ 1, chunk + 1);
            asm volatile("cp.async.commit_group;");
            asm volatile("cp.async.wait_group 1;");
        } else {
            asm volatile("cp.async.wait_group 0;");
        }
        __syncthreads();

        const char* st = smem + buf * STAGE_BYTES;
        const char* sAh = st + OFF_AH;
        const char* sAl = st + OFF_AL;
        const char* sBh = st + OFF_BH;
        const char* sBl = st + OFF_BL;

        #pragma unroll
        for (int ks = 0; ks < 2; ks++) {
            const int colb  = ks * 32 + tig * 4;     // byte offset of this lane's k-pair
            // A fragments: 4 M-tiles, hi + lo
            uint32_t Afh[4][4], Afl[4][4];
            #pragma unroll
            for (int mt = 0; mt < 4; mt++) {
                const int ra = (wm + mt * 16 + g) * PITCH;
                const int rb = (wm + mt * 16 + g + 8) * PITCH;
                Afh[mt][0] = *(const uint32_t*)(sAh + ra + colb);
                Afh[mt][1] = *(const uint32_t*)(sAh + rb + colb);
                Afh[mt][2] = *(const uint32_t*)(sAh + ra + colb + 16);
                Afh[mt][3] = *(const uint32_t*)(sAh + rb + colb + 16);
                Afl[mt][0] = *(const uint32_t*)(sAl + ra + colb);
                Afl[mt][1] = *(const uint32_t*)(sAl + rb + colb);
                Afl[mt][2] = *(const uint32_t*)(sAl + ra + colb + 16);
                Afl[mt][3] = *(const uint32_t*)(sAl + rb + colb + 16);
            }
            // B fragments: 4 N-tiles, hi + lo
            uint32_t Bfh[4][2], Bfl[4][2];
            #pragma unroll
            for (int nt = 0; nt < 4; nt++) {
                const int rn = (wn + nt * 8 + g) * PITCH;
                Bfh[nt][0] = *(const uint32_t*)(sBh + rn + colb);
                Bfh[nt][1] = *(const uint32_t*)(sBh + rn + colb + 16);
                Bfl[nt][0] = *(const uint32_t*)(sBl + rn + colb);
                Bfl[nt][1] = *(const uint32_t*)(sBl + rn + colb + 16);
            }
            #pragma unroll
            for (int mt = 0; mt < 4; mt++)
                #pragma unroll
                for (int nt = 0; nt < 4; nt++) {
                    mma16816(acc[mt][nt], Afh[mt][0], Afh[mt][1], Afh[mt][2], Afh[mt][3],
                             Bfh[nt][0], Bfh[nt][1]);
                    mma16816(acc[mt][nt], Afh[mt][0], Afh[mt][1], Afh[mt][2], Afh[mt][3],
                             Bfl[nt][0], Bfl[nt][1]);
                    mma16816(acc[mt][nt], Afl[mt][0], Afl[mt][1], Afl[mt][2], Afl[mt][3],
                             Bfh[nt][0], Bfh[nt][1]);
                }
        }
        __syncthreads();
    }

    // epilogue: c0,c1 at (row g, col 2*tig), c2,c3 at row g+8
    #pragma unroll
    for (int mt = 0; mt < 4; mt++) {
        const int row = bm + wm + mt * 16 + g;
        #pragma unroll
        for (int nt = 0; nt < 4; nt++) {
            const int col = bn + wn + nt * 8 + tig * 2;
            const float b0 = bias[col], b1 = bias[col + 1];
            float* p0 = C + (size_t)row * ldc + col;
            float* p1 = C + (size_t)(row + 8) * ldc + col;
            p0[0] = acc[mt][nt][0] + b0;
            p0[1] = acc[mt][nt][1] + b1;
            p1[0] = acc[mt][nt][2] + b0;
            p1[1] = acc[mt][nt][3] + b1;
        }
    }
}

// ---------------- embed: x = tok_emb[ids]*sqrt(D) + pos_emb[t] ----------------
__global__ void k_embed(const int* __restrict__ ids,
                        const float* __restrict__ tok_emb,
                        const float* __restrict__ pos_emb)
{
    int tok = blockIdx.x;
    int t = tok & (TT - 1);
    int v = ids[tok];
    const float* te = tok_emb + (size_t)v * DD;
    const float* pe = pos_emb + (size_t)t * DD;
    float* xo = g_x + (size_t)tok * DD;
    for (int d = threadIdx.x; d < DD; d += blockDim.x)
        xo[d] = te[d] * 32.0f + pe[d];
}

// ---------------- fp32 -> bf16 hi/lo split ----------------
__global__ void k_cvt(const float* __restrict__ src,
                      __nv_bfloat16* __restrict__ hi, __nv_bfloat16* __restrict__ lo, int n)
{
    int i = blockIdx.x * blockDim.x + threadIdx.x;
    if (i >= n) return;
    float x = src[i];
    __nv_bfloat16 h = __float2bfloat16_rn(x);
    hi[i] = h;
    lo[i] = __float2bfloat16_rn(x - __bfloat162float(h));
}

// ---------------- repack Wq/Wk/Wv -> K-major bf16 hi/lo [3072, 1024] ----------------
__global__ void k_repack_wqkv(const float* __restrict__ Wq,
                              const float* __restrict__ Wk,
                              const float* __restrict__ Wv)
{
    int n = blockIdx.x;                 // output row (qkv col) 0..3071
    int sel = n >> 10, c = n & 1023, h = c >> 6, k = c & 63;
    const float* src = (sel == 0) ? Wq : (sel == 1) ? Wk : Wv;
    const float* col = src + (size_t)h * (DD * DKK) + k;   // stride DKK over d
    __nv_bfloat16* oh = g_bh + (size_t)n * DD;
    __nv_bfloat16* ol = g_bl + (size_t)n * DD;
    for (int d = threadIdx.x; d < DD; d += blockDim.x) {
        float x = col[(size_t)d * DKK];
        __nv_bfloat16 hh = __float2bfloat16_rn(x);
        oh[d] = hh;
        ol[d] = __float2bfloat16_rn(x - __bfloat162float(hh));
    }
}

__global__ void k_repack_b(const float* __restrict__ bq,
                           const float* __restrict__ bk,
                           const float* __restrict__ bv)
{
    int col = blockIdx.x * blockDim.x + threadIdx.x;
    if (col >= N3) return;
    int sel = col >> 10, c = col & 1023;
    const float* src = (sel == 0) ? bq : (sel == 1) ? bk : bv;
    g_b3[col] = src[c];
}

// ---------------- transpose + split Wo [1024, 32000] -> [32000, 1024] bf16 hi/lo ----------------
__global__ void k_woT(const float* __restrict__ Wo)
{
    __shared__ float s[32][33];
    int v0 = blockIdx.x * 32, d0 = blockIdx.y * 32;
    int tx = threadIdx.x, ty = threadIdx.y;  // block (32, 8)
    #pragma unroll
    for (int i = 0; i < 4; i++)
        s[ty + i * 8][tx] = Wo[(size_t)(d0 + ty + i * 8) * VV + v0 + tx];
    __syncthreads();
    #pragma unroll
    for (int i = 0; i < 4; i++) {
        int v = v0 + ty + i * 8;
        int d = d0 + tx;
        float x = s[tx][ty + i * 8];
        __nv_bfloat16 h = __float2bfloat16_rn(x);
        g_bh[(size_t)v * DD + d] = h;
        g_bl[(size_t)v * DD + d] = __float2bfloat16_rn(x - __bfloat162float(h));
    }
}

// ---------------- scores: S[bh][t][s] = q . k (fp32, 64x64 tiles) ----------------
__global__ __launch_bounds__(256)
void k_scores()
{
    const int sT = blockIdx.x, tT = blockIdx.y, bh = blockIdx.z;
    if (sT > tT) return;
    const int b = bh >> 4, h = bh & 15;
    const int t0 = tT * 64, s0 = sT * 64;

    __shared__ float Qs[64][65];
    __shared__ float Ks[64][65];

    const int tid = threadIdx.x;
    const size_t qbase = ((size_t)(b * TT + t0)) * N3 + h * 64;
    const size_t kbase = ((size_t)(b * TT + s0)) * N3 + 1024 + h * 64;
    #pragma unroll
    for (int i = 0; i < 16; i++) {
        int e = i * 256 + tid;
        int r = e >> 6, c = e & 63;
        Qs[r][c] = g_qkv[qbase + (size_t)r * N3 + c];
        Ks[r][c] = g_qkv[kbase + (size_t)r * N3 + c];
    }
    __syncthreads();

    const int tm = (tid >> 4) * 4;
    const int tn = (tid & 15) * 4;
    float acc[4][4] = {};
    #pragma unroll
    for (int kk = 0; kk < 64; kk++) {
        float a[4], bb[4];
        #pragma unroll
        for (int i = 0; i < 4; i++) a[i]  = Qs[tm + i][kk];
        #pragma unroll
        for (int j = 0; j < 4; j++) bb[j] = Ks[tn + j][kk];
        #pragma unroll
        for (int i = 0; i < 4; i++)
            #pragma unroll
            for (int j = 0; j < 4; j++)
                acc[i][j] = fmaf(a[i], bb[j], acc[i][j]);
    }

    float* S = g_scores + (size_t)bh * TT * TT;
    #pragma unroll
    for (int i = 0; i < 4; i++) {
        float* row = S + (size_t)(t0 + tm + i) * TT + s0 + tn;
        row[0] = acc[i][0]; row[1] = acc[i][1]; row[2] = acc[i][2]; row[3] = acc[i][3];
    }
}

// ---------------- softmax per row (causal -> exact zeros above diag) ----------------
__global__ __launch_bounds__(256)
void k_softmax()
{
    const int t = blockIdx.x, bh = blockIdx.y;
    float* row = g_scores + (size_t)bh * TT * TT + (size_t)t * TT;
    const int n = t + 1;
    const int tid = threadIdx.x;
    __shared__ float red[256];

    float m = -INFINITY;
    for (int i = tid; i < n; i += 256) m = fmaxf(m, row[i] * 0.125f);
    red[tid] = m; __syncthreads();
    for (int s = 128; s > 0; s >>= 1) {
        if (tid < s) red[tid] = fmaxf(red[tid], red[tid + s]);
        __syncthreads();
    }
    m = red[0]; __syncthreads();

    float sum = 0.0f;
    for (int i = tid; i < n; i += 256) sum += __expf(fminf(row[i] * 0.125f - m, 0.0f));
    red[tid] = sum; __syncthreads();
    for (int s = 128; s > 0; s >>= 1) {
        if (tid < s) red[tid] += red[tid + s];
        __syncthreads();
    }
    const float inv = 1.0f / red[0];

    for (int i = tid; i < n; i += 256) row[i] = __expf(fminf(row[i] * 0.125f - m, 0.0f)) * inv;
    for (int i = n + tid; i < TT; i += 256) row[i] = 0.0f;
}

// ---------------- PV (fp32, 64x64 tiles over lower triangle) ----------------
__global__ __launch_bounds__(256)
void k_pv()
{
    const int tT = blockIdx.x, bh = blockIdx.y;
    const int b = bh >> 4, h = bh & 15;
    const int t0 = tT * 64;

    __shared__ float Ps[64][65];
    __shared__ float Vs[64][65];

    const int tid = threadIdx.x;
    const int tm = (tid >> 4) * 4;
    const int tn = (tid & 15) * 4;
    float acc[4][4] = {};

    const float* P = g_scores + (size_t)bh * TT * TT;

    for (int s0 = 0; s0 <= t0; s0 += 64) {
        #pragma unroll
        for (int i = 0; i < 16; i++) {
            int e = i * 256 + tid;
            int r = e >> 6, c = e & 63;
            Ps[r][c] = P[(size_t)(t0 + r) * TT + s0 + c];
            Vs[r][c] = g_qkv[((size_t)(b * TT + s0 + r)) * N3 + 2048 + h * 64 + c];
        }
        __syncthreads();
        #pragma unroll
        for (int ss = 0; ss < 64; ss++) {
            float a[4], bb[4];
            #pragma unroll
            for (int i = 0; i < 4; i++) a[i]  = Ps[tm + i][ss];
            #pragma unroll
            for (int j = 0; j < 4; j++) bb[j] = Vs[ss][tn + j];
            #pragma unroll
            for (int i = 0; i < 4; i++)
                #pragma unroll
                for (int j = 0; j < 4; j++)
                    acc[i][j] = fmaf(a[i], bb[j], acc[i][j]);
        }
        __syncthreads();
    }

    #pragma unroll
    for (int i = 0; i < 4; i++) {
        float* o = g_ao + ((size_t)(b * TT + t0 + tm + i)) * DD + h * 64 + tn;
        o[0] = acc[i][0]; o[1] = acc[i][1]; o[2] = acc[i][2]; o[3] = acc[i][3];
    }
}

// ---------------- loss ----------------
__global__ __launch_bounds__(256)
void k_loss_rows(const float* __restrict__ logits, const int* __restrict__ targets)
{
    const int r = blockIdx.x;
    const float* row = logits + (size_t)r * VV;
    const int tid = threadIdx.x;
    __shared__ float red[256];

    float m = -INFINITY;
    for (int i = tid; i < VV; i += 256) m = fmaxf(m, row[i]);
    red[tid] = m; __syncthreads();
    for (int s = 128; s > 0; s >>= 1) {
        if (tid < s) red[tid] = fmaxf(red[tid], red[tid + s]);
        __syncthreads();
    }
    m = red[0]; __syncthreads();

    float sum = 0.0f;
    for (int i = tid; i < VV; i += 256) sum += __expf(row[i] - m);
    red[tid] = sum; __syncthreads();
    for (int s = 128; s > 0; s >>= 1) {
        if (tid < s) red[tid] += red[tid + s];
        __syncthreads();
    }
    if (tid == 0) {
        int tgt = targets[r];
        float logp = row[tgt] - m - __logf(red[0]);
        g_rowloss[r] = -logp;
    }
}

__global__ void k_loss_final(float* out)
{
    const int tid = threadIdx.x;
    __shared__ float red[256];
    float s = 0.0f;
    for (int i = tid; i < BT; i += 256) s += g_rowloss[i];
    red[tid] = s; __syncthreads();
    for (int k = 128; k > 0; k >>= 1) {
        if (tid < k) red[tid] += red[tid + k];
        __syncthreads();
    }
    if (tid == 0) out[0] = red[0] * (1.0f / BT);
}

// ---------------- launch ----------------
extern "C" void kernel_launch(void* const* d_in, const int* in_sizes, int n_in,
                              void* d_out, int out_size)
{
    const int*   ids     = (const int*)  d_in[0];
    const int*   targets = (const int*)  d_in[1];
    const float* tok_emb = (const float*)d_in[2];
    const float* pos_emb = (const float*)d_in[3];
    const float* Wq      = (const float*)d_in[4];
    const float* bq      = (const float*)d_in[5];
    const float* Wk      = (const float*)d_in[6];
    const float* bk      = (const float*)d_in[7];
    const float* Wv      = (const float*)d_in[8];
    const float* bv      = (const float*)d_in[9];
    const float* Wo      = (const float*)d_in[10];
    const float* bo      = (const float*)d_in[11];
    float* out = (float*)d_out;

    float *px, *pb3, *pqkv, *pao;
    __nv_bfloat16 *pah, *pal, *pbh, *pbl;
    cudaGetSymbolAddress((void**)&px,   g_x);
    cudaGetSymbolAddress((void**)&pb3,  g_b3);
    cudaGetSymbolAddress((void**)&pqkv, g_qkv);
    cudaGetSymbolAddress((void**)&pao,  g_ao);
    cudaGetSymbolAddress((void**)&pah,  g_ah);
    cudaGetSymbolAddress((void**)&pal,  g_al);
    cudaGetSymbolAddress((void**)&pbh,  g_bh);
    cudaGetSymbolAddress((void**)&pbl,  g_bl);

    cudaFuncSetAttribute(k_gemm_mma, cudaFuncAttributeMaxDynamicSharedMemorySize,
                         GEMM_SMEM);

    // 1. embed + split A
    k_embed<<<BT, 256>>>(ids, tok_emb, pos_emb);
    k_cvt<<<(BT * DD + 255) / 256, 256>>>(px, pah, pal, BT * DD);

    // 2. repack QKV weights (K-major bf16 hi/lo) + bias
    k_repack_wqkv<<<N3, 256>>>(Wq, Wk, Wv);
    k_repack_b<<<(N3 + 255) / 256, 256>>>(bq, bk, bv);

    // 3. QKV projection: [4096,1024] x [1024,3072]  (grid: M fastest)
    k_gemm_mma<<<dim3(BT / 128, N3 / 128), 256, GEMM_SMEM>>>(
        BT, N3, DD, pah, pal, pbh, pbl, pqkv, N3, pb3);

    // 4. attention (fp32)
    k_scores <<<dim3(16, 16, BHN), 256>>>();
    k_softmax<<<dim3(TT, BHN), 256>>>();
    k_pv     <<<dim3(16, BHN), 256>>>();

    // 5. logits: [4096,1024] x [1024,32000] + bo  (grid: M fastest)
    k_cvt<<<(BT * DD + 255) / 256, 256>>>(pao, pah, pal, BT * DD);
    k_woT<<<dim3(VV / 32, DD / 32), dim3(32, 8)>>>(Wo);
    k_gemm_mma<<<dim3(BT / 128, VV / 128), 256, GEMM_SMEM>>>(
        BT, VV, DD, pah, pal, pbh, pbl, out, VV, bo);

    // 6. loss
    if ((long long)out_size > BTV) {
        k_loss_rows<<<BT, 256>>>(out, targets);
        k_loss_final<<<1, 256>>>(out + BTV);
    }
}

// round 7
// speedup vs baseline: 4.4628x; 2.7418x over previous
#include <cuda_runtime.h>
#include <cuda_bf16.h>
#include <cuda_fp16.h>
#include <math.h>
#include <stdint.h>

// Problem constants
#define BB 4
#define TT 1024
#define VV 32000
#define DD 1024
#define HH 16
#define DKK 64
#define BT 4096            // B*T
#define N3 3072            // 3*D (q|k|v)
#define BHN 64             // B*H
#define BTV 131072000LL    // BT*VV

// ---------------- scratch (device globals; no allocation) ----------------
__device__ float g_b3[N3];                       // repacked qkv bias
__device__ float g_qkv[BT * N3];                 // 48 MB [token][h*64+k | +1024 | +2048]
__device__ float g_scores[(long long)BHN * TT * TT]; // 256 MB scores/probs in place
__device__ float g_rowloss[BT];

__device__ __nv_bfloat16 g_ah[BT * DD];          // x hi (QKV A operand)
__device__ __nv_bfloat16 g_al[BT * DD];          // x lo
__device__ __nv_bfloat16 g_bh[N3 * DD];          // Wqkv hi (K-major [3072,1024])
__device__ __nv_bfloat16 g_bl[N3 * DD];          // Wqkv lo

__device__ __half g_ha[BT * DD];                 // attention-out fp16 (logits A)
__device__ __half g_hb[(size_t)VV * DD];         // Wo^T fp16 (K-major [32000,1024])

// ================= helpers =================
__device__ __forceinline__ uint32_t smem_to_u32(const void* p) {
    uint32_t a;
    asm("{ .reg .u64 t; cvta.to.shared.u64 t, %1; cvt.u32.u64 %0, t; }" : "=r"(a) : "l"(p));
    return a;
}
__device__ __forceinline__ void cp16(uint32_t saddr, const void* gptr) {
    asm volatile("cp.async.cg.shared.global [%0], [%1], 16;" :: "r"(saddr), "l"(gptr));
}
__device__ __forceinline__ void mma_bf16(float* c,
                                         uint32_t a0, uint32_t a1, uint32_t a2, uint32_t a3,
                                         uint32_t b0, uint32_t b1)
{
    asm volatile(
        "mma.sync.aligned.m16n8k16.row.col.f32.bf16.bf16.f32 "
        "{%0,%1,%2,%3}, {%4,%5,%6,%7}, {%8,%9}, {%0,%1,%2,%3};"
        : "+f"(c[0]), "+f"(c[1]), "+f"(c[2]), "+f"(c[3])
        : "r"(a0), "r"(a1), "r"(a2), "r"(a3), "r"(b0), "r"(b1));
}
__device__ __forceinline__ void mma_f16(float* c,
                                        uint32_t a0, uint32_t a1, uint32_t a2, uint32_t a3,
                                        uint32_t b0, uint32_t b1)
{
    asm volatile(
        "mma.sync.aligned.m16n8k16.row.col.f32.f16.f16.f32 "
        "{%0,%1,%2,%3}, {%4,%5,%6,%7}, {%8,%9}, {%0,%1,%2,%3};"
        : "+f"(c[0]), "+f"(c[1]), "+f"(c[2]), "+f"(c[3])
        : "r"(a0), "r"(a1), "r"(a2), "r"(a3), "r"(b0), "r"(b1));
}

// ============ QKV GEMM: bf16x3 (AhBh + AhBl + AlBh), 128x128 tile, BK=32, 3-stage ============
#define QPITCH 80
#define QARR (128 * QPITCH)          // 10240
#define QSTAGE (4 * QARR)            // 40960
#define QSMEM (3 * QSTAGE)           // 122880
#define QOFF_AH 0
#define QOFF_AL QARR
#define QOFF_BH (2 * QARR)
#define QOFF_BL (3 * QARR)

__global__ __launch_bounds__(256, 1)
void k_gemm_qkv(int M, int N, int K,
                const __nv_bfloat16* __restrict__ Ahi, const __nv_bfloat16* __restrict__ Alo,
                const __nv_bfloat16* __restrict__ Bhi, const __nv_bfloat16* __restrict__ Blo,
                float* __restrict__ C, int ldc, const float* __restrict__ bias)
{
    extern __shared__ char smem[];
    const uint32_t sbase = smem_to_u32(smem);
    const int tid = threadIdx.x;
    const int wid = tid >> 5, lid = tid & 31;
    const int g = lid >> 2, tig = lid & 3;
    const int wm = (wid >> 2) * 64;
    const int wn = (wid & 3) * 32;
    const int bm = blockIdx.x * 128;
    const int bn = blockIdx.y * 128;
    const int nchunks = K >> 5;

    // per-thread cp mapping: 2 chunks of 16B per array
    const int r0 = tid >> 2, cA = tid & 3;
    const int r1 = 64 + r0;

    float acc[4][4][4];
    #pragma unroll
    for (int i = 0; i < 4; i++)
        #pragma unroll
        for (int j = 0; j < 4; j++)
            #pragma unroll
            for (int q = 0; q < 4; q++) acc[i][j][q] = 0.0f;

    auto load_stage = [&](int slot, int chunk) {
        const int k0 = chunk << 5;
        const uint32_t st = sbase + slot * QSTAGE;
        const uint32_t s0 = st + r0 * QPITCH + cA * 16;
        const uint32_t s1 = st + r1 * QPITCH + cA * 16;
        cp16(s0 + QOFF_AH, Ahi + (size_t)(bm + r0) * K + k0 + cA * 8);
        cp16(s0 + QOFF_AL, Alo + (size_t)(bm + r0) * K + k0 + cA * 8);
        cp16(s1 + QOFF_AH, Ahi + (size_t)(bm + r1) * K + k0 + cA * 8);
        cp16(s1 + QOFF_AL, Alo + (size_t)(bm + r1) * K + k0 + cA * 8);
        cp16(s0 + QOFF_BH, Bhi + (size_t)(bn + r0) * K + k0 + cA * 8);
        cp16(s0 + QOFF_BL, Blo + (size_t)(bn + r0) * K + k0 + cA * 8);
        cp16(s1 + QOFF_BH, Bhi + (size_t)(bn + r1) * K + k0 + cA * 8);
        cp16(s1 + QOFF_BL, Blo + (size_t)(bn + r1) * K + k0 + cA * 8);
    };

    load_stage(0, 0);
    asm volatile("cp.async.commit_group;");
    load_stage(1, 1);
    asm volatile("cp.async.commit_group;");

    for (int c = 0; c < nchunks; c++) {
        asm volatile("cp.async.wait_group 1;");
        __syncthreads();
        if (c + 2 < nchunks) {
            load_stage((c + 2) % 3, c + 2);
            asm volatile("cp.async.commit_group;");
        }
        const char* st = smem + (c % 3) * QSTAGE;
        const char* sAh = st + QOFF_AH;
        const char* sAl = st + QOFF_AL;
        const char* sBh = st + QOFF_BH;
        const char* sBl = st + QOFF_BL;

        #pragma unroll
        for (int ks = 0; ks < 2; ks++) {
            const int colb = ks * 32 + tig * 4;
            uint32_t Afh[4][4], Afl[4][4];
            #pragma unroll
            for (int mt = 0; mt < 4; mt++) {
                const int ra = (wm + mt * 16 + g) * QPITCH;
                const int rb = ra + 8 * QPITCH;
                Afh[mt][0] = *(const uint32_t*)(sAh + ra + colb);
                Afh[mt][1] = *(const uint32_t*)(sAh + rb + colb);
                Afh[mt][2] = *(const uint32_t*)(sAh + ra + colb + 16);
                Afh[mt][3] = *(const uint32_t*)(sAh + rb + colb + 16);
                Afl[mt][0] = *(const uint32_t*)(sAl + ra + colb);
                Afl[mt][1] = *(const uint32_t*)(sAl + rb + colb);
                Afl[mt][2] = *(const uint32_t*)(sAl + ra + colb + 16);
                Afl[mt][3] = *(const uint32_t*)(sAl + rb + colb + 16);
            }
            uint32_t Bfh[4][2], Bfl[4][2];
            #pragma unroll
            for (int nt = 0; nt < 4; nt++) {
                const int rn = (wn + nt * 8 + g) * QPITCH;
                Bfh[nt][0] = *(const uint32_t*)(sBh + rn + colb);
                Bfh[nt][1] = *(const uint32_t*)(sBh + rn + colb + 16);
                Bfl[nt][0] = *(const uint32_t*)(sBl + rn + colb);
                Bfl[nt][1] = *(const uint32_t*)(sBl + rn + colb + 16);
            }
            #pragma unroll
            for (int mt = 0; mt < 4; mt++)
                #pragma unroll
                for (int nt = 0; nt < 4; nt++) {
                    mma_bf16(acc[mt][nt], Afh[mt][0], Afh[mt][1], Afh[mt][2], Afh[mt][3],
                             Bfh[nt][0], Bfh[nt][1]);
                    mma_bf16(acc[mt][nt], Afh[mt][0], Afh[mt][1], Afh[mt][2], Afh[mt][3],
                             Bfl[nt][0], Bfl[nt][1]);
                    mma_bf16(acc[mt][nt], Afl[mt][0], Afl[mt][1], Afl[mt][2], Afl[mt][3],
                             Bfh[nt][0], Bfh[nt][1]);
                }
        }
    }

    #pragma unroll
    for (int mt = 0; mt < 4; mt++) {
        const int row = bm + wm + mt * 16 + g;
        #pragma unroll
        for (int nt = 0; nt < 4; nt++) {
            const int col = bn + wn + nt * 8 + tig * 2;
            const float b0 = bias[col], b1 = bias[col + 1];
            float* p0 = C + (size_t)row * ldc + col;
            float* p1 = C + (size_t)(row + 8) * ldc + col;
            p0[0] = acc[mt][nt][0] + b0;
            p0[1] = acc[mt][nt][1] + b1;
            p1[0] = acc[mt][nt][2] + b0;
            p1[1] = acc[mt][nt][3] + b1;
        }
    }
}

// ============ Logits GEMM: pure fp16, 128x128 tile, BK=64, 3-stage ============
#define FPITCH 144
#define FARR (128 * FPITCH)          // 18432
#define FSTAGE (2 * FARR)            // 36864
#define FSMEM (3 * FSTAGE)           // 110592
#define FOFF_A 0
#define FOFF_B FARR

__global__ __launch_bounds__(256, 1)
void k_gemm_f16(int M, int N, int K,
                const __half* __restrict__ A, const __half* __restrict__ B,
                float* __restrict__ C, int ldc, const float* __restrict__ bias)
{
    extern __shared__ char smem[];
    const uint32_t sbase = smem_to_u32(smem);
    const int tid = threadIdx.x;
    const int wid = tid >> 5, lid = tid & 31;
    const int g = lid >> 2, tig = lid & 3;
    const int wm = (wid >> 2) * 64;
    const int wn = (wid & 3) * 32;
    const int bm = blockIdx.x * 128;    // M fastest -> wave shares B tile
    const int bn = blockIdx.y * 128;
    const int nchunks = K >> 6;

    float acc[4][4][4];
    #pragma unroll
    for (int i = 0; i < 4; i++)
        #pragma unroll
        for (int j = 0; j < 4; j++)
            #pragma unroll
            for (int q = 0; q < 4; q++) acc[i][j][q] = 0.0f;

    auto load_stage = [&](int slot, int chunk) {
        const int k0 = chunk << 6;
        const uint32_t st = sbase + slot * FSTAGE;
        #pragma unroll
        for (int i = 0; i < 4; i++) {
            const int u = i * 256 + tid;          // 0..1023
            const int r = u >> 3, cc = u & 7;
            const uint32_t sa = st + r * FPITCH + cc * 16;
            cp16(sa + FOFF_A, A + (size_t)(bm + r) * K + k0 + cc * 8);
            cp16(sa + FOFF_B, B + (size_t)(bn + r) * K + k0 + cc * 8);
        }
    };

    load_stage(0, 0);
    asm volatile("cp.async.commit_group;");
    load_stage(1, 1);
    asm volatile("cp.async.commit_group;");

    for (int c = 0; c < nchunks; c++) {
        asm volatile("cp.async.wait_group 1;");
        __syncthreads();
        if (c + 2 < nchunks) {
            load_stage((c + 2) % 3, c + 2);
            asm volatile("cp.async.commit_group;");
        }
        const char* st = smem + (c % 3) * FSTAGE;
        const char* sA = st + FOFF_A;
        const char* sB = st + FOFF_B;

        #pragma unroll
        for (int ks = 0; ks < 4; ks++) {
            const int colb = ks * 32 + tig * 4;
            uint32_t Af[4][4];
            #pragma unroll
            for (int mt = 0; mt < 4; mt++) {
                const int ra = (wm + mt * 16 + g) * FPITCH;
                const int rb = ra + 8 * FPITCH;
                Af[mt][0] = *(const uint32_t*)(sA + ra + colb);
                Af[mt][1] = *(const uint32_t*)(sA + rb + colb);
                Af[mt][2] = *(const uint32_t*)(sA + ra + colb + 16);
                Af[mt][3] = *(const uint32_t*)(sA + rb + colb + 16);
            }
            uint32_t Bf[4][2];
            #pragma unroll
            for (int nt = 0; nt < 4; nt++) {
                const int rn = (wn + nt * 8 + g) * FPITCH;
                Bf[nt][0] = *(const uint32_t*)(sB + rn + colb);
                Bf[nt][1] = *(const uint32_t*)(sB + rn + colb + 16);
            }
            #pragma unroll
            for (int mt = 0; mt < 4; mt++)
                #pragma unroll
                for (int nt = 0; nt < 4; nt++)
                    mma_f16(acc[mt][nt], Af[mt][0], Af[mt][1], Af[mt][2], Af[mt][3],
                            Bf[nt][0], Bf[nt][1]);
        }
    }

    #pragma unroll
    for (int mt = 0; mt < 4; mt++) {
        const int row = bm + wm + mt * 16 + g;
        #pragma unroll
        for (int nt = 0; nt < 4; nt++) {
            const int col = bn + wn + nt * 8 + tig * 2;
            const float b0 = bias[col], b1 = bias[col + 1];
            float* p0 = C + (size_t)row * ldc + col;
            float* p1 = C + (size_t)(row + 8) * ldc + col;
            p0[0] = acc[mt][nt][0] + b0;
            p0[1] = acc[mt][nt][1] + b1;
            p1[0] = acc[mt][nt][2] + b0;
            p1[1] = acc[mt][nt][3] + b1;
        }
    }
}

// ---------------- embed + bf16 hi/lo split (fused) ----------------
__global__ void k_embed_split(const int* __restrict__ ids,
                              const float* __restrict__ tok_emb,
                              const float* __restrict__ pos_emb)
{
    int tok = blockIdx.x;
    int t = tok & (TT - 1);
    int v = ids[tok];
    const float* te = tok_emb + (size_t)v * DD;
    const float* pe = pos_emb + (size_t)t * DD;
    __nv_bfloat16* oh = g_ah + (size_t)tok * DD;
    __nv_bfloat16* ol = g_al + (size_t)tok * DD;
    for (int d = threadIdx.x; d < DD; d += blockDim.x) {
        float x = te[d] * 32.0f + pe[d];
        __nv_bfloat16 h = __float2bfloat16_rn(x);
        oh[d] = h;
        ol[d] = __float2bfloat16_rn(x - __bfloat162float(h));
    }
}

// ---------------- repack Wq/Wk/Wv -> K-major bf16 hi/lo [3072, 1024] ----------------
__global__ void k_repack_wqkv(const float* __restrict__ Wq,
                              const float* __restrict__ Wk,
                              const float* __restrict__ Wv)
{
    int n = blockIdx.x;
    int sel = n >> 10, c = n & 1023, h = c >> 6, k = c & 63;
    const float* src = (sel == 0) ? Wq : (sel == 1) ? Wk : Wv;
    const float* col = src + (size_t)h * (DD * DKK) + k;
    __nv_bfloat16* oh = g_bh + (size_t)n * DD;
    __nv_bfloat16* ol = g_bl + (size_t)n * DD;
    for (int d = threadIdx.x; d < DD; d += blockDim.x) {
        float x = col[(size_t)d * DKK];
        __nv_bfloat16 hh = __float2bfloat16_rn(x);
        oh[d] = hh;
        ol[d] = __float2bfloat16_rn(x - __bfloat162float(hh));
    }
}

__global__ void k_repack_b(const float* __restrict__ bq,
                           const float* __restrict__ bk,
                           const float* __restrict__ bv)
{
    int col = blockIdx.x * blockDim.x + threadIdx.x;
    if (col >= N3) return;
    int sel = col >> 10, c = col & 1023;
    const float* src = (sel == 0) ? bq : (sel == 1) ? bk : bv;
    g_b3[col] = src[c];
}

// ---------------- transpose Wo [1024, 32000] -> fp16 [32000, 1024] ----------------
__global__ void k_woT(const float* __restrict__ Wo)
{
    __shared__ float s[32][33];
    int v0 = blockIdx.x * 32, d0 = blockIdx.y * 32;
    int tx = threadIdx.x, ty = threadIdx.y;  // (32, 8)
    #pragma unroll
    for (int i = 0; i < 4; i++)
        s[ty + i * 8][tx] = Wo[(size_t)(d0 + ty + i * 8) * VV + v0 + tx];
    __syncthreads();
    #pragma unroll
    for (int i = 0; i < 4; i++) {
        int v = v0 + ty + i * 8;
        int d = d0 + tx;
        g_hb[(size_t)v * DD + d] = __float2half(s[tx][ty + i * 8]);
    }
}

// ---------------- scores: S[bh][t][s] = q . k (fp32, 64x64 tiles) ----------------
__global__ __launch_bounds__(256)
void k_scores()
{
    const int sT = blockIdx.x, tT = blockIdx.y, bh = blockIdx.z;
    if (sT > tT) return;
    const int b = bh >> 4, h = bh & 15;
    const int t0 = tT * 64, s0 = sT * 64;

    __shared__ float Qs[64][65];
    __shared__ float Ks[64][65];

    const int tid = threadIdx.x;
    const size_t qbase = ((size_t)(b * TT + t0)) * N3 + h * 64;
    const size_t kbase = ((size_t)(b * TT + s0)) * N3 + 1024 + h * 64;
    #pragma unroll
    for (int i = 0; i < 16; i++) {
        int e = i * 256 + tid;
        int r = e >> 6, c = e & 63;
        Qs[r][c] = g_qkv[qbase + (size_t)r * N3 + c];
        Ks[r][c] = g_qkv[kbase + (size_t)r * N3 + c];
    }
    __syncthreads();

    const int tm = (tid >> 4) * 4;
    const int tn = (tid & 15) * 4;
    float acc[4][4] = {};
    #pragma unroll
    for (int kk = 0; kk < 64; kk++) {
        float a[4], bb[4];
        #pragma unroll
        for (int i = 0; i < 4; i++) a[i]  = Qs[tm + i][kk];
        #pragma unroll
        for (int j = 0; j < 4; j++) bb[j] = Ks[tn + j][kk];
        #pragma unroll
        for (int i = 0; i < 4; i++)
            #pragma unroll
            for (int j = 0; j < 4; j++)
                acc[i][j] = fmaf(a[i], bb[j], acc[i][j]);
    }

    float* S = g_scores + (size_t)bh * TT * TT;
    #pragma unroll
    for (int i = 0; i < 4; i++) {
        float* row = S + (size_t)(t0 + tm + i) * TT + s0 + tn;
        row[0] = acc[i][0]; row[1] = acc[i][1]; row[2] = acc[i][2]; row[3] = acc[i][3];
    }
}

// ---------------- softmax per row (causal -> exact zeros above diag) ----------------
__global__ __launch_bounds__(256)
void k_softmax()
{
    const int t = blockIdx.x, bh = blockIdx.y;
    float* row = g_scores + (size_t)bh * TT * TT + (size_t)t * TT;
    const int n = t + 1;
    const int tid = threadIdx.x;
    __shared__ float red[256];

    float m = -INFINITY;
    for (int i = tid; i < n; i += 256) m = fmaxf(m, row[i] * 0.125f);
    red[tid] = m; __syncthreads();
    for (int s = 128; s > 0; s >>= 1) {
        if (tid < s) red[tid] = fmaxf(red[tid], red[tid + s]);
        __syncthreads();
    }
    m = red[0]; __syncthreads();

    float sum = 0.0f;
    for (int i = tid; i < n; i += 256) sum += __expf(fminf(row[i] * 0.125f - m, 0.0f));
    red[tid] = sum; __syncthreads();
    for (int s = 128; s > 0; s >>= 1) {
        if (tid < s) red[tid] += red[tid + s];
        __syncthreads();
    }
    const float inv = 1.0f / red[0];

    for (int i = tid; i < n; i += 256) row[i] = __expf(fminf(row[i] * 0.125f - m, 0.0f)) * inv;
    for (int i = n + tid; i < TT; i += 256) row[i] = 0.0f;
}

// ---------------- PV (fp32 compute, fp16 output for logits A) ----------------
__global__ __launch_bounds__(256)
void k_pv()
{
    const int tT = blockIdx.x, bh = blockIdx.y;
    const int b = bh >> 4, h = bh & 15;
    const int t0 = tT * 64;

    __shared__ float Ps[64][65];
    __shared__ float Vs[64][65];

    const int tid = threadIdx.x;
    const int tm = (tid >> 4) * 4;
    const int tn = (tid & 15) * 4;
    float acc[4][4] = {};

    const float* P = g_scores + (size_t)bh * TT * TT;

    for (int s0 = 0; s0 <= t0; s0 += 64) {
        #pragma unroll
        for (int i = 0; i < 16; i++) {
            int e = i * 256 + tid;
            int r = e >> 6, c = e & 63;
            Ps[r][c] = P[(size_t)(t0 + r) * TT + s0 + c];
            Vs[r][c] = g_qkv[((size_t)(b * TT + s0 + r)) * N3 + 2048 + h * 64 + c];
        }
        __syncthreads();
        #pragma unroll
        for (int ss = 0; ss < 64; ss++) {
            float a[4], bb[4];
            #pragma unroll
            for (int i = 0; i < 4; i++) a[i]  = Ps[tm + i][ss];
            #pragma unroll
            for (int j = 0; j < 4; j++) bb[j] = Vs[ss][tn + j];
            #pragma unroll
            for (int i = 0; i < 4; i++)
                #pragma unroll
                for (int j = 0; j < 4; j++)
                    acc[i][j] = fmaf(a[i], bb[j], acc[i][j]);
        }
        __syncthreads();
    }

    #pragma unroll
    for (int i = 0; i < 4; i++) {
        __half* o = g_ha + ((size_t)(b * TT + t0 + tm + i)) * DD + h * 64 + tn;
        __half2 p0 = __floats2half2_rn(acc[i][0], acc[i][1]);
        __half2 p1 = __floats2half2_rn(acc[i][2], acc[i][3]);
        *(__half2*)(o)     = p0;
        *(__half2*)(o + 2) = p1;
    }
}

// ---------------- loss: single-pass online logsumexp per row ----------------
__global__ __launch_bounds__(256)
void k_loss_rows(const float* __restrict__ logits, const int* __restrict__ targets)
{
    const int r = blockIdx.x;
    const float* row = logits + (size_t)r * VV;
    const int tid = threadIdx.x;
    __shared__ float sm[256], ss[256];

    float m = -INFINITY, s = 0.0f;
    for (int i = tid; i < VV; i += 256) {
        float x = row[i];
        if (x <= m) {
            s += __expf(x - m);
        } else {
            s = s * __expf(m - x) + 1.0f;
            m = x;
        }
    }
    sm[tid] = m; ss[tid] = s;
    __syncthreads();
    for (int k = 128; k > 0; k >>= 1) {
        if (tid < k) {
            float m1 = sm[tid], s1 = ss[tid];
            float m2 = sm[tid + k], s2 = ss[tid + k];
            float M = fmaxf(m1, m2);
            sm[tid] = M;
            ss[tid] = s1 * __expf(m1 - M) + s2 * __expf(m2 - M);
        }
        __syncthreads();
    }
    if (tid == 0) {
        int tgt = targets[r];
        float logp = row[tgt] - sm[0] - __logf(ss[0]);
        g_rowloss[r] = -logp;
    }
}

__global__ void k_loss_final(float* out)
{
    const int tid = threadIdx.x;
    __shared__ float red[256];
    float s = 0.0f;
    for (int i = tid; i < BT; i += 256) s += g_rowloss[i];
    red[tid] = s; __syncthreads();
    for (int k = 128; k > 0; k >>= 1) {
        if (tid < k) red[tid] += red[tid + k];
        __syncthreads();
    }
    if (tid == 0) out[0] = red[0] * (1.0f / BT);
}

// ---------------- launch ----------------
extern "C" void kernel_launch(void* const* d_in, const int* in_sizes, int n_in,
                              void* d_out, int out_size)
{
    const int*   ids     = (const int*)  d_in[0];
    const int*   targets = (const int*)  d_in[1];
    const float* tok_emb = (const float*)d_in[2];
    const float* pos_emb = (const float*)d_in[3];
    const float* Wq      = (const float*)d_in[4];
    const float* bq      = (const float*)d_in[5];
    const float* Wk      = (const float*)d_in[6];
    const float* bk      = (const float*)d_in[7];
    const float* Wv      = (const float*)d_in[8];
    const float* bv      = (const float*)d_in[9];
    const float* Wo      = (const float*)d_in[10];
    const float* bo      = (const float*)d_in[11];
    float* out = (float*)d_out;

    float *pb3, *pqkv;
    __nv_bfloat16 *pah, *pal, *pbh, *pbl;
    __half *pha, *phb;
    cudaGetSymbolAddress((void**)&pb3,  g_b3);
    cudaGetSymbolAddress((void**)&pqkv, g_qkv);
    cudaGetSymbolAddress((void**)&pah,  g_ah);
    cudaGetSymbolAddress((void**)&pal,  g_al);
    cudaGetSymbolAddress((void**)&pbh,  g_bh);
    cudaGetSymbolAddress((void**)&pbl,  g_bl);
    cudaGetSymbolAddress((void**)&pha,  g_ha);
    cudaGetSymbolAddress((void**)&phb,  g_hb);

    cudaFuncSetAttribute(k_gemm_qkv, cudaFuncAttributeMaxDynamicSharedMemorySize, QSMEM);
    cudaFuncSetAttribute(k_gemm_f16, cudaFuncAttributeMaxDynamicSharedMemorySize, FSMEM);

    // 1. embed + split (fused), weight repacks
    k_embed_split<<<BT, 256>>>(ids, tok_emb, pos_emb);
    k_repack_wqkv<<<N3, 256>>>(Wq, Wk, Wv);
    k_repack_b<<<(N3 + 255) / 256, 256>>>(bq, bk, bv);
    k_woT<<<dim3(VV / 32, DD / 32), dim3(32, 8)>>>(Wo);

    // 2. QKV projection (bf16x3): [4096,1024] x [1024,3072]
    k_gemm_qkv<<<dim3(BT / 128, N3 / 128), 256, QSMEM>>>(
        BT, N3, DD, pah, pal, pbh, pbl, pqkv, N3, pb3);

    // 3. attention (fp32; PV emits fp16 A for the logits GEMM)
    k_scores <<<dim3(16, 16, BHN), 256>>>();
    k_softmax<<<dim3(TT, BHN), 256>>>();
    k_pv     <<<dim3(16, BHN), 256>>>();

    // 4. logits (pure fp16): [4096,1024] x [1024,32000] + bo
    k_gemm_f16<<<dim3(BT / 128, VV / 128), 256, FSMEM>>>(
        BT, VV, DD, pha, phb, out, VV, bo);

    // 5. loss
    if ((long long)out_size > BTV) {
        k_loss_rows<<<BT, 256>>>(out, targets);
        k_loss_final<<<1, 256>>>(out + BTV);
    }
}

// round 8
// speedup vs baseline: 4.9175x; 1.1019x over previous
#include <cuda_runtime.h>
#include <cuda_bf16.h>
#include <cuda_fp16.h>
#include <math.h>
#include <stdint.h>

// Problem constants
#define BB 4
#define TT 1024
#define VV 32000
#define DD 1024
#define HH 16
#define DKK 64
#define BT 4096            // B*T
#define N3 3072            // 3*D (q|k|v)
#define BHN 64             // B*H
#define BTV 131072000LL    // BT*VV

// ---------------- scratch (device globals; no allocation) ----------------
__device__ float g_b3[N3];                       // repacked qkv bias
__device__ float g_qkv[BT * N3];                 // 48 MB [token][h*64+k | +1024 | +2048]
__device__ float g_rowloss[BT];

__device__ __nv_bfloat16 g_ah[BT * DD];          // x hi (QKV A operand)
__device__ __nv_bfloat16 g_al[BT * DD];          // x lo
__device__ __nv_bfloat16 g_bh[N3 * DD];          // Wqkv hi (K-major [3072,1024])
__device__ __nv_bfloat16 g_bl[N3 * DD];          // Wqkv lo

__device__ __half g_ha[BT * DD];                 // attention-out fp16 (logits A)
__device__ __half g_hb[(size_t)VV * DD];         // Wo^T fp16 (K-major [32000,1024])

// ================= helpers =================
__device__ __forceinline__ uint32_t smem_to_u32(const void* p) {
    uint32_t a;
    asm("{ .reg .u64 t; cvta.to.shared.u64 t, %1; cvt.u32.u64 %0, t; }" : "=r"(a) : "l"(p));
    return a;
}
__device__ __forceinline__ void cp16(uint32_t saddr, const void* gptr) {
    asm volatile("cp.async.cg.shared.global [%0], [%1], 16;" :: "r"(saddr), "l"(gptr));
}
__device__ __forceinline__ void mma_bf16(float* c,
                                         uint32_t a0, uint32_t a1, uint32_t a2, uint32_t a3,
                                         uint32_t b0, uint32_t b1)
{
    asm volatile(
        "mma.sync.aligned.m16n8k16.row.col.f32.bf16.bf16.f32 "
        "{%0,%1,%2,%3}, {%4,%5,%6,%7}, {%8,%9}, {%0,%1,%2,%3};"
        : "+f"(c[0]), "+f"(c[1]), "+f"(c[2]), "+f"(c[3])
        : "r"(a0), "r"(a1), "r"(a2), "r"(a3), "r"(b0), "r"(b1));
}
__device__ __forceinline__ void mma_f16(float* c,
                                        uint32_t a0, uint32_t a1, uint32_t a2, uint32_t a3,
                                        uint32_t b0, uint32_t b1)
{
    asm volatile(
        "mma.sync.aligned.m16n8k16.row.col.f32.f16.f16.f32 "
        "{%0,%1,%2,%3}, {%4,%5,%6,%7}, {%8,%9}, {%0,%1,%2,%3};"
        : "+f"(c[0]), "+f"(c[1]), "+f"(c[2]), "+f"(c[3])
        : "r"(a0), "r"(a1), "r"(a2), "r"(a3), "r"(b0), "r"(b1));
}

// ============ QKV GEMM: bf16x3 (AhBh + AhBl + AlBh), 128x128 tile, BK=32, 3-stage ============
#define QPITCH 80
#define QARR (128 * QPITCH)          // 10240
#define QSTAGE (4 * QARR)            // 40960
#define QSMEM (3 * QSTAGE)           // 122880
#define QOFF_AH 0
#define QOFF_AL QARR
#define QOFF_BH (2 * QARR)
#define QOFF_BL (3 * QARR)

__global__ __launch_bounds__(256, 1)
void k_gemm_qkv(int M, int N, int K,
                const __nv_bfloat16* __restrict__ Ahi, const __nv_bfloat16* __restrict__ Alo,
                const __nv_bfloat16* __restrict__ Bhi, const __nv_bfloat16* __restrict__ Blo,
                float* __restrict__ C, int ldc, const float* __restrict__ bias)
{
    extern __shared__ char smem[];
    const uint32_t sbase = smem_to_u32(smem);
    const int tid = threadIdx.x;
    const int wid = tid >> 5, lid = tid & 31;
    const int g = lid >> 2, tig = lid & 3;
    const int wm = (wid >> 2) * 64;
    const int wn = (wid & 3) * 32;
    const int bm = blockIdx.x * 128;
    const int bn = blockIdx.y * 128;
    const int nchunks = K >> 5;

    const int r0 = tid >> 2, cA = tid & 3;
    const int r1 = 64 + r0;

    float acc[4][4][4];
    #pragma unroll
    for (int i = 0; i < 4; i++)
        #pragma unroll
        for (int j = 0; j < 4; j++)
            #pragma unroll
            for (int q = 0; q < 4; q++) acc[i][j][q] = 0.0f;

    auto load_stage = [&](int slot, int chunk) {
        const int k0 = chunk << 5;
        const uint32_t st = sbase + slot * QSTAGE;
        const uint32_t s0 = st + r0 * QPITCH + cA * 16;
        const uint32_t s1 = st + r1 * QPITCH + cA * 16;
        cp16(s0 + QOFF_AH, Ahi + (size_t)(bm + r0) * K + k0 + cA * 8);
        cp16(s0 + QOFF_AL, Alo + (size_t)(bm + r0) * K + k0 + cA * 8);
        cp16(s1 + QOFF_AH, Ahi + (size_t)(bm + r1) * K + k0 + cA * 8);
        cp16(s1 + QOFF_AL, Alo + (size_t)(bm + r1) * K + k0 + cA * 8);
        cp16(s0 + QOFF_BH, Bhi + (size_t)(bn + r0) * K + k0 + cA * 8);
        cp16(s0 + QOFF_BL, Blo + (size_t)(bn + r0) * K + k0 + cA * 8);
        cp16(s1 + QOFF_BH, Bhi + (size_t)(bn + r1) * K + k0 + cA * 8);
        cp16(s1 + QOFF_BL, Blo + (size_t)(bn + r1) * K + k0 + cA * 8);
    };

    load_stage(0, 0);
    asm volatile("cp.async.commit_group;");
    load_stage(1, 1);
    asm volatile("cp.async.commit_group;");

    for (int c = 0; c < nchunks; c++) {
        asm volatile("cp.async.wait_group 1;");
        __syncthreads();
        if (c + 2 < nchunks) {
            load_stage((c + 2) % 3, c + 2);
            asm volatile("cp.async.commit_group;");
        }
        const char* st = smem + (c % 3) * QSTAGE;
        const char* sAh = st + QOFF_AH;
        const char* sAl = st + QOFF_AL;
        const char* sBh = st + QOFF_BH;
        const char* sBl = st + QOFF_BL;

        #pragma unroll
        for (int ks = 0; ks < 2; ks++) {
            const int colb = ks * 32 + tig * 4;
            uint32_t Afh[4][4], Afl[4][4];
            #pragma unroll
            for (int mt = 0; mt < 4; mt++) {
                const int ra = (wm + mt * 16 + g) * QPITCH;
                const int rb = ra + 8 * QPITCH;
                Afh[mt][0] = *(const uint32_t*)(sAh + ra + colb);
                Afh[mt][1] = *(const uint32_t*)(sAh + rb + colb);
                Afh[mt][2] = *(const uint32_t*)(sAh + ra + colb + 16);
                Afh[mt][3] = *(const uint32_t*)(sAh + rb + colb + 16);
                Afl[mt][0] = *(const uint32_t*)(sAl + ra + colb);
                Afl[mt][1] = *(const uint32_t*)(sAl + rb + colb);
                Afl[mt][2] = *(const uint32_t*)(sAl + ra + colb + 16);
                Afl[mt][3] = *(const uint32_t*)(sAl + rb + colb + 16);
            }
            uint32_t Bfh[4][2], Bfl[4][2];
            #pragma unroll
            for (int nt = 0; nt < 4; nt++) {
                const int rn = (wn + nt * 8 + g) * QPITCH;
                Bfh[nt][0] = *(const uint32_t*)(sBh + rn + colb);
                Bfh[nt][1] = *(const uint32_t*)(sBh + rn + colb + 16);
                Bfl[nt][0] = *(const uint32_t*)(sBl + rn + colb);
                Bfl[nt][1] = *(const uint32_t*)(sBl + rn + colb + 16);
            }
            #pragma unroll
            for (int mt = 0; mt < 4; mt++)
                #pragma unroll
                for (int nt = 0; nt < 4; nt++) {
                    mma_bf16(acc[mt][nt], Afh[mt][0], Afh[mt][1], Afh[mt][2], Afh[mt][3],
                             Bfh[nt][0], Bfh[nt][1]);
                    mma_bf16(acc[mt][nt], Afh[mt][0], Afh[mt][1], Afh[mt][2], Afh[mt][3],
                             Bfl[nt][0], Bfl[nt][1]);
                    mma_bf16(acc[mt][nt], Afl[mt][0], Afl[mt][1], Afl[mt][2], Afl[mt][3],
                             Bfh[nt][0], Bfh[nt][1]);
                }
        }
    }

    #pragma unroll
    for (int mt = 0; mt < 4; mt++) {
        const int row = bm + wm + mt * 16 + g;
        #pragma unroll
        for (int nt = 0; nt < 4; nt++) {
            const int col = bn + wn + nt * 8 + tig * 2;
            const float b0 = bias[col], b1 = bias[col + 1];
            float* p0 = C + (size_t)row * ldc + col;
            float* p1 = C + (size_t)(row + 8) * ldc + col;
            p0[0] = acc[mt][nt][0] + b0;
            p0[1] = acc[mt][nt][1] + b1;
            p1[0] = acc[mt][nt][2] + b0;
            p1[1] = acc[mt][nt][3] + b1;
        }
    }
}

// ============ Logits GEMM: pure fp16, 128x128 tile, BK=64, 3-stage ============
#define FPITCH 144
#define FARR (128 * FPITCH)          // 18432
#define FSTAGE (2 * FARR)            // 36864
#define FSMEM (3 * FSTAGE)           // 110592
#define FOFF_A 0
#define FOFF_B FARR

__global__ __launch_bounds__(256, 1)
void k_gemm_f16(int M, int N, int K,
                const __half* __restrict__ A, const __half* __restrict__ B,
                float* __restrict__ C, int ldc, const float* __restrict__ bias)
{
    extern __shared__ char smem[];
    const uint32_t sbase = smem_to_u32(smem);
    const int tid = threadIdx.x;
    const int wid = tid >> 5, lid = tid & 31;
    const int g = lid >> 2, tig = lid & 3;
    const int wm = (wid >> 2) * 64;
    const int wn = (wid & 3) * 32;
    const int bm = blockIdx.x * 128;    // M fastest -> wave shares B tile
    const int bn = blockIdx.y * 128;
    const int nchunks = K >> 6;

    float acc[4][4][4];
    #pragma unroll
    for (int i = 0; i < 4; i++)
        #pragma unroll
        for (int j = 0; j < 4; j++)
            #pragma unroll
            for (int q = 0; q < 4; q++) acc[i][j][q] = 0.0f;

    auto load_stage = [&](int slot, int chunk) {
        const int k0 = chunk << 6;
        const uint32_t st = sbase + slot * FSTAGE;
        #pragma unroll
        for (int i = 0; i < 4; i++) {
            const int u = i * 256 + tid;
            const int r = u >> 3, cc = u & 7;
            const uint32_t sa = st + r * FPITCH + cc * 16;
            cp16(sa + FOFF_A, A + (size_t)(bm + r) * K + k0 + cc * 8);
            cp16(sa + FOFF_B, B + (size_t)(bn + r) * K + k0 + cc * 8);
        }
    };

    load_stage(0, 0);
    asm volatile("cp.async.commit_group;");
    load_stage(1, 1);
    asm volatile("cp.async.commit_group;");

    for (int c = 0; c < nchunks; c++) {
        asm volatile("cp.async.wait_group 1;");
        __syncthreads();
        if (c + 2 < nchunks) {
            load_stage((c + 2) % 3, c + 2);
            asm volatile("cp.async.commit_group;");
        }
        const char* st = smem + (c % 3) * FSTAGE;
        const char* sA = st + FOFF_A;
        const char* sB = st + FOFF_B;

        #pragma unroll
        for (int ks = 0; ks < 4; ks++) {
            const int colb = ks * 32 + tig * 4;
            uint32_t Af[4][4];
            #pragma unroll
            for (int mt = 0; mt < 4; mt++) {
                const int ra = (wm + mt * 16 + g) * FPITCH;
                const int rb = ra + 8 * FPITCH;
                Af[mt][0] = *(const uint32_t*)(sA + ra + colb);
                Af[mt][1] = *(const uint32_t*)(sA + rb + colb);
                Af[mt][2] = *(const uint32_t*)(sA + ra + colb + 16);
                Af[mt][3] = *(const uint32_t*)(sA + rb + colb + 16);
            }
            uint32_t Bf[4][2];
            #pragma unroll
            for (int nt = 0; nt < 4; nt++) {
                const int rn = (wn + nt * 8 + g) * FPITCH;
                Bf[nt][0] = *(const uint32_t*)(sB + rn + colb);
                Bf[nt][1] = *(const uint32_t*)(sB + rn + colb + 16);
            }
            #pragma unroll
            for (int mt = 0; mt < 4; mt++)
                #pragma unroll
                for (int nt = 0; nt < 4; nt++)
                    mma_f16(acc[mt][nt], Af[mt][0], Af[mt][1], Af[mt][2], Af[mt][3],
                            Bf[nt][0], Bf[nt][1]);
        }
    }

    #pragma unroll
    for (int mt = 0; mt < 4; mt++) {
        const int row = bm + wm + mt * 16 + g;
        #pragma unroll
        for (int nt = 0; nt < 4; nt++) {
            const int col = bn + wn + nt * 8 + tig * 2;
            const float b0 = bias[col], b1 = bias[col + 1];
            float* p0 = C + (size_t)row * ldc + col;
            float* p1 = C + (size_t)(row + 8) * ldc + col;
            p0[0] = acc[mt][nt][0] + b0;
            p0[1] = acc[mt][nt][1] + b1;
            p1[0] = acc[mt][nt][2] + b0;
            p1[1] = acc[mt][nt][3] + b1;
        }
    }
}

// ---------------- embed + bf16 hi/lo split (fused) ----------------
__global__ void k_embed_split(const int* __restrict__ ids,
                              const float* __restrict__ tok_emb,
                              const float* __restrict__ pos_emb)
{
    int tok = blockIdx.x;
    int t = tok & (TT - 1);
    int v = ids[tok];
    const float* te = tok_emb + (size_t)v * DD;
    const float* pe = pos_emb + (size_t)t * DD;
    __nv_bfloat16* oh = g_ah + (size_t)tok * DD;
    __nv_bfloat16* ol = g_al + (size_t)tok * DD;
    for (int d = threadIdx.x; d < DD; d += blockDim.x) {
        float x = te[d] * 32.0f + pe[d];
        __nv_bfloat16 h = __float2bfloat16_rn(x);
        oh[d] = h;
        ol[d] = __float2bfloat16_rn(x - __bfloat162float(h));
    }
}

// ---------------- repack Wq/Wk/Wv via smem transpose -> K-major bf16 hi/lo ----------------
// grid: (48, 32, 2)  = (sel*16+h, dTile, kTile), block (32, 8)
__global__ void k_repack_wqkvT(const float* __restrict__ Wq,
                               const float* __restrict__ Wk,
                               const float* __restrict__ Wv)
{
    __shared__ float s[32][33];
    const int sh = blockIdx.x;
    const int sel = sh >> 4, h = sh & 15;
    const int d0 = blockIdx.y * 32;
    const int k0 = blockIdx.z * 32;
    const float* src = (sel == 0) ? Wq : (sel == 1) ? Wk : Wv;
    const float* base = src + (size_t)h * (DD * DKK);
    const int tx = threadIdx.x, ty = threadIdx.y;
    #pragma unroll
    for (int i = 0; i < 4; i++)
        s[ty + i * 8][tx] = base[(size_t)(d0 + ty + i * 8) * DKK + k0 + tx];
    __syncthreads();
    #pragma unroll
    for (int i = 0; i < 4; i++) {
        const int k = k0 + ty + i * 8;
        const int n = sel * 1024 + h * 64 + k;
        const int d = d0 + tx;
        const float x = s[tx][ty + i * 8];
        __nv_bfloat16 hh = __float2bfloat16_rn(x);
        g_bh[(size_t)n * DD + d] = hh;
        g_bl[(size_t)n * DD + d] = __float2bfloat16_rn(x - __bfloat162float(hh));
    }
}

__global__ void k_repack_b(const float* __restrict__ bq,
                           const float* __restrict__ bk,
                           const float* __restrict__ bv)
{
    int col = blockIdx.x * blockDim.x + threadIdx.x;
    if (col >= N3) return;
    int sel = col >> 10, c = col & 1023;
    const float* src = (sel == 0) ? bq : (sel == 1) ? bk : bv;
    g_b3[col] = src[c];
}

// ---------------- transpose Wo [1024, 32000] -> fp16 [32000, 1024] ----------------
__global__ void k_woT(const float* __restrict__ Wo)
{
    __shared__ float s[32][33];
    int v0 = blockIdx.x * 32, d0 = blockIdx.y * 32;
    int tx = threadIdx.x, ty = threadIdx.y;  // (32, 8)
    #pragma unroll
    for (int i = 0; i < 4; i++)
        s[ty + i * 8][tx] = Wo[(size_t)(d0 + ty + i * 8) * VV + v0 + tx];
    __syncthreads();
    #pragma unroll
    for (int i = 0; i < 4; i++) {
        int v = v0 + ty + i * 8;
        int d = d0 + tx;
        g_hb[(size_t)v * DD + d] = __float2half(s[tx][ty + i * 8]);
    }
}

// ---------------- fused flash attention (fp32): scores + softmax + PV ----------------
// grid: (16 tTiles reversed, 64 bh), 256 threads, 64x64 tiles, 4x4 per thread.
// smem (dynamic): Q | K | V | P, each 64x65 floats = 66560 bytes total.
#define FL_Q 0
#define FL_K (64 * 65)
#define FL_V (2 * 64 * 65)
#define FL_P (3 * 64 * 65)
#define FL_SMEM (4 * 64 * 65 * 4)     // 66560 bytes

__global__ __launch_bounds__(256)
void k_flash()
{
    extern __shared__ float fs[];
    const int tT = (int)gridDim.x - 1 - (int)blockIdx.x;   // heavy tiles first
    const int bh = blockIdx.y;
    const int b = bh >> 4, h = bh & 15;
    const int t0 = tT * 64;
    const int tid = threadIdx.x;
    const int tm = (tid >> 4) * 4;   // t-row base
    const int tn = (tid & 15) * 4;   // col base (s in score phase, dk in PV phase)

    // load Q tile once
    const size_t qbase = ((size_t)(b * TT + t0)) * N3 + h * 64;
    #pragma unroll
    for (int i = 0; i < 16; i++) {
        int e = i * 256 + tid;
        int r = e >> 6, c = e & 63;
        fs[FL_Q + r * 65 + c] = g_qkv[qbase + (size_t)r * N3 + c];
    }

    float O[4][4] = {};
    float m[4], l[4];
    #pragma unroll
    for (int i = 0; i < 4; i++) { m[i] = -INFINITY; l[i] = 0.0f; }

    for (int s0 = 0; s0 <= t0; s0 += 64) {
        const size_t kbase = ((size_t)(b * TT + s0)) * N3 + 1024 + h * 64;
        const size_t vbase = ((size_t)(b * TT + s0)) * N3 + 2048 + h * 64;
        #pragma unroll
        for (int i = 0; i < 16; i++) {
            int e = i * 256 + tid;
            int r = e >> 6, c = e & 63;
            fs[FL_K + r * 65 + c] = g_qkv[kbase + (size_t)r * N3 + c];
            fs[FL_V + r * 65 + c] = g_qkv[vbase + (size_t)r * N3 + c];
        }
        __syncthreads();

        // S = (Q K^T) / 8, causal mask on diagonal tile
        float S[4][4] = {};
        #pragma unroll 16
        for (int kk = 0; kk < 64; kk++) {
            float a[4], bb[4];
            #pragma unroll
            for (int i = 0; i < 4; i++) a[i]  = fs[FL_Q + (tm + i) * 65 + kk];
            #pragma unroll
            for (int j = 0; j < 4; j++) bb[j] = fs[FL_K + (tn + j) * 65 + kk];
            #pragma unroll
            for (int i = 0; i < 4; i++)
                #pragma unroll
                for (int j = 0; j < 4; j++)
                    S[i][j] = fmaf(a[i], bb[j], S[i][j]);
        }
        const bool diag = (s0 == t0);
        #pragma unroll
        for (int i = 0; i < 4; i++)
            #pragma unroll
            for (int j = 0; j < 4; j++) {
                float sv = S[i][j] * 0.125f;
                if (diag && (tn + j > tm + i)) sv = -INFINITY;
                S[i][j] = sv;
            }

        // online softmax per row
        float fac[4];
        #pragma unroll
        for (int i = 0; i < 4; i++) {
            float rm = fmaxf(fmaxf(S[i][0], S[i][1]), fmaxf(S[i][2], S[i][3]));
            #pragma unroll
            for (int w = 1; w < 16; w <<= 1)
                rm = fmaxf(rm, __shfl_xor_sync(0xFFFFFFFF, rm, w));
            const float mn = fmaxf(m[i], rm);
            fac[i] = __expf(m[i] - mn);
            float rs = 0.0f;
            #pragma unroll
            for (int j = 0; j < 4; j++) {
                S[i][j] = __expf(S[i][j] - mn);
                rs += S[i][j];
            }
            #pragma unroll
            for (int w = 1; w < 16; w <<= 1)
                rs += __shfl_xor_sync(0xFFFFFFFF, rs, w);
            l[i] = l[i] * fac[i] + rs;
            m[i] = mn;
        }
        #pragma unroll
        for (int i = 0; i < 4; i++) {
            #pragma unroll
            for (int j = 0; j < 4; j++) {
                fs[FL_P + (tm + i) * 65 + tn + j] = S[i][j];
                O[i][j] *= fac[i];
            }
        }
        __syncthreads();

        // O += P V
        #pragma unroll 16
        for (int ss = 0; ss < 64; ss++) {
            float a[4], bb[4];
            #pragma unroll
            for (int i = 0; i < 4; i++) a[i]  = fs[FL_P + (tm + i) * 65 + ss];
            #pragma unroll
            for (int j = 0; j < 4; j++) bb[j] = fs[FL_V + ss * 65 + tn + j];
            #pragma unroll
            for (int i = 0; i < 4; i++)
                #pragma unroll
                for (int j = 0; j < 4; j++)
                    O[i][j] = fmaf(a[i], bb[j], O[i][j]);
        }
        __syncthreads();   // protect K/V/P before next iteration
    }

    // normalize, emit fp16 (logits A operand), concat-head layout
    #pragma unroll
    for (int i = 0; i < 4; i++) {
        const float inv = 1.0f / l[i];
        __half* o = g_ha + ((size_t)(b * TT + t0 + tm + i)) * DD + h * 64 + tn;
        *(__half2*)(o)     = __floats2half2_rn(O[i][0] * inv, O[i][1] * inv);
        *(__half2*)(o + 2) = __floats2half2_rn(O[i][2] * inv, O[i][3] * inv);
    }
}

// ---------------- loss: single-pass online logsumexp per row ----------------
__global__ __launch_bounds__(256)
void k_loss_rows(const float* __restrict__ logits, const int* __restrict__ targets)
{
    const int r = blockIdx.x;
    const float* row = logits + (size_t)r * VV;
    const int tid = threadIdx.x;
    __shared__ float sm[256], ss[256];

    float m = -INFINITY, s = 0.0f;
    for (int i = tid; i < VV; i += 256) {
        float x = row[i];
        if (x <= m) {
            s += __expf(x - m);
        } else {
            s = s * __expf(m - x) + 1.0f;
            m = x;
        }
    }
    sm[tid] = m; ss[tid] = s;
    __syncthreads();
    for (int k = 128; k > 0; k >>= 1) {
        if (tid < k) {
            float m1 = sm[tid], s1 = ss[tid];
            float m2 = sm[tid + k], s2 = ss[tid + k];
            float M = fmaxf(m1, m2);
            sm[tid] = M;
            ss[tid] = s1 * __expf(m1 - M) + s2 * __expf(m2 - M);
        }
        __syncthreads();
    }
    if (tid == 0) {
        int tgt = targets[r];
        float logp = row[tgt] - sm[0] - __logf(ss[0]);
        g_rowloss[r] = -logp;
    }
}

__global__ void k_loss_final(float* out)
{
    const int tid = threadIdx.x;
    __shared__ float red[256];
    float s = 0.0f;
    for (int i = tid; i < BT; i += 256) s += g_rowloss[i];
    red[tid] = s; __syncthreads();
    for (int k = 128; k > 0; k >>= 1) {
        if (tid < k) red[tid] += red[tid + k];
        __syncthreads();
    }
    if (tid == 0) out[0] = red[0] * (1.0f / BT);
}

// ---------------- launch ----------------
extern "C" void kernel_launch(void* const* d_in, const int* in_sizes, int n_in,
                              void* d_out, int out_size)
{
    const int*   ids     = (const int*)  d_in[0];
    const int*   targets = (const int*)  d_in[1];
    const float* tok_emb = (const float*)d_in[2];
    const float* pos_emb = (const float*)d_in[3];
    const float* Wq      = (const float*)d_in[4];
    const float* bq      = (const float*)d_in[5];
    const float* Wk      = (const float*)d_in[6];
    const float* bk      = (const float*)d_in[7];
    const float* Wv      = (const float*)d_in[8];
    const float* bv      = (const float*)d_in[9];
    const float* Wo      = (const float*)d_in[10];
    const float* bo      = (const float*)d_in[11];
    float* out = (float*)d_out;

    float *pb3, *pqkv;
    __nv_bfloat16 *pah, *pal, *pbh, *pbl;
    __half *pha, *phb;
    cudaGetSymbolAddress((void**)&pb3,  g_b3);
    cudaGetSymbolAddress((void**)&pqkv, g_qkv);
    cudaGetSymbolAddress((void**)&pah,  g_ah);
    cudaGetSymbolAddress((void**)&pal,  g_al);
    cudaGetSymbolAddress((void**)&pbh,  g_bh);
    cudaGetSymbolAddress((void**)&pbl,  g_bl);
    cudaGetSymbolAddress((void**)&pha,  g_ha);
    cudaGetSymbolAddress((void**)&phb,  g_hb);

    cudaFuncSetAttribute(k_gemm_qkv, cudaFuncAttributeMaxDynamicSharedMemorySize, QSMEM);
    cudaFuncSetAttribute(k_gemm_f16, cudaFuncAttributeMaxDynamicSharedMemorySize, FSMEM);
    cudaFuncSetAttribute(k_flash,    cudaFuncAttributeMaxDynamicSharedMemorySize, FL_SMEM);

    // 1. embed + split (fused), weight repacks
    k_embed_split<<<BT, 256>>>(ids, tok_emb, pos_emb);
    k_repack_wqkvT<<<dim3(48, 32, 2), dim3(32, 8)>>>(Wq, Wk, Wv);
    k_repack_b<<<(N3 + 255) / 256, 256>>>(bq, bk, bv);
    k_woT<<<dim3(VV / 32, DD / 32), dim3(32, 8)>>>(Wo);

    // 2. QKV projection (bf16x3): [4096,1024] x [1024,3072]
    k_gemm_qkv<<<dim3(BT / 128, N3 / 128), 256, QSMEM>>>(
        BT, N3, DD, pah, pal, pbh, pbl, pqkv, N3, pb3);

    // 3. fused flash attention (fp32; emits fp16 A for the logits GEMM)
    k_flash<<<dim3(16, BHN), 256, FL_SMEM>>>();

    // 4. logits (pure fp16): [4096,1024] x [1024,32000] + bo
    k_gemm_f16<<<dim3(BT / 128, VV / 128), 256, FSMEM>>>(
        BT, VV, DD, pha, phb, out, VV, bo);

    // 5. loss
    if ((long long)out_size > BTV) {
        k_loss_rows<<<BT, 256>>>(out, targets);
        k_loss_final<<<1, 256>>>(out + BTV);
    }
}

// round 9
// speedup vs baseline: 5.0341x; 1.0237x over previous
#include <cuda_runtime.h>
#include <cuda_bf16.h>
#include <cuda_fp16.h>
#include <math.h>
#include <stdint.h>

// Problem constants
#define BB 4
#define TT 1024
#define VV 32000
#define DD 1024
#define HH 16
#define DKK 64
#define BT 4096            // B*T
#define N3 3072            // 3*D (q|k|v)
#define BHN 64             // B*H
#define BTV 131072000LL    // BT*VV

// ---------------- scratch (device globals; no allocation) ----------------
__device__ float g_b3[N3];                       // repacked qkv bias
__device__ float g_qkv[BT * N3];                 // 48 MB [token][h*64+k | +1024 | +2048]
__device__ float g_rowloss[BT];

__device__ __nv_bfloat16 g_ah[BT * DD];          // x hi (QKV A operand)
__device__ __nv_bfloat16 g_al[BT * DD];          // x lo
__device__ __nv_bfloat16 g_bh[N3 * DD];          // Wqkv hi (K-major [3072,1024])
__device__ __nv_bfloat16 g_bl[N3 * DD];          // Wqkv lo

__device__ __half g_ha[BT * DD];                 // attention-out fp16 (logits A)
__device__ __half g_hb[(size_t)VV * DD];         // Wo^T fp16 (K-major [32000,1024])

// ================= helpers =================
__device__ __forceinline__ uint32_t smem_to_u32(const void* p) {
    uint32_t a;
    asm("{ .reg .u64 t; cvta.to.shared.u64 t, %1; cvt.u32.u64 %0, t; }" : "=r"(a) : "l"(p));
    return a;
}
__device__ __forceinline__ void cp16(uint32_t saddr, const void* gptr) {
    asm volatile("cp.async.cg.shared.global [%0], [%1], 16;" :: "r"(saddr), "l"(gptr));
}
#define LDSM_X4(R0, R1, R2, R3, addr) \
    asm volatile("ldmatrix.sync.aligned.m8n8.x4.shared.b16 {%0,%1,%2,%3}, [%4];" \
                 : "=r"(R0), "=r"(R1), "=r"(R2), "=r"(R3) : "r"(addr))

__device__ __forceinline__ void mma_bf16(float* c,
                                         uint32_t a0, uint32_t a1, uint32_t a2, uint32_t a3,
                                         uint32_t b0, uint32_t b1)
{
    asm volatile(
        "mma.sync.aligned.m16n8k16.row.col.f32.bf16.bf16.f32 "
        "{%0,%1,%2,%3}, {%4,%5,%6,%7}, {%8,%9}, {%0,%1,%2,%3};"
        : "+f"(c[0]), "+f"(c[1]), "+f"(c[2]), "+f"(c[3])
        : "r"(a0), "r"(a1), "r"(a2), "r"(a3), "r"(b0), "r"(b1));
}
__device__ __forceinline__ void mma_f16(float* c,
                                        uint32_t a0, uint32_t a1, uint32_t a2, uint32_t a3,
                                        uint32_t b0, uint32_t b1)
{
    asm volatile(
        "mma.sync.aligned.m16n8k16.row.col.f32.f16.f16.f32 "
        "{%0,%1,%2,%3}, {%4,%5,%6,%7}, {%8,%9}, {%0,%1,%2,%3};"
        : "+f"(c[0]), "+f"(c[1]), "+f"(c[2]), "+f"(c[3])
        : "r"(a0), "r"(a1), "r"(a2), "r"(a3), "r"(b0), "r"(b1));
}

// ============ QKV GEMM: bf16x3 (AhBh + AhBl + AlBh), 128x128 tile, BK=32, 3-stage ============
#define QPITCH 80
#define QARR (128 * QPITCH)          // 10240
#define QSTAGE (4 * QARR)            // 40960
#define QSMEM (3 * QSTAGE)           // 122880
#define QOFF_AH 0
#define QOFF_AL QARR
#define QOFF_BH (2 * QARR)
#define QOFF_BL (3 * QARR)

__global__ __launch_bounds__(256, 1)
void k_gemm_qkv(int M, int N, int K,
                const __nv_bfloat16* __restrict__ Ahi, const __nv_bfloat16* __restrict__ Alo,
                const __nv_bfloat16* __restrict__ Bhi, const __nv_bfloat16* __restrict__ Blo,
                float* __restrict__ C, int ldc, const float* __restrict__ bias)
{
    extern __shared__ char smem[];
    const uint32_t sbase = smem_to_u32(smem);
    const int tid = threadIdx.x;
    const int wid = tid >> 5, lid = tid & 31;
    const int g = lid >> 2, tig = lid & 3;
    const int wm = (wid >> 2) * 64;
    const int wn = (wid & 3) * 32;
    const int bm = blockIdx.x * 128;
    const int bn = blockIdx.y * 128;
    const int nchunks = K >> 5;

    const int r0 = tid >> 2, cA = tid & 3;
    const int r1 = 64 + r0;

    // ldmatrix per-lane row/col components
    const uint32_t aRow = (uint32_t)((wm + (lid & 15)) * QPITCH + ((lid >> 4) << 4));
    const uint32_t bRow = (uint32_t)((wn + (lid & 7) + ((lid >> 4) << 3)) * QPITCH
                                     + (((lid >> 3) & 1) << 4));

    float acc[4][4][4];
    #pragma unroll
    for (int i = 0; i < 4; i++)
        #pragma unroll
        for (int j = 0; j < 4; j++)
            #pragma unroll
            for (int q = 0; q < 4; q++) acc[i][j][q] = 0.0f;

    auto load_stage = [&](int slot, int chunk) {
        const int k0 = chunk << 5;
        const uint32_t st = sbase + slot * QSTAGE;
        const uint32_t s0 = st + r0 * QPITCH + cA * 16;
        const uint32_t s1 = st + r1 * QPITCH + cA * 16;
        cp16(s0 + QOFF_AH, Ahi + (size_t)(bm + r0) * K + k0 + cA * 8);
        cp16(s0 + QOFF_AL, Alo + (size_t)(bm + r0) * K + k0 + cA * 8);
        cp16(s1 + QOFF_AH, Ahi + (size_t)(bm + r1) * K + k0 + cA * 8);
        cp16(s1 + QOFF_AL, Alo + (size_t)(bm + r1) * K + k0 + cA * 8);
        cp16(s0 + QOFF_BH, Bhi + (size_t)(bn + r0) * K + k0 + cA * 8);
        cp16(s0 + QOFF_BL, Blo + (size_t)(bn + r0) * K + k0 + cA * 8);
        cp16(s1 + QOFF_BH, Bhi + (size_t)(bn + r1) * K + k0 + cA * 8);
        cp16(s1 + QOFF_BL, Blo + (size_t)(bn + r1) * K + k0 + cA * 8);
    };

    load_stage(0, 0);
    asm volatile("cp.async.commit_group;");
    load_stage(1, 1);
    asm volatile("cp.async.commit_group;");

    for (int c = 0; c < nchunks; c++) {
        asm volatile("cp.async.wait_group 1;");
        __syncthreads();
        if (c + 2 < nchunks) {
            load_stage((c + 2) % 3, c + 2);
            asm volatile("cp.async.commit_group;");
        }
        const uint32_t stg = sbase + (c % 3) * QSTAGE;

        #pragma unroll
        for (int ks = 0; ks < 2; ks++) {
            const uint32_t ko = (uint32_t)(ks * 32);
            uint32_t Afh[4][4], Afl[4][4];
            #pragma unroll
            for (int mt = 0; mt < 4; mt++) {
                const uint32_t ra = stg + aRow + ko + (uint32_t)(mt * 16 * QPITCH);
                LDSM_X4(Afh[mt][0], Afh[mt][1], Afh[mt][2], Afh[mt][3], ra + QOFF_AH);
                LDSM_X4(Afl[mt][0], Afl[mt][1], Afl[mt][2], Afl[mt][3], ra + QOFF_AL);
            }
            uint32_t Bfh[4][2], Bfl[4][2];
            {
                const uint32_t rb0 = stg + bRow + ko;
                const uint32_t rb1 = rb0 + (uint32_t)(16 * QPITCH);
                LDSM_X4(Bfh[0][0], Bfh[0][1], Bfh[1][0], Bfh[1][1], rb0 + QOFF_BH);
                LDSM_X4(Bfh[2][0], Bfh[2][1], Bfh[3][0], Bfh[3][1], rb1 + QOFF_BH);
                LDSM_X4(Bfl[0][0], Bfl[0][1], Bfl[1][0], Bfl[1][1], rb0 + QOFF_BL);
                LDSM_X4(Bfl[2][0], Bfl[2][1], Bfl[3][0], Bfl[3][1], rb1 + QOFF_BL);
            }
            #pragma unroll
            for (int mt = 0; mt < 4; mt++)
                #pragma unroll
                for (int nt = 0; nt < 4; nt++) {
                    mma_bf16(acc[mt][nt], Afh[mt][0], Afh[mt][1], Afh[mt][2], Afh[mt][3],
                             Bfh[nt][0], Bfh[nt][1]);
                    mma_bf16(acc[mt][nt], Afh[mt][0], Afh[mt][1], Afh[mt][2], Afh[mt][3],
                             Bfl[nt][0], Bfl[nt][1]);
                    mma_bf16(acc[mt][nt], Afl[mt][0], Afl[mt][1], Afl[mt][2], Afl[mt][3],
                             Bfh[nt][0], Bfh[nt][1]);
                }
        }
    }

    #pragma unroll
    for (int mt = 0; mt < 4; mt++) {
        const int row = bm + wm + mt * 16 + g;
        #pragma unroll
        for (int nt = 0; nt < 4; nt++) {
            const int col = bn + wn + nt * 8 + tig * 2;
            const float b0 = bias[col], b1 = bias[col + 1];
            float* p0 = C + (size_t)row * ldc + col;
            float* p1 = C + (size_t)(row + 8) * ldc + col;
            p0[0] = acc[mt][nt][0] + b0;
            p0[1] = acc[mt][nt][1] + b1;
            p1[0] = acc[mt][nt][2] + b0;
            p1[1] = acc[mt][nt][3] + b1;
        }
    }
}

// ============ Logits GEMM: pure fp16, 128x128 tile, BK=64, 3-stage ============
#define FPITCH 144
#define FARR (128 * FPITCH)          // 18432
#define FSTAGE (2 * FARR)            // 36864
#define FSMEM (3 * FSTAGE)           // 110592
#define FOFF_A 0
#define FOFF_B FARR

__global__ __launch_bounds__(256, 1)
void k_gemm_f16(int M, int N, int K,
                const __half* __restrict__ A, const __half* __restrict__ B,
                float* __restrict__ C, int ldc, const float* __restrict__ bias)
{
    extern __shared__ char smem[];
    const uint32_t sbase = smem_to_u32(smem);
    const int tid = threadIdx.x;
    const int wid = tid >> 5, lid = tid & 31;
    const int g = lid >> 2, tig = lid & 3;
    const int wm = (wid >> 2) * 64;
    const int wn = (wid & 3) * 32;
    const int bm = blockIdx.x * 128;    // M fastest -> wave shares B tile
    const int bn = blockIdx.y * 128;
    const int nchunks = K >> 6;

    const uint32_t aRow = (uint32_t)((wm + (lid & 15)) * FPITCH + ((lid >> 4) << 4));
    const uint32_t bRow = (uint32_t)((wn + (lid & 7) + ((lid >> 4) << 3)) * FPITCH
                                     + (((lid >> 3) & 1) << 4));

    float acc[4][4][4];
    #pragma unroll
    for (int i = 0; i < 4; i++)
        #pragma unroll
        for (int j = 0; j < 4; j++)
            #pragma unroll
            for (int q = 0; q < 4; q++) acc[i][j][q] = 0.0f;

    auto load_stage = [&](int slot, int chunk) {
        const int k0 = chunk << 6;
        const uint32_t st = sbase + slot * FSTAGE;
        #pragma unroll
        for (int i = 0; i < 4; i++) {
            const int u = i * 256 + tid;
            const int r = u >> 3, cc = u & 7;
            const uint32_t sa = st + r * FPITCH + cc * 16;
            cp16(sa + FOFF_A, A + (size_t)(bm + r) * K + k0 + cc * 8);
            cp16(sa + FOFF_B, B + (size_t)(bn + r) * K + k0 + cc * 8);
        }
    };

    load_stage(0, 0);
    asm volatile("cp.async.commit_group;");
    load_stage(1, 1);
    asm volatile("cp.async.commit_group;");

    for (int c = 0; c < nchunks; c++) {
        asm volatile("cp.async.wait_group 1;");
        __syncthreads();
        if (c + 2 < nchunks) {
            load_stage((c + 2) % 3, c + 2);
            asm volatile("cp.async.commit_group;");
        }
        const uint32_t stg = sbase + (c % 3) * FSTAGE;

        #pragma unroll
        for (int ks = 0; ks < 4; ks++) {
            const uint32_t ko = (uint32_t)(ks * 32);
            uint32_t Af[4][4];
            #pragma unroll
            for (int mt = 0; mt < 4; mt++) {
                const uint32_t ra = stg + FOFF_A + aRow + ko + (uint32_t)(mt * 16 * FPITCH);
                LDSM_X4(Af[mt][0], Af[mt][1], Af[mt][2], Af[mt][3], ra);
            }
            uint32_t Bf[4][2];
            {
                const uint32_t rb0 = stg + FOFF_B + bRow + ko;
                const uint32_t rb1 = rb0 + (uint32_t)(16 * FPITCH);
                LDSM_X4(Bf[0][0], Bf[0][1], Bf[1][0], Bf[1][1], rb0);
                LDSM_X4(Bf[2][0], Bf[2][1], Bf[3][0], Bf[3][1], rb1);
            }
            #pragma unroll
            for (int mt = 0; mt < 4; mt++)
                #pragma unroll
                for (int nt = 0; nt < 4; nt++)
                    mma_f16(acc[mt][nt], Af[mt][0], Af[mt][1], Af[mt][2], Af[mt][3],
                            Bf[nt][0], Bf[nt][1]);
        }
    }

    #pragma unroll
    for (int mt = 0; mt < 4; mt++) {
        const int row = bm + wm + mt * 16 + g;
        #pragma unroll
        for (int nt = 0; nt < 4; nt++) {
            const int col = bn + wn + nt * 8 + tig * 2;
            const float b0 = bias[col], b1 = bias[col + 1];
            float* p0 = C + (size_t)row * ldc + col;
            float* p1 = C + (size_t)(row + 8) * ldc + col;
            p0[0] = acc[mt][nt][0] + b0;
            p0[1] = acc[mt][nt][1] + b1;
            p1[0] = acc[mt][nt][2] + b0;
            p1[1] = acc[mt][nt][3] + b1;
        }
    }
}

// ---------------- embed + bf16 hi/lo split (fused) ----------------
__global__ void k_embed_split(const int* __restrict__ ids,
                              const float* __restrict__ tok_emb,
                              const float* __restrict__ pos_emb)
{
    int tok = blockIdx.x;
    int t = tok & (TT - 1);
    int v = ids[tok];
    const float* te = tok_emb + (size_t)v * DD;
    const float* pe = pos_emb + (size_t)t * DD;
    __nv_bfloat16* oh = g_ah + (size_t)tok * DD;
    __nv_bfloat16* ol = g_al + (size_t)tok * DD;
    for (int d = threadIdx.x; d < DD; d += blockDim.x) {
        float x = te[d] * 32.0f + pe[d];
        __nv_bfloat16 h = __float2bfloat16_rn(x);
        oh[d] = h;
        ol[d] = __float2bfloat16_rn(x - __bfloat162float(h));
    }
}

// ---------------- repack Wq/Wk/Wv via smem transpose -> K-major bf16 hi/lo ----------------
__global__ void k_repack_wqkvT(const float* __restrict__ Wq,
                               const float* __restrict__ Wk,
                               const float* __restrict__ Wv)
{
    __shared__ float s[32][33];
    const int sh = blockIdx.x;
    const int sel = sh >> 4, h = sh & 15;
    const int d0 = blockIdx.y * 32;
    const int k0 = blockIdx.z * 32;
    const float* src = (sel == 0) ? Wq : (sel == 1) ? Wk : Wv;
    const float* base = src + (size_t)h * (DD * DKK);
    const int tx = threadIdx.x, ty = threadIdx.y;
    #pragma unroll
    for (int i = 0; i < 4; i++)
        s[ty + i * 8][tx] = base[(size_t)(d0 + ty + i * 8) * DKK + k0 + tx];
    __syncthreads();
    #pragma unroll
    for (int i = 0; i < 4; i++) {
        const int k = k0 + ty + i * 8;
        const int n = sel * 1024 + h * 64 + k;
        const int d = d0 + tx;
        const float x = s[tx][ty + i * 8];
        __nv_bfloat16 hh = __float2bfloat16_rn(x);
        g_bh[(size_t)n * DD + d] = hh;
        g_bl[(size_t)n * DD + d] = __float2bfloat16_rn(x - __bfloat162float(hh));
    }
}

__global__ void k_repack_b(const float* __restrict__ bq,
                           const float* __restrict__ bk,
                           const float* __restrict__ bv)
{
    int col = blockIdx.x * blockDim.x + threadIdx.x;
    if (col >= N3) return;
    int sel = col >> 10, c = col & 1023;
    const float* src = (sel == 0) ? bq : (sel == 1) ? bk : bv;
    g_b3[col] = src[c];
}

// ---------------- transpose Wo [1024, 32000] -> fp16 [32000, 1024] ----------------
__global__ void k_woT(const float* __restrict__ Wo)
{
    __shared__ float s[32][33];
    int v0 = blockIdx.x * 32, d0 = blockIdx.y * 32;
    int tx = threadIdx.x, ty = threadIdx.y;  // (32, 8)
    #pragma unroll
    for (int i = 0; i < 4; i++)
        s[ty + i * 8][tx] = Wo[(size_t)(d0 + ty + i * 8) * VV + v0 + tx];
    __syncthreads();
    #pragma unroll
    for (int i = 0; i < 4; i++) {
        int v = v0 + ty + i * 8;
        int d = d0 + tx;
        g_hb[(size_t)v * DD + d] = __float2half(s[tx][ty + i * 8]);
    }
}

// ---------------- fused flash attention (fp32): scores + softmax + PV ----------------
#define FL_Q 0
#define FL_K (64 * 65)
#define FL_V (2 * 64 * 65)
#define FL_P (3 * 64 * 65)
#define FL_SMEM (4 * 64 * 65 * 4)     // 66560 bytes

__global__ __launch_bounds__(256)
void k_flash()
{
    extern __shared__ float fs[];
    const int tT = (int)gridDim.x - 1 - (int)blockIdx.x;   // heavy tiles first
    const int bh = blockIdx.y;
    const int b = bh >> 4, h = bh & 15;
    const int t0 = tT * 64;
    const int tid = threadIdx.x;
    const int tm = (tid >> 4) * 4;
    const int tn = (tid & 15) * 4;

    const size_t qbase = ((size_t)(b * TT + t0)) * N3 + h * 64;
    #pragma unroll
    for (int i = 0; i < 16; i++) {
        int e = i * 256 + tid;
        int r = e >> 6, c = e & 63;
        fs[FL_Q + r * 65 + c] = g_qkv[qbase + (size_t)r * N3 + c];
    }

    float O[4][4] = {};
    float m[4], l[4];
    #pragma unroll
    for (int i = 0; i < 4; i++) { m[i] = -INFINITY; l[i] = 0.0f; }

    for (int s0 = 0; s0 <= t0; s0 += 64) {
        const size_t kbase = ((size_t)(b * TT + s0)) * N3 + 1024 + h * 64;
        const size_t vbase = ((size_t)(b * TT + s0)) * N3 + 2048 + h * 64;
        #pragma unroll
        for (int i = 0; i < 16; i++) {
            int e = i * 256 + tid;
            int r = e >> 6, c = e & 63;
            fs[FL_K + r * 65 + c] = g_qkv[kbase + (size_t)r * N3 + c];
            fs[FL_V + r * 65 + c] = g_qkv[vbase + (size_t)r * N3 + c];
        }
        __syncthreads();

        float S[4][4] = {};
        #pragma unroll 16
        for (int kk = 0; kk < 64; kk++) {
            float a[4], bb[4];
            #pragma unroll
            for (int i = 0; i < 4; i++) a[i]  = fs[FL_Q + (tm + i) * 65 + kk];
            #pragma unroll
            for (int j = 0; j < 4; j++) bb[j] = fs[FL_K + (tn + j) * 65 + kk];
            #pragma unroll
            for (int i = 0; i < 4; i++)
                #pragma unroll
                for (int j = 0; j < 4; j++)
                    S[i][j] = fmaf(a[i], bb[j], S[i][j]);
        }
        const bool diag = (s0 == t0);
        #pragma unroll
        for (int i = 0; i < 4; i++)
            #pragma unroll
            for (int j = 0; j < 4; j++) {
                float sv = S[i][j] * 0.125f;
                if (diag && (tn + j > tm + i)) sv = -INFINITY;
                S[i][j] = sv;
            }

        float fac[4];
        #pragma unroll
        for (int i = 0; i < 4; i++) {
            float rm = fmaxf(fmaxf(S[i][0], S[i][1]), fmaxf(S[i][2], S[i][3]));
            #pragma unroll
            for (int w = 1; w < 16; w <<= 1)
                rm = fmaxf(rm, __shfl_xor_sync(0xFFFFFFFF, rm, w));
            const float mn = fmaxf(m[i], rm);
            fac[i] = __expf(m[i] - mn);
            float rs = 0.0f;
            #pragma unroll
            for (int j = 0; j < 4; j++) {
                S[i][j] = __expf(S[i][j] - mn);
                rs += S[i][j];
            }
            #pragma unroll
            for (int w = 1; w < 16; w <<= 1)
                rs += __shfl_xor_sync(0xFFFFFFFF, rs, w);
            l[i] = l[i] * fac[i] + rs;
            m[i] = mn;
        }
        #pragma unroll
        for (int i = 0; i < 4; i++) {
            #pragma unroll
            for (int j = 0; j < 4; j++) {
                fs[FL_P + (tm + i) * 65 + tn + j] = S[i][j];
                O[i][j] *= fac[i];
            }
        }
        __syncthreads();

        #pragma unroll 16
        for (int ss = 0; ss < 64; ss++) {
            float a[4], bb[4];
            #pragma unroll
            for (int i = 0; i < 4; i++) a[i]  = fs[FL_P + (tm + i) * 65 + ss];
            #pragma unroll
            for (int j = 0; j < 4; j++) bb[j] = fs[FL_V + ss * 65 + tn + j];
            #pragma unroll
            for (int i = 0; i < 4; i++)
                #pragma unroll
                for (int j = 0; j < 4; j++)
                    O[i][j] = fmaf(a[i], bb[j], O[i][j]);
        }
        __syncthreads();
    }

    #pragma unroll
    for (int i = 0; i < 4; i++) {
        const float inv = 1.0f / l[i];
        __half* o = g_ha + ((size_t)(b * TT + t0 + tm + i)) * DD + h * 64 + tn;
        *(__half2*)(o)     = __floats2half2_rn(O[i][0] * inv, O[i][1] * inv);
        *(__half2*)(o + 2) = __floats2half2_rn(O[i][2] * inv, O[i][3] * inv);
    }
}

// ---------------- loss: single-pass online logsumexp per row ----------------
__global__ __launch_bounds__(256)
void k_loss_rows(const float* __restrict__ logits, const int* __restrict__ targets)
{
    const int r = blockIdx.x;
    const float* row = logits + (size_t)r * VV;
    const int tid = threadIdx.x;
    __shared__ float sm[256], ss[256];

    float m = -INFINITY, s = 0.0f;
    for (int i = tid; i < VV; i += 256) {
        float x = row[i];
        if (x <= m) {
            s += __expf(x - m);
        } else {
            s = s * __expf(m - x) + 1.0f;
            m = x;
        }
    }
    sm[tid] = m; ss[tid] = s;
    __syncthreads();
    for (int k = 128; k > 0; k >>= 1) {
        if (tid < k) {
            float m1 = sm[tid], s1 = ss[tid];
            float m2 = sm[tid + k], s2 = ss[tid + k];
            float M = fmaxf(m1, m2);
            sm[tid] = M;
            ss[tid] = s1 * __expf(m1 - M) + s2 * __expf(m2 - M);
        }
        __syncthreads();
    }
    if (tid == 0) {
        int tgt = targets[r];
        float logp = row[tgt] - sm[0] - __logf(ss[0]);
        g_rowloss[r] = -logp;
    }
}

__global__ void k_loss_final(float* out)
{
    const int tid = threadIdx.x;
    __shared__ float red[256];
    float s = 0.0f;
    for (int i = tid; i < BT; i += 256) s += g_rowloss[i];
    red[tid] = s; __syncthreads();
    for (int k = 128; k > 0; k >>= 1) {
        if (tid < k) red[tid] += red[tid + k];
        __syncthreads();
    }
    if (tid == 0) out[0] = red[0] * (1.0f / BT);
}

// ---------------- launch ----------------
extern "C" void kernel_launch(void* const* d_in, const int* in_sizes, int n_in,
                              void* d_out, int out_size)
{
    const int*   ids     = (const int*)  d_in[0];
    const int*   targets = (const int*)  d_in[1];
    const float* tok_emb = (const float*)d_in[2];
    const float* pos_emb = (const float*)d_in[3];
    const float* Wq      = (const float*)d_in[4];
    const float* bq      = (const float*)d_in[5];
    const float* Wk      = (const float*)d_in[6];
    const float* bk      = (const float*)d_in[7];
    const float* Wv      = (const float*)d_in[8];
    const float* bv      = (const float*)d_in[9];
    const float* Wo      = (const float*)d_in[10];
    const float* bo      = (const float*)d_in[11];
    float* out = (float*)d_out;

    float *pb3, *pqkv;
    __nv_bfloat16 *pah, *pal, *pbh, *pbl;
    __half *pha, *phb;
    cudaGetSymbolAddress((void**)&pb3,  g_b3);
    cudaGetSymbolAddress((void**)&pqkv, g_qkv);
    cudaGetSymbolAddress((void**)&pah,  g_ah);
    cudaGetSymbolAddress((void**)&pal,  g_al);
    cudaGetSymbolAddress((void**)&pbh,  g_bh);
    cudaGetSymbolAddress((void**)&pbl,  g_bl);
    cudaGetSymbolAddress((void**)&pha,  g_ha);
    cudaGetSymbolAddress((void**)&phb,  g_hb);

    cudaFuncSetAttribute(k_gemm_qkv, cudaFuncAttributeMaxDynamicSharedMemorySize, QSMEM);
    cudaFuncSetAttribute(k_gemm_f16, cudaFuncAttributeMaxDynamicSharedMemorySize, FSMEM);
    cudaFuncSetAttribute(k_flash,    cudaFuncAttributeMaxDynamicSharedMemorySize, FL_SMEM);

    // 1. embed + split (fused), weight repacks
    k_embed_split<<<BT, 256>>>(ids, tok_emb, pos_emb);
    k_repack_wqkvT<<<dim3(48, 32, 2), dim3(32, 8)>>>(Wq, Wk, Wv);
    k_repack_b<<<(N3 + 255) / 256, 256>>>(bq, bk, bv);
    k_woT<<<dim3(VV / 32, DD / 32), dim3(32, 8)>>>(Wo);

    // 2. QKV projection (bf16x3): [4096,1024] x [1024,3072]
    k_gemm_qkv<<<dim3(BT / 128, N3 / 128), 256, QSMEM>>>(
        BT, N3, DD, pah, pal, pbh, pbl, pqkv, N3, pb3);

    // 3. fused flash attention (fp32; emits fp16 A for the logits GEMM)
    k_flash<<<dim3(16, BHN), 256, FL_SMEM>>>();

    // 4. logits (pure fp16): [4096,1024] x [1024,32000] + bo
    k_gemm_f16<<<dim3(BT / 128, VV / 128), 256, FSMEM>>>(
        BT, VV, DD, pha, phb, out, VV, bo);

    // 5. loss
    if ((long long)out_size > BTV) {
        k_loss_rows<<<BT, 256>>>(out, targets);
        k_loss_final<<<1, 256>>>(out + BTV);
    }
}

// round 10
// speedup vs baseline: 5.9565x; 1.1832x over previous
#include <cuda_runtime.h>
#include <cuda_bf16.h>
#include <cuda_fp16.h>
#include <math.h>
#include <stdint.h>

// Problem constants
#define BB 4
#define TT 1024
#define VV 32000
#define DD 1024
#define HH 16
#define DKK 64
#define BT 4096            // B*T
#define N3 3072            // 3*D (q|k|v)
#define BHN 64             // B*H
#define BTV 131072000LL    // BT*VV

// ---------------- scratch (device globals; no allocation) ----------------
__device__ float g_b3[N3];                       // repacked qkv bias
__device__ float g_rowloss[BT];

__device__ __nv_bfloat16 g_ah[BT * DD];          // x hi (QKV A operand)
__device__ __nv_bfloat16 g_al[BT * DD];          // x lo
__device__ __nv_bfloat16 g_bh[N3 * DD];          // Wqkv hi (K-major [3072,1024])
__device__ __nv_bfloat16 g_bl[N3 * DD];          // Wqkv lo

__device__ __half g_q16[BHN * TT * DKK];         // q fp16 head-major [bh][t][dk]
__device__ __half g_k16[BHN * TT * DKK];         // k fp16
__device__ __half g_v16[BHN * TT * DKK];         // v fp16
__device__ __half g_ha[BT * DD];                 // attention-out fp16 (logits A)
__device__ __half g_hb[(size_t)VV * DD];         // Wo^T fp16 (K-major [32000,1024])

// ================= helpers =================
__device__ __forceinline__ uint32_t smem_to_u32(const void* p) {
    uint32_t a;
    asm("{ .reg .u64 t; cvta.to.shared.u64 t, %1; cvt.u32.u64 %0, t; }" : "=r"(a) : "l"(p));
    return a;
}
__device__ __forceinline__ void cp16(uint32_t saddr, const void* gptr) {
    asm volatile("cp.async.cg.shared.global [%0], [%1], 16;" :: "r"(saddr), "l"(gptr));
}
#define LDSM_X4(R0, R1, R2, R3, addr) \
    asm volatile("ldmatrix.sync.aligned.m8n8.x4.shared.b16 {%0,%1,%2,%3}, [%4];" \
                 : "=r"(R0), "=r"(R1), "=r"(R2), "=r"(R3) : "r"(addr))
#define LDSM_X4_T(R0, R1, R2, R3, addr) \
    asm volatile("ldmatrix.sync.aligned.m8n8.x4.trans.shared.b16 {%0,%1,%2,%3}, [%4];" \
                 : "=r"(R0), "=r"(R1), "=r"(R2), "=r"(R3) : "r"(addr))

__device__ __forceinline__ void mma_bf16(float* c,
                                         uint32_t a0, uint32_t a1, uint32_t a2, uint32_t a3,
                                         uint32_t b0, uint32_t b1)
{
    asm volatile(
        "mma.sync.aligned.m16n8k16.row.col.f32.bf16.bf16.f32 "
        "{%0,%1,%2,%3}, {%4,%5,%6,%7}, {%8,%9}, {%0,%1,%2,%3};"
        : "+f"(c[0]), "+f"(c[1]), "+f"(c[2]), "+f"(c[3])
        : "r"(a0), "r"(a1), "r"(a2), "r"(a3), "r"(b0), "r"(b1));
}
__device__ __forceinline__ void mma_f16(float* c,
                                        uint32_t a0, uint32_t a1, uint32_t a2, uint32_t a3,
                                        uint32_t b0, uint32_t b1)
{
    asm volatile(
        "mma.sync.aligned.m16n8k16.row.col.f32.f16.f16.f32 "
        "{%0,%1,%2,%3}, {%4,%5,%6,%7}, {%8,%9}, {%0,%1,%2,%3};"
        : "+f"(c[0]), "+f"(c[1]), "+f"(c[2]), "+f"(c[3])
        : "r"(a0), "r"(a1), "r"(a2), "r"(a3), "r"(b0), "r"(b1));
}
__device__ __forceinline__ uint32_t packh2(float a, float b) {
    __half2 h = __floats2half2_rn(a, b);
    return *(uint32_t*)&h;
}

// ============ QKV GEMM: bf16x3, 128x128 tile, BK=32, 3-stage; fp16 head-major out ============
#define QPITCH 80
#define QARR (128 * QPITCH)          // 10240
#define QSTAGE (4 * QARR)            // 40960
#define QSMEM (3 * QSTAGE)           // 122880
#define QOFF_AH 0
#define QOFF_AL QARR
#define QOFF_BH (2 * QARR)
#define QOFF_BL (3 * QARR)

__global__ __launch_bounds__(256, 1)
void k_gemm_qkv(int M, int N, int K,
                const __nv_bfloat16* __restrict__ Ahi, const __nv_bfloat16* __restrict__ Alo,
                const __nv_bfloat16* __restrict__ Bhi, const __nv_bfloat16* __restrict__ Blo,
                const float* __restrict__ bias)
{
    extern __shared__ char smem[];
    const uint32_t sbase = smem_to_u32(smem);
    const int tid = threadIdx.x;
    const int wid = tid >> 5, lid = tid & 31;
    const int g = lid >> 2, tig = lid & 3;
    const int wm = (wid >> 2) * 64;
    const int wn = (wid & 3) * 32;
    const int bm = blockIdx.x * 128;
    const int bn = blockIdx.y * 128;
    const int nchunks = K >> 5;

    const int r0 = tid >> 2, cA = tid & 3;
    const int r1 = 64 + r0;

    const uint32_t aRow = (uint32_t)((wm + (lid & 15)) * QPITCH + ((lid >> 4) << 4));
    const uint32_t bRow = (uint32_t)((wn + (lid & 7) + ((lid >> 4) << 3)) * QPITCH
                                     + (((lid >> 3) & 1) << 4));

    float acc[4][4][4];
    #pragma unroll
    for (int i = 0; i < 4; i++)
        #pragma unroll
        for (int j = 0; j < 4; j++)
            #pragma unroll
            for (int q = 0; q < 4; q++) acc[i][j][q] = 0.0f;

    auto load_stage = [&](int slot, int chunk) {
        const int k0 = chunk << 5;
        const uint32_t st = sbase + slot * QSTAGE;
        const uint32_t s0 = st + r0 * QPITCH + cA * 16;
        const uint32_t s1 = st + r1 * QPITCH + cA * 16;
        cp16(s0 + QOFF_AH, Ahi + (size_t)(bm + r0) * K + k0 + cA * 8);
        cp16(s0 + QOFF_AL, Alo + (size_t)(bm + r0) * K + k0 + cA * 8);
        cp16(s1 + QOFF_AH, Ahi + (size_t)(bm + r1) * K + k0 + cA * 8);
        cp16(s1 + QOFF_AL, Alo + (size_t)(bm + r1) * K + k0 + cA * 8);
        cp16(s0 + QOFF_BH, Bhi + (size_t)(bn + r0) * K + k0 + cA * 8);
        cp16(s0 + QOFF_BL, Blo + (size_t)(bn + r0) * K + k0 + cA * 8);
        cp16(s1 + QOFF_BH, Bhi + (size_t)(bn + r1) * K + k0 + cA * 8);
        cp16(s1 + QOFF_BL, Blo + (size_t)(bn + r1) * K + k0 + cA * 8);
    };

    load_stage(0, 0);
    asm volatile("cp.async.commit_group;");
    load_stage(1, 1);
    asm volatile("cp.async.commit_group;");

    for (int c = 0; c < nchunks; c++) {
        asm volatile("cp.async.wait_group 1;");
        __syncthreads();
        if (c + 2 < nchunks) {
            load_stage((c + 2) % 3, c + 2);
            asm volatile("cp.async.commit_group;");
        }
        const uint32_t stg = sbase + (c % 3) * QSTAGE;

        #pragma unroll
        for (int ks = 0; ks < 2; ks++) {
            const uint32_t ko = (uint32_t)(ks * 32);
            uint32_t Afh[4][4], Afl[4][4];
            #pragma unroll
            for (int mt = 0; mt < 4; mt++) {
                const uint32_t ra = stg + aRow + ko + (uint32_t)(mt * 16 * QPITCH);
                LDSM_X4(Afh[mt][0], Afh[mt][1], Afh[mt][2], Afh[mt][3], ra + QOFF_AH);
                LDSM_X4(Afl[mt][0], Afl[mt][1], Afl[mt][2], Afl[mt][3], ra + QOFF_AL);
            }
            uint32_t Bfh[4][2], Bfl[4][2];
            {
                const uint32_t rb0 = stg + bRow + ko;
                const uint32_t rb1 = rb0 + (uint32_t)(16 * QPITCH);
                LDSM_X4(Bfh[0][0], Bfh[0][1], Bfh[1][0], Bfh[1][1], rb0 + QOFF_BH);
                LDSM_X4(Bfh[2][0], Bfh[2][1], Bfh[3][0], Bfh[3][1], rb1 + QOFF_BH);
                LDSM_X4(Bfl[0][0], Bfl[0][1], Bfl[1][0], Bfl[1][1], rb0 + QOFF_BL);
                LDSM_X4(Bfl[2][0], Bfl[2][1], Bfl[3][0], Bfl[3][1], rb1 + QOFF_BL);
            }
            #pragma unroll
            for (int mt = 0; mt < 4; mt++)
                #pragma unroll
                for (int nt = 0; nt < 4; nt++) {
                    mma_bf16(acc[mt][nt], Afh[mt][0], Afh[mt][1], Afh[mt][2], Afh[mt][3],
                             Bfh[nt][0], Bfh[nt][1]);
                    mma_bf16(acc[mt][nt], Afh[mt][0], Afh[mt][1], Afh[mt][2], Afh[mt][3],
                             Bfl[nt][0], Bfl[nt][1]);
                    mma_bf16(acc[mt][nt], Afl[mt][0], Afl[mt][1], Afl[mt][2], Afl[mt][3],
                             Bfh[nt][0], Bfh[nt][1]);
                }
        }
    }

    // epilogue: bias + fp16, head-major q/k/v
    #pragma unroll
    for (int mt = 0; mt < 4; mt++) {
        const int row = bm + wm + mt * 16 + g;     // token (rows row, row+8 share b)
        const int b_ = row >> 10, t_ = row & 1023;
        #pragma unroll
        for (int nt = 0; nt < 4; nt++) {
            const int col = bn + wn + nt * 8 + tig * 2;
            const float b0 = bias[col], b1 = bias[col + 1];
            const int sel = col >> 10, hc = col & 1023;
            const int h = hc >> 6, dk = hc & 63;
            __half* dst = (sel == 0) ? g_q16 : (sel == 1) ? g_k16 : g_v16;
            const size_t o0 = ((size_t)(b_ * HH + h) * TT + t_) * DKK + dk;
            *(__half2*)(dst + o0) =
                __floats2half2_rn(acc[mt][nt][0] + b0, acc[mt][nt][1] + b1);
            *(__half2*)(dst + o0 + 8 * DKK) =
                __floats2half2_rn(acc[mt][nt][2] + b0, acc[mt][nt][3] + b1);
        }
    }
}

// ============ Logits GEMM: pure fp16, 128x128 tile, BK=64, 3-stage ============
#define FPITCH 144
#define FARR (128 * FPITCH)          // 18432
#define FSTAGE (2 * FARR)            // 36864
#define FSMEM (3 * FSTAGE)           // 110592
#define FOFF_A 0
#define FOFF_B FARR

__global__ __launch_bounds__(256, 1)
void k_gemm_f16(int M, int N, int K,
                const __half* __restrict__ A, const __half* __restrict__ B,
                float* __restrict__ C, int ldc, const float* __restrict__ bias)
{
    extern __shared__ char smem[];
    const uint32_t sbase = smem_to_u32(smem);
    const int tid = threadIdx.x;
    const int wid = tid >> 5, lid = tid & 31;
    const int g = lid >> 2, tig = lid & 3;
    const int wm = (wid >> 2) * 64;
    const int wn = (wid & 3) * 32;
    const int bm = blockIdx.x * 128;    // M fastest -> wave shares B tile
    const int bn = blockIdx.y * 128;
    const int nchunks = K >> 6;

    const uint32_t aRow = (uint32_t)((wm + (lid & 15)) * FPITCH + ((lid >> 4) << 4));
    const uint32_t bRow = (uint32_t)((wn + (lid & 7) + ((lid >> 4) << 3)) * FPITCH
                                     + (((lid >> 3) & 1) << 4));

    float acc[4][4][4];
    #pragma unroll
    for (int i = 0; i < 4; i++)
        #pragma unroll
        for (int j = 0; j < 4; j++)
            #pragma unroll
            for (int q = 0; q < 4; q++) acc[i][j][q] = 0.0f;

    auto load_stage = [&](int slot, int chunk) {
        const int k0 = chunk << 6;
        const uint32_t st = sbase + slot * FSTAGE;
        #pragma unroll
        for (int i = 0; i < 4; i++) {
            const int u = i * 256 + tid;
            const int r = u >> 3, cc = u & 7;
            const uint32_t sa = st + r * FPITCH + cc * 16;
            cp16(sa + FOFF_A, A + (size_t)(bm + r) * K + k0 + cc * 8);
            cp16(sa + FOFF_B, B + (size_t)(bn + r) * K + k0 + cc * 8);
        }
    };

    load_stage(0, 0);
    asm volatile("cp.async.commit_group;");
    load_stage(1, 1);
    asm volatile("cp.async.commit_group;");

    for (int c = 0; c < nchunks; c++) {
        asm volatile("cp.async.wait_group 1;");
        __syncthreads();
        if (c + 2 < nchunks) {
            load_stage((c + 2) % 3, c + 2);
            asm volatile("cp.async.commit_group;");
        }
        const uint32_t stg = sbase + (c % 3) * FSTAGE;

        #pragma unroll
        for (int ks = 0; ks < 4; ks++) {
            const uint32_t ko = (uint32_t)(ks * 32);
            uint32_t Af[4][4];
            #pragma unroll
            for (int mt = 0; mt < 4; mt++) {
                const uint32_t ra = stg + FOFF_A + aRow + ko + (uint32_t)(mt * 16 * FPITCH);
                LDSM_X4(Af[mt][0], Af[mt][1], Af[mt][2], Af[mt][3], ra);
            }
            uint32_t Bf[4][2];
            {
                const uint32_t rb0 = stg + FOFF_B + bRow + ko;
                const uint32_t rb1 = rb0 + (uint32_t)(16 * FPITCH);
                LDSM_X4(Bf[0][0], Bf[0][1], Bf[1][0], Bf[1][1], rb0);
                LDSM_X4(Bf[2][0], Bf[2][1], Bf[3][0], Bf[3][1], rb1);
            }
            #pragma unroll
            for (int mt = 0; mt < 4; mt++)
                #pragma unroll
                for (int nt = 0; nt < 4; nt++)
                    mma_f16(acc[mt][nt], Af[mt][0], Af[mt][1], Af[mt][2], Af[mt][3],
                            Bf[nt][0], Bf[nt][1]);
        }
    }

    #pragma unroll
    for (int mt = 0; mt < 4; mt++) {
        const int row = bm + wm + mt * 16 + g;
        #pragma unroll
        for (int nt = 0; nt < 4; nt++) {
            const int col = bn + wn + nt * 8 + tig * 2;
            const float b0 = bias[col], b1 = bias[col + 1];
            float* p0 = C + (size_t)row * ldc + col;
            float* p1 = C + (size_t)(row + 8) * ldc + col;
            p0[0] = acc[mt][nt][0] + b0;
            p0[1] = acc[mt][nt][1] + b1;
            p1[0] = acc[mt][nt][2] + b0;
            p1[1] = acc[mt][nt][3] + b1;
        }
    }
}

// ---------------- embed + bf16 hi/lo split (fused) ----------------
__global__ void k_embed_split(const int* __restrict__ ids,
                              const float* __restrict__ tok_emb,
                              const float* __restrict__ pos_emb)
{
    int tok = blockIdx.x;
    int t = tok & (TT - 1);
    int v = ids[tok];
    const float* te = tok_emb + (size_t)v * DD;
    const float* pe = pos_emb + (size_t)t * DD;
    __nv_bfloat16* oh = g_ah + (size_t)tok * DD;
    __nv_bfloat16* ol = g_al + (size_t)tok * DD;
    for (int d = threadIdx.x; d < DD; d += blockDim.x) {
        float x = te[d] * 32.0f + pe[d];
        __nv_bfloat16 h = __float2bfloat16_rn(x);
        oh[d] = h;
        ol[d] = __float2bfloat16_rn(x - __bfloat162float(h));
    }
}

// ---------------- repack Wq/Wk/Wv via smem transpose -> K-major bf16 hi/lo ----------------
__global__ void k_repack_wqkvT(const float* __restrict__ Wq,
                               const float* __restrict__ Wk,
                               const float* __restrict__ Wv)
{
    __shared__ float s[32][33];
    const int sh = blockIdx.x;
    const int sel = sh >> 4, h = sh & 15;
    const int d0 = blockIdx.y * 32;
    const int k0 = blockIdx.z * 32;
    const float* src = (sel == 0) ? Wq : (sel == 1) ? Wk : Wv;
    const float* base = src + (size_t)h * (DD * DKK);
    const int tx = threadIdx.x, ty = threadIdx.y;
    #pragma unroll
    for (int i = 0; i < 4; i++)
        s[ty + i * 8][tx] = base[(size_t)(d0 + ty + i * 8) * DKK + k0 + tx];
    __syncthreads();
    #pragma unroll
    for (int i = 0; i < 4; i++) {
        const int k = k0 + ty + i * 8;
        const int n = sel * 1024 + h * 64 + k;
        const int d = d0 + tx;
        const float x = s[tx][ty + i * 8];
        __nv_bfloat16 hh = __float2bfloat16_rn(x);
        g_bh[(size_t)n * DD + d] = hh;
        g_bl[(size_t)n * DD + d] = __float2bfloat16_rn(x - __bfloat162float(hh));
    }
}

__global__ void k_repack_b(const float* __restrict__ bq,
                           const float* __restrict__ bk,
                           const float* __restrict__ bv)
{
    int col = blockIdx.x * blockDim.x + threadIdx.x;
    if (col >= N3) return;
    int sel = col >> 10, c = col & 1023;
    const float* src = (sel == 0) ? bq : (sel == 1) ? bk : bv;
    g_b3[col] = src[c];
}

// ---------------- transpose Wo [1024, 32000] -> fp16 [32000, 1024] ----------------
__global__ void k_woT(const float* __restrict__ Wo)
{
    __shared__ float s[32][33];
    int v0 = blockIdx.x * 32, d0 = blockIdx.y * 32;
    int tx = threadIdx.x, ty = threadIdx.y;  // (32, 8)
    #pragma unroll
    for (int i = 0; i < 4; i++)
        s[ty + i * 8][tx] = Wo[(size_t)(d0 + ty + i * 8) * VV + v0 + tx];
    __syncthreads();
    #pragma unroll
    for (int i = 0; i < 4; i++) {
        int v = v0 + ty + i * 8;
        int d = d0 + tx;
        g_hb[(size_t)v * DD + d] = __float2half(s[tx][ty + i * 8]);
    }
}

// ---------------- tensor-core flash attention ----------------
// grid (8 tTiles reversed, 64 bh), 256 thr (8 warps x 16 t-rows = 128 rows/CTA).
// smem: Q fp16 [128][64] pitch 144 | 3 stages of (K,V) fp16 [64][64] pitch 144.
#define PL 144
#define FLK_BYTES (64 * PL)                 // 9216
#define FLQ_BYTES (128 * PL)                // 18432
#define FL2_STAGE (2 * FLK_BYTES)           // 18432
#define FL2_SMEM (FLQ_BYTES + 3 * FL2_STAGE) // 73728

__global__ __launch_bounds__(256, 1)
void k_flash_tc()
{
    extern __shared__ char smem[];
    const uint32_t sbase = smem_to_u32(smem);
    const int tid = threadIdx.x;
    const int w = tid >> 5, lid = tid & 31;
    const int g = lid >> 2, tig = lid & 3;
    const int tT = 7 - (int)blockIdx.x;      // heavy tiles first
    const int bh = blockIdx.y;
    const int t0 = tT * 128;
    const int wr = w * 16;
    const int nb = t0 / 64 + 2;

    const __half* gq = g_q16 + (size_t)bh * TT * DKK;
    const __half* gk = g_k16 + (size_t)bh * TT * DKK;
    const __half* gv = g_v16 + (size_t)bh * TT * DKK;

    auto load_kv = [&](int slot, int s0) {
        const uint32_t st = sbase + FLQ_BYTES + slot * FL2_STAGE;
        #pragma unroll
        for (int i = 0; i < 2; i++) {
            int u = i * 256 + tid;          // 0..511
            int r = u >> 3, cc = u & 7;
            uint32_t sa = st + r * PL + cc * 16;
            cp16(sa, gk + (size_t)(s0 + r) * DKK + cc * 8);
            cp16(sa + FLK_BYTES, gv + (size_t)(s0 + r) * DKK + cc * 8);
        }
    };

    // Q load (grouped with KV block 0)
    #pragma unroll
    for (int i = 0; i < 4; i++) {
        int u = i * 256 + tid;              // 0..1023
        int r = u >> 3, cc = u & 7;
        cp16(sbase + r * PL + cc * 16, gq + (size_t)(t0 + r) * DKK + cc * 8);
    }
    load_kv(0, 0);
    asm volatile("cp.async.commit_group;");
    load_kv(1, 64);
    asm volatile("cp.async.commit_group;");

    const uint32_t aoff = (uint32_t)((lid & 15) * PL + ((lid >> 4) << 4));
    const uint32_t boff = (uint32_t)(((lid & 7) + ((lid >> 4) << 3)) * PL
                                     + (((lid >> 3) & 1) << 4));
    const uint32_t voff = aoff;             // same lane formula for trans V

    float O[8][4];
    #pragma unroll
    for (int j = 0; j < 8; j++)
        #pragma unroll
        for (int q = 0; q < 4; q++) O[j][q] = 0.0f;
    float m0 = -INFINITY, m1 = -INFINITY, l0 = 0.0f, l1 = 0.0f;

    const int trow0 = t0 + wr + g;
    const int trow1 = trow0 + 8;

    for (int c = 0; c < nb; c++) {
        const int s0 = c * 64;
        if (c + 2 <= nb) asm volatile("cp.async.wait_group 1;");
        else             asm volatile("cp.async.wait_group 0;");
        __syncthreads();
        if (c + 2 < nb) {
            load_kv((c + 2) % 3, (c + 2) * 64);
            asm volatile("cp.async.commit_group;");
        }

        if (s0 <= t0 + wr + 15) {           // warp has at least one unmasked row
            const uint32_t stK = sbase + FLQ_BYTES + (c % 3) * FL2_STAGE;
            const uint32_t stV = stK + FLK_BYTES;

            // S = Q K^T
            uint32_t Af[4][4];
            #pragma unroll
            for (int ks = 0; ks < 4; ks++)
                LDSM_X4(Af[ks][0], Af[ks][1], Af[ks][2], Af[ks][3],
                        sbase + (uint32_t)(wr * PL) + aoff + ks * 32);
            float S[8][4];
            #pragma unroll
            for (int j = 0; j < 8; j++)
                #pragma unroll
                for (int q = 0; q < 4; q++) S[j][q] = 0.0f;
            #pragma unroll
            for (int ks = 0; ks < 4; ks++) {
                uint32_t Bf[8][2];
                #pragma unroll
                for (int jp = 0; jp < 4; jp++)
                    LDSM_X4(Bf[2 * jp][0], Bf[2 * jp][1], Bf[2 * jp + 1][0], Bf[2 * jp + 1][1],
                            stK + boff + (uint32_t)(jp * 16 * PL) + ks * 32);
                #pragma unroll
                for (int j = 0; j < 8; j++)
                    mma_f16(S[j], Af[ks][0], Af[ks][1], Af[ks][2], Af[ks][3],
                            Bf[j][0], Bf[j][1]);
            }

            // scale + causal mask (only the top two s-blocks can mask)
            const bool domask = (s0 + 63 > t0 + wr);
            #pragma unroll
            for (int j = 0; j < 8; j++) {
                #pragma unroll
                for (int q = 0; q < 4; q++) S[j][q] *= 0.125f;
                if (domask) {
                    const int sc = s0 + j * 8 + tig * 2;
                    if (sc     > trow0) S[j][0] = -INFINITY;
                    if (sc + 1 > trow0) S[j][1] = -INFINITY;
                    if (sc     > trow1) S[j][2] = -INFINITY;
                    if (sc + 1 > trow1) S[j][3] = -INFINITY;
                }
            }

            // online softmax (rows trow0, trow1; row spread over quad lanes)
            float rm0 = -INFINITY, rm1 = -INFINITY;
            #pragma unroll
            for (int j = 0; j < 8; j++) {
                rm0 = fmaxf(rm0, fmaxf(S[j][0], S[j][1]));
                rm1 = fmaxf(rm1, fmaxf(S[j][2], S[j][3]));
            }
            rm0 = fmaxf(rm0, __shfl_xor_sync(0xFFFFFFFF, rm0, 1));
            rm0 = fmaxf(rm0, __shfl_xor_sync(0xFFFFFFFF, rm0, 2));
            rm1 = fmaxf(rm1, __shfl_xor_sync(0xFFFFFFFF, rm1, 1));
            rm1 = fmaxf(rm1, __shfl_xor_sync(0xFFFFFFFF, rm1, 2));
            const float mn0 = fmaxf(m0, rm0), mn1 = fmaxf(m1, rm1);
            const float fac0 = __expf(m0 - mn0), fac1 = __expf(m1 - mn1);
            float rs0 = 0.0f, rs1 = 0.0f;
            #pragma unroll
            for (int j = 0; j < 8; j++) {
                S[j][0] = __expf(S[j][0] - mn0);
                S[j][1] = __expf(S[j][1] - mn0);
                S[j][2] = __expf(S[j][2] - mn1);
                S[j][3] = __expf(S[j][3] - mn1);
                rs0 += S[j][0] + S[j][1];
                rs1 += S[j][2] + S[j][3];
            }
            rs0 += __shfl_xor_sync(0xFFFFFFFF, rs0, 1);
            rs0 += __shfl_xor_sync(0xFFFFFFFF, rs0, 2);
            rs1 += __shfl_xor_sync(0xFFFFFFFF, rs1, 1);
            rs1 += __shfl_xor_sync(0xFFFFFFFF, rs1, 2);
            l0 = l0 * fac0 + rs0;  m0 = mn0;
            l1 = l1 * fac1 + rs1;  m1 = mn1;
            #pragma unroll
            for (int j = 0; j < 8; j++) {
                O[j][0] *= fac0; O[j][1] *= fac0;
                O[j][2] *= fac1; O[j][3] *= fac1;
            }

            // P fragments (accum -> A-frag identity), then O += P V
            uint32_t Pa[4][4];
            #pragma unroll
            for (int ks = 0; ks < 4; ks++) {
                const int j0 = 2 * ks, j1 = 2 * ks + 1;
                Pa[ks][0] = packh2(S[j0][0], S[j0][1]);
                Pa[ks][1] = packh2(S[j0][2], S[j0][3]);
                Pa[ks][2] = packh2(S[j1][0], S[j1][1]);
                Pa[ks][3] = packh2(S[j1][2], S[j1][3]);
            }
            #pragma unroll
            for (int ks = 0; ks < 4; ks++) {
                #pragma unroll
                for (int dp = 0; dp < 4; dp++) {
                    uint32_t Vb[4];
                    LDSM_X4_T(Vb[0], Vb[1], Vb[2], Vb[3],
                              stV + voff + (uint32_t)(ks * 16 * PL) + dp * 32);
                    mma_f16(O[2 * dp],     Pa[ks][0], Pa[ks][1], Pa[ks][2], Pa[ks][3],
                            Vb[0], Vb[1]);
                    mma_f16(O[2 * dp + 1], Pa[ks][0], Pa[ks][1], Pa[ks][2], Pa[ks][3],
                            Vb[2], Vb[3]);
                }
            }
        }
    }

    // normalize + write fp16 concat-head layout
    const float inv0 = 1.0f / l0, inv1 = 1.0f / l1;
    const int b_ = bh >> 4, h_ = bh & 15;
    __half* o0 = g_ha + (size_t)(b_ * TT + trow0) * DD + h_ * 64;
    __half* o1 = g_ha + (size_t)(b_ * TT + trow1) * DD + h_ * 64;
    #pragma unroll
    for (int j = 0; j < 8; j++) {
        const int col = j * 8 + tig * 2;
        *(__half2*)(o0 + col) = __floats2half2_rn(O[j][0] * inv0, O[j][1] * inv0);
        *(__half2*)(o1 + col) = __floats2half2_rn(O[j][2] * inv1, O[j][3] * inv1);
    }
}

// ---------------- loss: single-pass online logsumexp per row ----------------
__global__ __launch_bounds__(256)
void k_loss_rows(const float* __restrict__ logits, const int* __restrict__ targets)
{
    const int r = blockIdx.x;
    const float* row = logits + (size_t)r * VV;
    const int tid = threadIdx.x;
    __shared__ float sm[256], ss[256];

    float m = -INFINITY, s = 0.0f;
    for (int i = tid; i < VV; i += 256) {
        float x = row[i];
        if (x <= m) {
            s += __expf(x - m);
        } else {
            s = s * __expf(m - x) + 1.0f;
            m = x;
        }
    }
    sm[tid] = m; ss[tid] = s;
    __syncthreads();
    for (int k = 128; k > 0; k >>= 1) {
        if (tid < k) {
            float m1 = sm[tid], s1 = ss[tid];
            float m2 = sm[tid + k], s2 = ss[tid + k];
            float M = fmaxf(m1, m2);
            sm[tid] = M;
            ss[tid] = s1 * __expf(m1 - M) + s2 * __expf(m2 - M);
        }
        __syncthreads();
    }
    if (tid == 0) {
        int tgt = targets[r];
        float logp = row[tgt] - sm[0] - __logf(ss[0]);
        g_rowloss[r] = -logp;
    }
}

__global__ void k_loss_final(float* out)
{
    const int tid = threadIdx.x;
    __shared__ float red[256];
    float s = 0.0f;
    for (int i = tid; i < BT; i += 256) s += g_rowloss[i];
    red[tid] = s; __syncthreads();
    for (int k = 128; k > 0; k >>= 1) {
        if (tid < k) red[tid] += red[tid + k];
        __syncthreads();
    }
    if (tid == 0) out[0] = red[0] * (1.0f / BT);
}

// ---------------- launch ----------------
extern "C" void kernel_launch(void* const* d_in, const int* in_sizes, int n_in,
                              void* d_out, int out_size)
{
    const int*   ids     = (const int*)  d_in[0];
    const int*   targets = (const int*)  d_in[1];
    const float* tok_emb = (const float*)d_in[2];
    const float* pos_emb = (const float*)d_in[3];
    const float* Wq      = (const float*)d_in[4];
    const float* bq      = (const float*)d_in[5];
    const float* Wk      = (const float*)d_in[6];
    const float* bk      = (const float*)d_in[7];
    const float* Wv      = (const float*)d_in[8];
    const float* bv      = (const float*)d_in[9];
    const float* Wo      = (const float*)d_in[10];
    const float* bo      = (const float*)d_in[11];
    float* out = (float*)d_out;

    float* pb3;
    __nv_bfloat16 *pah, *pal, *pbh, *pbl;
    __half *pha, *phb;
    cudaGetSymbolAddress((void**)&pb3, g_b3);
    cudaGetSymbolAddress((void**)&pah, g_ah);
    cudaGetSymbolAddress((void**)&pal, g_al);
    cudaGetSymbolAddress((void**)&pbh, g_bh);
    cudaGetSymbolAddress((void**)&pbl, g_bl);
    cudaGetSymbolAddress((void**)&pha, g_ha);
    cudaGetSymbolAddress((void**)&phb, g_hb);

    cudaFuncSetAttribute(k_gemm_qkv, cudaFuncAttributeMaxDynamicSharedMemorySize, QSMEM);
    cudaFuncSetAttribute(k_gemm_f16, cudaFuncAttributeMaxDynamicSharedMemorySize, FSMEM);
    cudaFuncSetAttribute(k_flash_tc, cudaFuncAttributeMaxDynamicSharedMemorySize, FL2_SMEM);

    // 1. embed + split (fused), weight repacks
    k_embed_split<<<BT, 256>>>(ids, tok_emb, pos_emb);
    k_repack_wqkvT<<<dim3(48, 32, 2), dim3(32, 8)>>>(Wq, Wk, Wv);
    k_repack_b<<<(N3 + 255) / 256, 256>>>(bq, bk, bv);
    k_woT<<<dim3(VV / 32, DD / 32), dim3(32, 8)>>>(Wo);

    // 2. QKV projection (bf16x3) -> fp16 head-major q/k/v
    k_gemm_qkv<<<dim3(BT / 128, N3 / 128), 256, QSMEM>>>(
        BT, N3, DD, pah, pal, pbh, pbl, pb3);

    // 3. tensor-core flash attention (emits fp16 A for the logits GEMM)
    k_flash_tc<<<dim3(8, BHN), 256, FL2_SMEM>>>();

    // 4. logits (pure fp16): [4096,1024] x [1024,32000] + bo
    k_gemm_f16<<<dim3(BT / 128, VV / 128), 256, FSMEM>>>(
        BT, VV, DD, pha, phb, out, VV, bo);

    // 5. loss
    if ((long long)out_size > BTV) {
        k_loss_rows<<<BT, 256>>>(out, targets);
        k_loss_final<<<1, 256>>>(out + BTV);
    }
}

// round 11
// speedup vs baseline: 8.2519x; 1.3854x over previous
#include <cuda_runtime.h>
#include <cuda_bf16.h>
#include <cuda_fp16.h>
#include <math.h>
#include <stdint.h>

// Problem constants
#define BB 4
#define TT 1024
#define VV 32000
#define DD 1024
#define HH 16
#define DKK 64
#define BT 4096            // B*T
#define N3 3072            // 3*D (q|k|v)
#define BHN 64             // B*H
#define BTV 131072000LL    // BT*VV

// ---------------- scratch (device globals; no allocation) ----------------
__device__ float g_b3[N3];                       // repacked qkv bias
__device__ float g_rowloss[BT];

__device__ __half g_x16[BT * DD];                // embedded input fp16 (QKV A)
__device__ __half g_w16[N3 * DD];                // Wqkv fp16 K-major [3072,1024]
__device__ __half g_q16[BHN * TT * DKK];         // q fp16 head-major [bh][t][dk]
__device__ __half g_k16[BHN * TT * DKK];         // k fp16
__device__ __half g_v16[BHN * TT * DKK];         // v fp16
__device__ __half g_ha[BT * DD];                 // attention-out fp16 (logits A)
__device__ __half g_hb[(size_t)VV * DD];         // Wo^T fp16 (K-major [32000,1024])

// ================= helpers =================
__device__ __forceinline__ uint32_t smem_to_u32(const void* p) {
    uint32_t a;
    asm("{ .reg .u64 t; cvta.to.shared.u64 t, %1; cvt.u32.u64 %0, t; }" : "=r"(a) : "l"(p));
    return a;
}
__device__ __forceinline__ void cp16(uint32_t saddr, const void* gptr) {
    asm volatile("cp.async.cg.shared.global [%0], [%1], 16;" :: "r"(saddr), "l"(gptr));
}
#define LDSM_X4(R0, R1, R2, R3, addr) \
    asm volatile("ldmatrix.sync.aligned.m8n8.x4.shared.b16 {%0,%1,%2,%3}, [%4];" \
                 : "=r"(R0), "=r"(R1), "=r"(R2), "=r"(R3) : "r"(addr))
#define LDSM_X4_T(R0, R1, R2, R3, addr) \
    asm volatile("ldmatrix.sync.aligned.m8n8.x4.trans.shared.b16 {%0,%1,%2,%3}, [%4];" \
                 : "=r"(R0), "=r"(R1), "=r"(R2), "=r"(R3) : "r"(addr))

__device__ __forceinline__ void mma_f16(float* c,
                                        uint32_t a0, uint32_t a1, uint32_t a2, uint32_t a3,
                                        uint32_t b0, uint32_t b1)
{
    asm volatile(
        "mma.sync.aligned.m16n8k16.row.col.f32.f16.f16.f32 "
        "{%0,%1,%2,%3}, {%4,%5,%6,%7}, {%8,%9}, {%0,%1,%2,%3};"
        : "+f"(c[0]), "+f"(c[1]), "+f"(c[2]), "+f"(c[3])
        : "r"(a0), "r"(a1), "r"(a2), "r"(a3), "r"(b0), "r"(b1));
}
__device__ __forceinline__ uint32_t packh2(float a, float b) {
    __half2 h = __floats2half2_rn(a, b);
    return *(uint32_t*)&h;
}

// ============ fp16 GEMM core: 128x128 tile, BK=64, 3-stage, occupancy 2 ============
#define FPITCH 144
#define FARR (128 * FPITCH)          // 18432
#define FSTAGE (2 * FARR)            // 36864
#define FSMEM (3 * FSTAGE)           // 110592
#define FOFF_A 0
#define FOFF_B FARR

// mainloop producing acc[4][4][4]; shared between the two GEMMs via macro
#define GEMM_F16_MAINLOOP(Aptr, Bptr, Kdim)                                        \
    const uint32_t aRow = (uint32_t)((wm + (lid & 15)) * FPITCH + ((lid >> 4) << 4)); \
    const uint32_t bRow = (uint32_t)((wn + (lid & 7) + ((lid >> 4) << 3)) * FPITCH    \
                                     + (((lid >> 3) & 1) << 4));                      \
    float acc[4][4][4];                                                            \
    _Pragma("unroll")                                                              \
    for (int i = 0; i < 4; i++)                                                    \
        _Pragma("unroll")                                                          \
        for (int j = 0; j < 4; j++)                                                \
            _Pragma("unroll")                                                      \
            for (int q = 0; q < 4; q++) acc[i][j][q] = 0.0f;                       \
    auto load_stage = [&](int slot, int chunk) {                                   \
        const int k0 = chunk << 6;                                                 \
        const uint32_t st = sbase + slot * FSTAGE;                                 \
        _Pragma("unroll")                                                          \
        for (int i = 0; i < 4; i++) {                                              \
            const int u = i * 256 + tid;                                           \
            const int r = u >> 3, cc = u & 7;                                      \
            const uint32_t sa = st + r * FPITCH + cc * 16;                         \
            cp16(sa + FOFF_A, (Aptr) + (size_t)(bm + r) * (Kdim) + k0 + cc * 8);   \
            cp16(sa + FOFF_B, (Bptr) + (size_t)(bn + r) * (Kdim) + k0 + cc * 8);   \
        }                                                                          \
    };                                                                             \
    load_stage(0, 0);                                                              \
    asm volatile("cp.async.commit_group;");                                        \
    load_stage(1, 1);                                                              \
    asm volatile("cp.async.commit_group;");                                        \
    const int nchunks = (Kdim) >> 6;                                               \
    for (int c = 0; c < nchunks; c++) {                                            \
        asm volatile("cp.async.wait_group 1;");                                    \
        __syncthreads();                                                           \
        if (c + 2 < nchunks) {                                                     \
            load_stage((c + 2) % 3, c + 2);                                        \
            asm volatile("cp.async.commit_group;");                                \
        }                                                                          \
        const uint32_t stg = sbase + (c % 3) * FSTAGE;                             \
        _Pragma("unroll")                                                          \
        for (int ks = 0; ks < 4; ks++) {                                           \
            const uint32_t ko = (uint32_t)(ks * 32);                               \
            uint32_t Af[4][4];                                                     \
            _Pragma("unroll")                                                      \
            for (int mt = 0; mt < 4; mt++) {                                       \
                const uint32_t ra = stg + FOFF_A + aRow + ko                       \
                                    + (uint32_t)(mt * 16 * FPITCH);                \
                LDSM_X4(Af[mt][0], Af[mt][1], Af[mt][2], Af[mt][3], ra);           \
            }                                                                      \
            uint32_t Bf[4][2];                                                     \
            {                                                                      \
                const uint32_t rb0 = stg + FOFF_B + bRow + ko;                     \
                const uint32_t rb1 = rb0 + (uint32_t)(16 * FPITCH);                \
                LDSM_X4(Bf[0][0], Bf[0][1], Bf[1][0], Bf[1][1], rb0);              \
                LDSM_X4(Bf[2][0], Bf[2][1], Bf[3][0], Bf[3][1], rb1);              \
            }                                                                      \
            _Pragma("unroll")                                                      \
            for (int mt = 0; mt < 4; mt++)                                         \
                _Pragma("unroll")                                                  \
                for (int nt = 0; nt < 4; nt++)                                     \
                    mma_f16(acc[mt][nt], Af[mt][0], Af[mt][1], Af[mt][2],          \
                            Af[mt][3], Bf[nt][0], Bf[nt][1]);                      \
        }                                                                          \
    }

// ---- QKV projection: C -> fp16 head-major q/k/v with bias ----
__global__ __launch_bounds__(256, 2)
void k_gemm_qkv16(const __half* __restrict__ A, const __half* __restrict__ B,
                  const float* __restrict__ bias)
{
    extern __shared__ char smem[];
    const uint32_t sbase = smem_to_u32(smem);
    const int tid = threadIdx.x;
    const int wid = tid >> 5, lid = tid & 31;
    const int g = lid >> 2, tig = lid & 3;
    const int wm = (wid >> 2) * 64;
    const int wn = (wid & 3) * 32;
    const int bm = blockIdx.x * 128;
    const int bn = blockIdx.y * 128;

    GEMM_F16_MAINLOOP(A, B, DD)

    #pragma unroll
    for (int mt = 0; mt < 4; mt++) {
        const int row = bm + wm + mt * 16 + g;     // token
        const int b_ = row >> 10, t_ = row & 1023;
        #pragma unroll
        for (int nt = 0; nt < 4; nt++) {
            const int col = bn + wn + nt * 8 + tig * 2;
            const float b0 = bias[col], b1 = bias[col + 1];
            const int sel = col >> 10, hc = col & 1023;
            const int h = hc >> 6, dk = hc & 63;
            __half* dst = (sel == 0) ? g_q16 : (sel == 1) ? g_k16 : g_v16;
            const size_t o0 = ((size_t)(b_ * HH + h) * TT + t_) * DKK + dk;
            *(__half2*)(dst + o0) =
                __floats2half2_rn(acc[mt][nt][0] + b0, acc[mt][nt][1] + b1);
            *(__half2*)(dst + o0 + 8 * DKK) =
                __floats2half2_rn(acc[mt][nt][2] + b0, acc[mt][nt][3] + b1);
        }
    }
}

// ---- Logits GEMM: C fp32 + bias ----
__global__ __launch_bounds__(256, 2)
void k_gemm_f16(const __half* __restrict__ A, const __half* __restrict__ B,
                float* __restrict__ C, const float* __restrict__ bias)
{
    extern __shared__ char smem[];
    const uint32_t sbase = smem_to_u32(smem);
    const int tid = threadIdx.x;
    const int wid = tid >> 5, lid = tid & 31;
    const int g = lid >> 2, tig = lid & 3;
    const int wm = (wid >> 2) * 64;
    const int wn = (wid & 3) * 32;
    const int bm = blockIdx.x * 128;    // M fastest -> wave shares B tile
    const int bn = blockIdx.y * 128;

    GEMM_F16_MAINLOOP(A, B, DD)

    #pragma unroll
    for (int mt = 0; mt < 4; mt++) {
        const int row = bm + wm + mt * 16 + g;
        #pragma unroll
        for (int nt = 0; nt < 4; nt++) {
            const int col = bn + wn + nt * 8 + tig * 2;
            const float b0 = bias[col], b1 = bias[col + 1];
            float* p0 = C + (size_t)row * VV + col;
            float* p1 = C + (size_t)(row + 8) * VV + col;
            p0[0] = acc[mt][nt][0] + b0;
            p0[1] = acc[mt][nt][1] + b1;
            p1[0] = acc[mt][nt][2] + b0;
            p1[1] = acc[mt][nt][3] + b1;
        }
    }
}

// ---------------- embed -> fp16 ----------------
__global__ void k_embed16(const int* __restrict__ ids,
                          const float* __restrict__ tok_emb,
                          const float* __restrict__ pos_emb)
{
    int tok = blockIdx.x;
    int t = tok & (TT - 1);
    int v = ids[tok];
    const float* te = tok_emb + (size_t)v * DD;
    const float* pe = pos_emb + (size_t)t * DD;
    __half* xo = g_x16 + (size_t)tok * DD;
    for (int d = threadIdx.x; d < DD; d += blockDim.x)
        xo[d] = __float2half(te[d] * 32.0f + pe[d]);
}

// ---------------- repack Wq/Wk/Wv via smem transpose -> K-major fp16 ----------------
__global__ void k_repack_wqkvT(const float* __restrict__ Wq,
                               const float* __restrict__ Wk,
                               const float* __restrict__ Wv)
{
    __shared__ float s[32][33];
    const int sh = blockIdx.x;
    const int sel = sh >> 4, h = sh & 15;
    const int d0 = blockIdx.y * 32;
    const int k0 = blockIdx.z * 32;
    const float* src = (sel == 0) ? Wq : (sel == 1) ? Wk : Wv;
    const float* base = src + (size_t)h * (DD * DKK);
    const int tx = threadIdx.x, ty = threadIdx.y;
    #pragma unroll
    for (int i = 0; i < 4; i++)
        s[ty + i * 8][tx] = base[(size_t)(d0 + ty + i * 8) * DKK + k0 + tx];
    __syncthreads();
    #pragma unroll
    for (int i = 0; i < 4; i++) {
        const int k = k0 + ty + i * 8;
        const int n = sel * 1024 + h * 64 + k;
        const int d = d0 + tx;
        g_w16[(size_t)n * DD + d] = __float2half(s[tx][ty + i * 8]);
    }
}

__global__ void k_repack_b(const float* __restrict__ bq,
                           const float* __restrict__ bk,
                           const float* __restrict__ bv)
{
    int col = blockIdx.x * blockDim.x + threadIdx.x;
    if (col >= N3) return;
    int sel = col >> 10, c = col & 1023;
    const float* src = (sel == 0) ? bq : (sel == 1) ? bk : bv;
    g_b3[col] = src[c];
}

// ---------------- transpose Wo [1024, 32000] -> fp16 [32000, 1024] ----------------
__global__ void k_woT(const float* __restrict__ Wo)
{
    __shared__ float s[32][33];
    int v0 = blockIdx.x * 32, d0 = blockIdx.y * 32;
    int tx = threadIdx.x, ty = threadIdx.y;  // (32, 8)
    #pragma unroll
    for (int i = 0; i < 4; i++)
        s[ty + i * 8][tx] = Wo[(size_t)(d0 + ty + i * 8) * VV + v0 + tx];
    __syncthreads();
    #pragma unroll
    for (int i = 0; i < 4; i++) {
        int v = v0 + ty + i * 8;
        int d = d0 + tx;
        g_hb[(size_t)v * DD + d] = __float2half(s[tx][ty + i * 8]);
    }
}

// ---------------- tensor-core flash attention ----------------
// grid (8 tTiles reversed, 64 bh), 256 thr (8 warps x 16 t-rows = 128 rows/CTA).
#define PL 144
#define FLK_BYTES (64 * PL)                  // 9216
#define FLQ_BYTES (128 * PL)                 // 18432
#define FL2_STAGE (2 * FLK_BYTES)            // 18432
#define FL2_SMEM (FLQ_BYTES + 3 * FL2_STAGE) // 73728

__global__ __launch_bounds__(256, 1)
void k_flash_tc()
{
    extern __shared__ char smem[];
    const uint32_t sbase = smem_to_u32(smem);
    const int tid = threadIdx.x;
    const int w = tid >> 5, lid = tid & 31;
    const int g = lid >> 2, tig = lid & 3;
    const int tT = 7 - (int)blockIdx.x;      // heavy tiles first
    const int bh = blockIdx.y;
    const int t0 = tT * 128;
    const int wr = w * 16;
    const int nb = t0 / 64 + 2;

    const __half* gq = g_q16 + (size_t)bh * TT * DKK;
    const __half* gk = g_k16 + (size_t)bh * TT * DKK;
    const __half* gv = g_v16 + (size_t)bh * TT * DKK;

    auto load_kv = [&](int slot, int s0) {
        const uint32_t st = sbase + FLQ_BYTES + slot * FL2_STAGE;
        #pragma unroll
        for (int i = 0; i < 2; i++) {
            int u = i * 256 + tid;
            int r = u >> 3, cc = u & 7;
            uint32_t sa = st + r * PL + cc * 16;
            cp16(sa, gk + (size_t)(s0 + r) * DKK + cc * 8);
            cp16(sa + FLK_BYTES, gv + (size_t)(s0 + r) * DKK + cc * 8);
        }
    };

    #pragma unroll
    for (int i = 0; i < 4; i++) {
        int u = i * 256 + tid;
        int r = u >> 3, cc = u & 7;
        cp16(sbase + r * PL + cc * 16, gq + (size_t)(t0 + r) * DKK + cc * 8);
    }
    load_kv(0, 0);
    asm volatile("cp.async.commit_group;");
    load_kv(1, 64);
    asm volatile("cp.async.commit_group;");

    const uint32_t aoff = (uint32_t)((lid & 15) * PL + ((lid >> 4) << 4));
    const uint32_t boff = (uint32_t)(((lid & 7) + ((lid >> 4) << 3)) * PL
                                     + (((lid >> 3) & 1) << 4));
    const uint32_t voff = aoff;

    float O[8][4];
    #pragma unroll
    for (int j = 0; j < 8; j++)
        #pragma unroll
        for (int q = 0; q < 4; q++) O[j][q] = 0.0f;
    float m0 = -INFINITY, m1 = -INFINITY, l0 = 0.0f, l1 = 0.0f;

    const int trow0 = t0 + wr + g;
    const int trow1 = trow0 + 8;

    for (int c = 0; c < nb; c++) {
        const int s0 = c * 64;
        if (c + 2 <= nb) asm volatile("cp.async.wait_group 1;");
        else             asm volatile("cp.async.wait_group 0;");
        __syncthreads();
        if (c + 2 < nb) {
            load_kv((c + 2) % 3, (c + 2) * 64);
            asm volatile("cp.async.commit_group;");
        }

        if (s0 <= t0 + wr + 15) {
            const uint32_t stK = sbase + FLQ_BYTES + (c % 3) * FL2_STAGE;
            const uint32_t stV = stK + FLK_BYTES;

            uint32_t Af[4][4];
            #pragma unroll
            for (int ks = 0; ks < 4; ks++)
                LDSM_X4(Af[ks][0], Af[ks][1], Af[ks][2], Af[ks][3],
                        sbase + (uint32_t)(wr * PL) + aoff + ks * 32);
            float S[8][4];
            #pragma unroll
            for (int j = 0; j < 8; j++)
                #pragma unroll
                for (int q = 0; q < 4; q++) S[j][q] = 0.0f;
            #pragma unroll
            for (int ks = 0; ks < 4; ks++) {
                uint32_t Bf[8][2];
                #pragma unroll
                for (int jp = 0; jp < 4; jp++)
                    LDSM_X4(Bf[2 * jp][0], Bf[2 * jp][1], Bf[2 * jp + 1][0], Bf[2 * jp + 1][1],
                            stK + boff + (uint32_t)(jp * 16 * PL) + ks * 32);
                #pragma unroll
                for (int j = 0; j < 8; j++)
                    mma_f16(S[j], Af[ks][0], Af[ks][1], Af[ks][2], Af[ks][3],
                            Bf[j][0], Bf[j][1]);
            }

            const bool domask = (s0 + 63 > t0 + wr);
            #pragma unroll
            for (int j = 0; j < 8; j++) {
                #pragma unroll
                for (int q = 0; q < 4; q++) S[j][q] *= 0.125f;
                if (domask) {
                    const int sc = s0 + j * 8 + tig * 2;
                    if (sc     > trow0) S[j][0] = -INFINITY;
                    if (sc + 1 > trow0) S[j][1] = -INFINITY;
                    if (sc     > trow1) S[j][2] = -INFINITY;
                    if (sc + 1 > trow1) S[j][3] = -INFINITY;
                }
            }

            float rm0 = -INFINITY, rm1 = -INFINITY;
            #pragma unroll
            for (int j = 0; j < 8; j++) {
                rm0 = fmaxf(rm0, fmaxf(S[j][0], S[j][1]));
                rm1 = fmaxf(rm1, fmaxf(S[j][2], S[j][3]));
            }
            rm0 = fmaxf(rm0, __shfl_xor_sync(0xFFFFFFFF, rm0, 1));
            rm0 = fmaxf(rm0, __shfl_xor_sync(0xFFFFFFFF, rm0, 2));
            rm1 = fmaxf(rm1, __shfl_xor_sync(0xFFFFFFFF, rm1, 1));
            rm1 = fmaxf(rm1, __shfl_xor_sync(0xFFFFFFFF, rm1, 2));
            const float mn0 = fmaxf(m0, rm0), mn1 = fmaxf(m1, rm1);
            const float fac0 = __expf(m0 - mn0), fac1 = __expf(m1 - mn1);
            float rs0 = 0.0f, rs1 = 0.0f;
            #pragma unroll
            for (int j = 0; j < 8; j++) {
                S[j][0] = __expf(S[j][0] - mn0);
                S[j][1] = __expf(S[j][1] - mn0);
                S[j][2] = __expf(S[j][2] - mn1);
                S[j][3] = __expf(S[j][3] - mn1);
                rs0 += S[j][0] + S[j][1];
                rs1 += S[j][2] + S[j][3];
            }
            rs0 += __shfl_xor_sync(0xFFFFFFFF, rs0, 1);
            rs0 += __shfl_xor_sync(0xFFFFFFFF, rs0, 2);
            rs1 += __shfl_xor_sync(0xFFFFFFFF, rs1, 1);
            rs1 += __shfl_xor_sync(0xFFFFFFFF, rs1, 2);
            l0 = l0 * fac0 + rs0;  m0 = mn0;
            l1 = l1 * fac1 + rs1;  m1 = mn1;
            #pragma unroll
            for (int j = 0; j < 8; j++) {
                O[j][0] *= fac0; O[j][1] *= fac0;
                O[j][2] *= fac1; O[j][3] *= fac1;
            }

            uint32_t Pa[4][4];
            #pragma unroll
            for (int ks = 0; ks < 4; ks++) {
                const int j0 = 2 * ks, j1 = 2 * ks + 1;
                Pa[ks][0] = packh2(S[j0][0], S[j0][1]);
                Pa[ks][1] = packh2(S[j0][2], S[j0][3]);
                Pa[ks][2] = packh2(S[j1][0], S[j1][1]);
                Pa[ks][3] = packh2(S[j1][2], S[j1][3]);
            }
            #pragma unroll
            for (int ks = 0; ks < 4; ks++) {
                #pragma unroll
                for (int dp = 0; dp < 4; dp++) {
                    uint32_t Vb[4];
                    LDSM_X4_T(Vb[0], Vb[1], Vb[2], Vb[3],
                              stV + voff + (uint32_t)(ks * 16 * PL) + dp * 32);
                    mma_f16(O[2 * dp],     Pa[ks][0], Pa[ks][1], Pa[ks][2], Pa[ks][3],
                            Vb[0], Vb[1]);
                    mma_f16(O[2 * dp + 1], Pa[ks][0], Pa[ks][1], Pa[ks][2], Pa[ks][3],
                            Vb[2], Vb[3]);
                }
            }
        }
    }

    const float inv0 = 1.0f / l0, inv1 = 1.0f / l1;
    const int b_ = bh >> 4, h_ = bh & 15;
    __half* o0 = g_ha + (size_t)(b_ * TT + trow0) * DD + h_ * 64;
    __half* o1 = g_ha + (size_t)(b_ * TT + trow1) * DD + h_ * 64;
    #pragma unroll
    for (int j = 0; j < 8; j++) {
        const int col = j * 8 + tig * 2;
        *(__half2*)(o0 + col) = __floats2half2_rn(O[j][0] * inv0, O[j][1] * inv0);
        *(__half2*)(o1 + col) = __floats2half2_rn(O[j][2] * inv1, O[j][3] * inv1);
    }
}

// ---------------- loss: float4 online logsumexp per row ----------------
__global__ __launch_bounds__(256)
void k_loss_rows(const float* __restrict__ logits, const int* __restrict__ targets)
{
    const int r = blockIdx.x;
    const float* row = logits + (size_t)r * VV;
    const float4* vrow = (const float4*)row;       // 128000B stride: 16B aligned
    const int tid = threadIdx.x;
    __shared__ float sm[256], ss[256];

    float m = -INFINITY, s = 0.0f;
    for (int i = tid; i < VV / 4; i += 256) {
        const float4 x = vrow[i];
        const float mx = fmaxf(fmaxf(x.x, x.y), fmaxf(x.z, x.w));
        if (mx > m) { s *= __expf(m - mx); m = mx; }
        s += __expf(x.x - m) + __expf(x.y - m) + __expf(x.z - m) + __expf(x.w - m);
    }
    sm[tid] = m; ss[tid] = s;
    __syncthreads();
    for (int k = 128; k > 0; k >>= 1) {
        if (tid < k) {
            float m1 = sm[tid], s1 = ss[tid];
            float m2 = sm[tid + k], s2 = ss[tid + k];
            float M = fmaxf(m1, m2);
            sm[tid] = M;
            ss[tid] = s1 * __expf(m1 - M) + s2 * __expf(m2 - M);
        }
        __syncthreads();
    }
    if (tid == 0) {
        int tgt = targets[r];
        float logp = row[tgt] - sm[0] - __logf(ss[0]);
        g_rowloss[r] = -logp;
    }
}

__global__ void k_loss_final(float* out)
{
    const int tid = threadIdx.x;
    __shared__ float red[256];
    float s = 0.0f;
    for (int i = tid; i < BT; i += 256) s += g_rowloss[i];
    red[tid] = s; __syncthreads();
    for (int k = 128; k > 0; k >>= 1) {
        if (tid < k) red[tid] += red[tid + k];
        __syncthreads();
    }
    if (tid == 0) out[0] = red[0] * (1.0f / BT);
}

// ---------------- launch ----------------
extern "C" void kernel_launch(void* const* d_in, const int* in_sizes, int n_in,
                              void* d_out, int out_size)
{
    const int*   ids     = (const int*)  d_in[0];
    const int*   targets = (const int*)  d_in[1];
    const float* tok_emb = (const float*)d_in[2];
    const float* pos_emb = (const float*)d_in[3];
    const float* Wq      = (const float*)d_in[4];
    const float* bq      = (const float*)d_in[5];
    const float* Wk      = (const float*)d_in[6];
    const float* bk      = (const float*)d_in[7];
    const float* Wv      = (const float*)d_in[8];
    const float* bv      = (const float*)d_in[9];
    const float* Wo      = (const float*)d_in[10];
    const float* bo      = (const float*)d_in[11];
    float* out = (float*)d_out;

    float* pb3;
    __half *px16, *pw16, *pha, *phb;
    cudaGetSymbolAddress((void**)&pb3,  g_b3);
    cudaGetSymbolAddress((void**)&px16, g_x16);
    cudaGetSymbolAddress((void**)&pw16, g_w16);
    cudaGetSymbolAddress((void**)&pha,  g_ha);
    cudaGetSymbolAddress((void**)&phb,  g_hb);

    cudaFuncSetAttribute(k_gemm_qkv16, cudaFuncAttributeMaxDynamicSharedMemorySize, FSMEM);
    cudaFuncSetAttribute(k_gemm_f16,   cudaFuncAttributeMaxDynamicSharedMemorySize, FSMEM);
    cudaFuncSetAttribute(k_flash_tc,   cudaFuncAttributeMaxDynamicSharedMemorySize, FL2_SMEM);

    // 1. embed + weight repacks (all fp16)
    k_embed16<<<BT, 256>>>(ids, tok_emb, pos_emb);
    k_repack_wqkvT<<<dim3(48, 32, 2), dim3(32, 8)>>>(Wq, Wk, Wv);
    k_repack_b<<<(N3 + 255) / 256, 256>>>(bq, bk, bv);
    k_woT<<<dim3(VV / 32, DD / 32), dim3(32, 8)>>>(Wo);

    // 2. QKV projection (fp16) -> fp16 head-major q/k/v
    k_gemm_qkv16<<<dim3(BT / 128, N3 / 128), 256, FSMEM>>>(px16, pw16, pb3);

    // 3. tensor-core flash attention (emits fp16 A for the logits GEMM)
    k_flash_tc<<<dim3(8, BHN), 256, FL2_SMEM>>>();

    // 4. logits (fp16): [4096,1024] x [1024,32000] + bo
    k_gemm_f16<<<dim3(BT / 128, VV / 128), 256, FSMEM>>>(pha, phb, out, bo);

    // 5. loss
    if ((long long)out_size > BTV) {
        k_loss_rows<<<BT, 256>>>(out, targets);
        k_loss_final<<<1, 256>>>(out + BTV);
    }
}

// round 13
// speedup vs baseline: 8.6148x; 1.0440x over previous
#include <cuda_runtime.h>
#include <cuda_bf16.h>
#include <cuda_fp16.h>
#include <math.h>
#include <stdint.h>

// Problem constants
#define BB 4
#define TT 1024
#define VV 32000
#define DD 1024
#define HH 16
#define DKK 64
#define BT 4096            // B*T
#define N3 3072            // 3*D (q|k|v)
#define BHN 64             // B*H
#define BTV 131072000LL    // BT*VV
#define NBLK 250           // VV / 128

// ---------------- scratch (device globals; no allocation) ----------------
__device__ float g_b3[N3];                       // repacked qkv bias
__device__ float g_rowloss[BT];
__device__ float2 g_pml[(size_t)BT * NBLK];      // per (row, nblock) partial (max, sum)

__device__ __half g_x16[BT * DD];                // embedded input fp16 (QKV A)
__device__ __half g_w16[N3 * DD];                // Wqkv fp16 K-major [3072,1024]
__device__ __half g_q16[BHN * TT * DKK];         // q fp16 head-major [bh][t][dk]
__device__ __half g_k16[BHN * TT * DKK];         // k fp16
__device__ __half g_v16[BHN * TT * DKK];         // v fp16
__device__ __half g_ha[BT * DD];                 // attention-out fp16 (logits A)
__device__ __half g_hb[(size_t)VV * DD];         // Wo^T fp16 (K-major [32000,1024])

// ================= helpers =================
__device__ __forceinline__ uint32_t smem_to_u32(const void* p) {
    uint32_t a;
    asm("{ .reg .u64 t; cvta.to.shared.u64 t, %1; cvt.u32.u64 %0, t; }" : "=r"(a) : "l"(p));
    return a;
}
__device__ __forceinline__ void cp16(uint32_t saddr, const void* gptr) {
    asm volatile("cp.async.cg.shared.global [%0], [%1], 16;" :: "r"(saddr), "l"(gptr));
}
#define LDSM_X4(R0, R1, R2, R3, addr) \
    asm volatile("ldmatrix.sync.aligned.m8n8.x4.shared.b16 {%0,%1,%2,%3}, [%4];" \
                 : "=r"(R0), "=r"(R1), "=r"(R2), "=r"(R3) : "r"(addr))
#define LDSM_X4_T(R0, R1, R2, R3, addr) \
    asm volatile("ldmatrix.sync.aligned.m8n8.x4.trans.shared.b16 {%0,%1,%2,%3}, [%4];" \
                 : "=r"(R0), "=r"(R1), "=r"(R2), "=r"(R3) : "r"(addr))

__device__ __forceinline__ void mma_f16(float* c,
                                        uint32_t a0, uint32_t a1, uint32_t a2, uint32_t a3,
                                        uint32_t b0, uint32_t b1)
{
    asm volatile(
        "mma.sync.aligned.m16n8k16.row.col.f32.f16.f16.f32 "
        "{%0,%1,%2,%3}, {%4,%5,%6,%7}, {%8,%9}, {%0,%1,%2,%3};"
        : "+f"(c[0]), "+f"(c[1]), "+f"(c[2]), "+f"(c[3])
        : "r"(a0), "r"(a1), "r"(a2), "r"(a3), "r"(b0), "r"(b1));
}
__device__ __forceinline__ uint32_t packh2(float a, float b) {
    __half2 h = __floats2half2_rn(a, b);
    return *(uint32_t*)&h;
}
// merge partial logsumexp (m2,s2) into (m,s)
__device__ __forceinline__ void lse_merge(float& m, float& s, float m2, float s2) {
    const float M = fmaxf(m, m2);
    s = s * __expf(m - M) + s2 * __expf(m2 - M);
    m = M;
}

// ============ fp16 GEMM core: 128x128 tile, BK=64, 3-stage, occupancy 2 ============
#define FPITCH 144
#define FARR (128 * FPITCH)          // 18432
#define FSTAGE (2 * FARR)            // 36864
#define FSMEM (3 * FSTAGE)           // 110592
#define FOFF_A 0
#define FOFF_B FARR

#define GEMM_F16_MAINLOOP(Aptr, Bptr, Kdim)                                        \
    const uint32_t aRow = (uint32_t)((wm + (lid & 15)) * FPITCH + ((lid >> 4) << 4)); \
    const uint32_t bRow = (uint32_t)((wn + (lid & 7) + ((lid >> 4) << 3)) * FPITCH    \
                                     + (((lid >> 3) & 1) << 4));                      \
    float acc[4][4][4];                                                            \
    _Pragma("unroll")                                                              \
    for (int i = 0; i < 4; i++)                                                    \
        _Pragma("unroll")                                                          \
        for (int j = 0; j < 4; j++)                                                \
            _Pragma("unroll")                                                      \
            for (int q = 0; q < 4; q++) acc[i][j][q] = 0.0f;                       \
    auto load_stage = [&](int slot, int chunk) {                                   \
        const int k0 = chunk << 6;                                                 \
        const uint32_t st = sbase + slot * FSTAGE;                                 \
        _Pragma("unroll")                                                          \
        for (int i = 0; i < 4; i++) {                                              \
            const int u = i * 256 + tid;                                           \
            const int r = u >> 3, cc = u & 7;                                      \
            const uint32_t sa = st + r * FPITCH + cc * 16;                         \
            cp16(sa + FOFF_A, (Aptr) + (size_t)(bm + r) * (Kdim) + k0 + cc * 8);   \
            cp16(sa + FOFF_B, (Bptr) + (size_t)(bn + r) * (Kdim) + k0 + cc * 8);   \
        }                                                                          \
    };                                                                             \
    load_stage(0, 0);                                                              \
    asm volatile("cp.async.commit_group;");                                        \
    load_stage(1, 1);                                                              \
    asm volatile("cp.async.commit_group;");                                        \
    const int nchunks = (Kdim) >> 6;                                               \
    for (int c = 0; c < nchunks; c++) {                                            \
        if (c < nchunks - 1) asm volatile("cp.async.wait_group 1;");               \
        else                 asm volatile("cp.async.wait_group 0;");               \
        __syncthreads();                                                           \
        if (c + 2 < nchunks) {                                                     \
            load_stage((c + 2) % 3, c + 2);                                        \
            asm volatile("cp.async.commit_group;");                                \
        }                                                                          \
        const uint32_t stg = sbase + (c % 3) * FSTAGE;                             \
        _Pragma("unroll")                                                          \
        for (int ks = 0; ks < 4; ks++) {                                           \
            const uint32_t ko = (uint32_t)(ks * 32);                               \
            uint32_t Af[4][4];                                                     \
            _Pragma("unroll")                                                      \
            for (int mt = 0; mt < 4; mt++) {                                       \
                const uint32_t ra = stg + FOFF_A + aRow + ko                       \
                                    + (uint32_t)(mt * 16 * FPITCH);                \
                LDSM_X4(Af[mt][0], Af[mt][1], Af[mt][2], Af[mt][3], ra);           \
            }                                                                      \
            uint32_t Bf[4][2];                                                     \
            {                                                                      \
                const uint32_t rb0 = stg + FOFF_B + bRow + ko;                     \
                const uint32_t rb1 = rb0 + (uint32_t)(16 * FPITCH);                \
                LDSM_X4(Bf[0][0], Bf[0][1], Bf[1][0], Bf[1][1], rb0);              \
                LDSM_X4(Bf[2][0], Bf[2][1], Bf[3][0], Bf[3][1], rb1);              \
            }                                                                      \
            _Pragma("unroll")                                                      \
            for (int mt = 0; mt < 4; mt++)                                         \
                _Pragma("unroll")                                                  \
                for (int nt = 0; nt < 4; nt++)                                     \
                    mma_f16(acc[mt][nt], Af[mt][0], Af[mt][1], Af[mt][2],          \
                            Af[mt][3], Bf[nt][0], Bf[nt][1]);                      \
        }                                                                          \
    }

// ---- QKV projection: C -> fp16 head-major q/k/v with bias ----
__global__ __launch_bounds__(256, 2)
void k_gemm_qkv16(const __half* __restrict__ A, const __half* __restrict__ B,
                  const float* __restrict__ bias)
{
    extern __shared__ char smem[];
    const uint32_t sbase = smem_to_u32(smem);
    const int tid = threadIdx.x;
    const int wid = tid >> 5, lid = tid & 31;
    const int g = lid >> 2, tig = lid & 3;
    const int wm = (wid >> 2) * 64;
    const int wn = (wid & 3) * 32;
    const int bm = blockIdx.x * 128;
    const int bn = blockIdx.y * 128;

    GEMM_F16_MAINLOOP(A, B, DD)

    #pragma unroll
    for (int mt = 0; mt < 4; mt++) {
        const int row = bm + wm + mt * 16 + g;     // token
        const int b_ = row >> 10, t_ = row & 1023;
        #pragma unroll
        for (int nt = 0; nt < 4; nt++) {
            const int col = bn + wn + nt * 8 + tig * 2;
            const float b0 = bias[col], b1 = bias[col + 1];
            const int sel = col >> 10, hc = col & 1023;
            const int h = hc >> 6, dk = hc & 63;
            __half* dst = (sel == 0) ? g_q16 : (sel == 1) ? g_k16 : g_v16;
            const size_t o0 = ((size_t)(b_ * HH + h) * TT + t_) * DKK + dk;
            *(__half2*)(dst + o0) =
                __floats2half2_rn(acc[mt][nt][0] + b0, acc[mt][nt][1] + b1);
            *(__half2*)(dst + o0 + 8 * DKK) =
                __floats2half2_rn(acc[mt][nt][2] + b0, acc[mt][nt][3] + b1);
        }
    }
}

// ---- Logits GEMM: C fp32 + bias, plus fused per-block loss partials ----
__global__ __launch_bounds__(256, 2)
void k_gemm_f16(const __half* __restrict__ A, const __half* __restrict__ B,
                float* __restrict__ C, const float* __restrict__ bias)
{
    extern __shared__ char smem[];
    const uint32_t sbase = smem_to_u32(smem);
    const int tid = threadIdx.x;
    const int wid = tid >> 5, lid = tid & 31;
    const int g = lid >> 2, tig = lid & 3;
    const int wm = (wid >> 2) * 64;
    const int wn = (wid & 3) * 32;
    const int bm = blockIdx.x * 128;    // M fastest -> wave shares B tile
    const int bn = blockIdx.y * 128;

    GEMM_F16_MAINLOOP(A, B, DD)

    // epilogue: store logits and accumulate per-row online logsumexp partials
    __syncthreads();                    // smem stages are dead; reuse for partials
    float2* part = (float2*)smem;       // [4 col-parts][128 rows]
    const int cpart = wid & 3;

    #pragma unroll
    for (int mt = 0; mt < 4; mt++) {
        const int lr = wm + mt * 16 + g;         // CTA-local row
        const int row = bm + lr;
        float m0 = -INFINITY, s0 = 0.0f, m1 = -INFINITY, s1 = 0.0f;
        #pragma unroll
        for (int nt = 0; nt < 4; nt++) {
            const int col = bn + wn + nt * 8 + tig * 2;
            const float b0 = bias[col], b1 = bias[col + 1];
            const float v00 = acc[mt][nt][0] + b0, v01 = acc[mt][nt][1] + b1;
            const float v10 = acc[mt][nt][2] + b0, v11 = acc[mt][nt][3] + b1;
            float* p0 = C + (size_t)row * VV + col;
            float* p1 = C + (size_t)(row + 8) * VV + col;
            p0[0] = v00; p0[1] = v01;
            p1[0] = v10; p1[1] = v11;
            // online partials
            const float mx0 = fmaxf(v00, v01);
            if (mx0 > m0) { s0 *= __expf(m0 - mx0); m0 = mx0; }
            s0 += __expf(v00 - m0) + __expf(v01 - m0);
            const float mx1 = fmaxf(v10, v11);
            if (mx1 > m1) { s1 *= __expf(m1 - mx1); m1 = mx1; }
            s1 += __expf(v10 - m1) + __expf(v11 - m1);
        }
        // reduce over the 4 quad lanes (tig)
        #pragma unroll
        for (int w = 1; w < 4; w <<= 1) {
            lse_merge(m0, s0, __shfl_xor_sync(0xFFFFFFFF, m0, w),
                              __shfl_xor_sync(0xFFFFFFFF, s0, w));
            lse_merge(m1, s1, __shfl_xor_sync(0xFFFFFFFF, m1, w),
                              __shfl_xor_sync(0xFFFFFFFF, s1, w));
        }
        if (tig == 0) {
            part[cpart * 128 + lr]     = make_float2(m0, s0);
            part[cpart * 128 + lr + 8] = make_float2(m1, s1);
        }
    }
    __syncthreads();

    if (tid < 128) {                    // one thread per CTA row
        float2 p = part[tid];
        float m = p.x, s = p.y;
        #pragma unroll
        for (int cp = 1; cp < 4; cp++) {
            const float2 q = part[cp * 128 + tid];
            lse_merge(m, s, q.x, q.y);
        }
        g_pml[(size_t)(bm + tid) * NBLK + blockIdx.y] = make_float2(m, s);
    }
}

// ---------------- embed -> fp16 ----------------
__global__ void k_embed16(const int* __restrict__ ids,
                          const float* __restrict__ tok_emb,
                          const float* __restrict__ pos_emb)
{
    int tok = blockIdx.x;
    int t = tok & (TT - 1);
    int v = ids[tok];
    const float* te = tok_emb + (size_t)v * DD;
    const float* pe = pos_emb + (size_t)t * DD;
    __half* xo = g_x16 + (size_t)tok * DD;
    for (int d = threadIdx.x; d < DD; d += blockDim.x)
        xo[d] = __float2half(te[d] * 32.0f + pe[d]);
}

// ---------------- repack Wq/Wk/Wv via smem transpose -> K-major fp16 ----------------
__global__ void k_repack_wqkvT(const float* __restrict__ Wq,
                               const float* __restrict__ Wk,
                               const float* __restrict__ Wv)
{
    __shared__ float s[32][33];
    const int sh = blockIdx.x;
    const int sel = sh >> 4, h = sh & 15;
    const int d0 = blockIdx.y * 32;
    const int k0 = blockIdx.z * 32;
    const float* src = (sel == 0) ? Wq : (sel == 1) ? Wk : Wv;
    const float* base = src + (size_t)h * (DD * DKK);
    const int tx = threadIdx.x, ty = threadIdx.y;
    #pragma unroll
    for (int i = 0; i < 4; i++)
        s[ty + i * 8][tx] = base[(size_t)(d0 + ty + i * 8) * DKK + k0 + tx];
    __syncthreads();
    #pragma unroll
    for (int i = 0; i < 4; i++) {
        const int k = k0 + ty + i * 8;
        const int n = sel * 1024 + h * 64 + k;
        const int d = d0 + tx;
        g_w16[(size_t)n * DD + d] = __float2half(s[tx][ty + i * 8]);
    }
}

__global__ void k_repack_b(const float* __restrict__ bq,
                           const float* __restrict__ bk,
                           const float* __restrict__ bv)
{
    int col = blockIdx.x * blockDim.x + threadIdx.x;
    if (col >= N3) return;
    int sel = col >> 10, c = col & 1023;
    const float* src = (sel == 0) ? bq : (sel == 1) ? bk : bv;
    g_b3[col] = src[c];
}

// ---------------- transpose Wo [1024, 32000] -> fp16 [32000, 1024] ----------------
__global__ void k_woT(const float* __restrict__ Wo)
{
    __shared__ float s[32][33];
    int v0 = blockIdx.x * 32, d0 = blockIdx.y * 32;
    int tx = threadIdx.x, ty = threadIdx.y;  // (32, 8)
    #pragma unroll
    for (int i = 0; i < 4; i++)
        s[ty + i * 8][tx] = Wo[(size_t)(d0 + ty + i * 8) * VV + v0 + tx];
    __syncthreads();
    #pragma unroll
    for (int i = 0; i < 4; i++) {
        int v = v0 + ty + i * 8;
        int d = d0 + tx;
        g_hb[(size_t)v * DD + d] = __float2half(s[tx][ty + i * 8]);
    }
}

// ---------------- tensor-core flash attention ----------------
#define PL 144
#define FLK_BYTES (64 * PL)                  // 9216
#define FLQ_BYTES (128 * PL)                 // 18432
#define FL2_STAGE (2 * FLK_BYTES)            // 18432
#define FL2_SMEM (FLQ_BYTES + 3 * FL2_STAGE) // 73728

__global__ __launch_bounds__(256, 2)
void k_flash_tc()
{
    extern __shared__ char smem[];
    const uint32_t sbase = smem_to_u32(smem);
    const int tid = threadIdx.x;
    const int w = tid >> 5, lid = tid & 31;
    const int g = lid >> 2, tig = lid & 3;
    const int tT = 7 - (int)blockIdx.x;      // heavy tiles first
    const int bh = blockIdx.y;
    const int t0 = tT * 128;
    const int wr = w * 16;
    const int nb = t0 / 64 + 2;

    const __half* gq = g_q16 + (size_t)bh * TT * DKK;
    const __half* gk = g_k16 + (size_t)bh * TT * DKK;
    const __half* gv = g_v16 + (size_t)bh * TT * DKK;

    auto load_kv = [&](int slot, int s0) {
        const uint32_t st = sbase + FLQ_BYTES + slot * FL2_STAGE;
        #pragma unroll
        for (int i = 0; i < 2; i++) {
            int u = i * 256 + tid;
            int r = u >> 3, cc = u & 7;
            uint32_t sa = st + r * PL + cc * 16;
            cp16(sa, gk + (size_t)(s0 + r) * DKK + cc * 8);
            cp16(sa + FLK_BYTES, gv + (size_t)(s0 + r) * DKK + cc * 8);
        }
    };

    #pragma unroll
    for (int i = 0; i < 4; i++) {
        int u = i * 256 + tid;
        int r = u >> 3, cc = u & 7;
        cp16(sbase + r * PL + cc * 16, gq + (size_t)(t0 + r) * DKK + cc * 8);
    }
    load_kv(0, 0);
    asm volatile("cp.async.commit_group;");
    load_kv(1, 64);
    asm volatile("cp.async.commit_group;");

    const uint32_t aoff = (uint32_t)((lid & 15) * PL + ((lid >> 4) << 4));
    const uint32_t boff = (uint32_t)(((lid & 7) + ((lid >> 4) << 3)) * PL
                                     + (((lid >> 3) & 1) << 4));
    const uint32_t voff = aoff;

    float O[8][4];
    #pragma unroll
    for (int j = 0; j < 8; j++)
        #pragma unroll
        for (int q = 0; q < 4; q++) O[j][q] = 0.0f;
    float m0 = -INFINITY, m1 = -INFINITY, l0 = 0.0f, l1 = 0.0f;

    const int trow0 = t0 + wr + g;
    const int trow1 = trow0 + 8;

    for (int c = 0; c < nb; c++) {
        const int s0 = c * 64;
        if (c < nb - 1) asm volatile("cp.async.wait_group 1;");
        else            asm volatile("cp.async.wait_group 0;");
        __syncthreads();
        if (c + 2 < nb) {
            load_kv((c + 2) % 3, (c + 2) * 64);
            asm volatile("cp.async.commit_group;");
        }

        if (s0 <= t0 + wr + 15) {
            const uint32_t stK = sbase + FLQ_BYTES + (c % 3) * FL2_STAGE;
            const uint32_t stV = stK + FLK_BYTES;

            uint32_t Af[4][4];
            #pragma unroll
            for (int ks = 0; ks < 4; ks++)
                LDSM_X4(Af[ks][0], Af[ks][1], Af[ks][2], Af[ks][3],
                        sbase + (uint32_t)(wr * PL) + aoff + ks * 32);
            float S[8][4];
            #pragma unroll
            for (int j = 0; j < 8; j++)
                #pragma unroll
                for (int q = 0; q < 4; q++) S[j][q] = 0.0f;
            #pragma unroll
            for (int ks = 0; ks < 4; ks++) {
                uint32_t Bf[8][2];
                #pragma unroll
                for (int jp = 0; jp < 4; jp++)
                    LDSM_X4(Bf[2 * jp][0], Bf[2 * jp][1], Bf[2 * jp + 1][0], Bf[2 * jp + 1][1],
                            stK + boff + (uint32_t)(jp * 16 * PL) + ks * 32);
                #pragma unroll
                for (int j = 0; j < 8; j++)
                    mma_f16(S[j], Af[ks][0], Af[ks][1], Af[ks][2], Af[ks][3],
                            Bf[j][0], Bf[j][1]);
            }

            const bool domask = (s0 + 63 > t0 + wr);
            #pragma unroll
            for (int j = 0; j < 8; j++) {
                #pragma unroll
                for (int q = 0; q < 4; q++) S[j][q] *= 0.125f;
                if (domask) {
                    const int sc = s0 + j * 8 + tig * 2;
                    if (sc     > trow0) S[j][0] = -INFINITY;
                    if (sc + 1 > trow0) S[j][1] = -INFINITY;
                    if (sc     > trow1) S[j][2] = -INFINITY;
                    if (sc + 1 > trow1) S[j][3] = -INFINITY;
                }
            }

            float rm0 = -INFINITY, rm1 = -INFINITY;
            #pragma unroll
            for (int j = 0; j < 8; j++) {
                rm0 = fmaxf(rm0, fmaxf(S[j][0], S[j][1]));
                rm1 = fmaxf(rm1, fmaxf(S[j][2], S[j][3]));
            }
            rm0 = fmaxf(rm0, __shfl_xor_sync(0xFFFFFFFF, rm0, 1));
            rm0 = fmaxf(rm0, __shfl_xor_sync(0xFFFFFFFF, rm0, 2));
            rm1 = fmaxf(rm1, __shfl_xor_sync(0xFFFFFFFF, rm1, 1));
            rm1 = fmaxf(rm1, __shfl_xor_sync(0xFFFFFFFF, rm1, 2));
            const float mn0 = fmaxf(m0, rm0), mn1 = fmaxf(m1, rm1);
            const float fac0 = __expf(m0 - mn0), fac1 = __expf(m1 - mn1);
            float rs0 = 0.0f, rs1 = 0.0f;
            #pragma unroll
            for (int j = 0; j < 8; j++) {
                S[j][0] = __expf(S[j][0] - mn0);
                S[j][1] = __expf(S[j][1] - mn0);
                S[j][2] = __expf(S[j][2] - mn1);
                S[j][3] = __expf(S[j][3] - mn1);
                rs0 += S[j][0] + S[j][1];
                rs1 += S[j][2] + S[j][3];
            }
            rs0 += __shfl_xor_sync(0xFFFFFFFF, rs0, 1);
            rs0 += __shfl_xor_sync(0xFFFFFFFF, rs0, 2);
            rs1 += __shfl_xor_sync(0xFFFFFFFF, rs1, 1);
            rs1 += __shfl_xor_sync(0xFFFFFFFF, rs1, 2);
            l0 = l0 * fac0 + rs0;  m0 = mn0;
            l1 = l1 * fac1 + rs1;  m1 = mn1;
            #pragma unroll
            for (int j = 0; j < 8; j++) {
                O[j][0] *= fac0; O[j][1] *= fac0;
                O[j][2] *= fac1; O[j][3] *= fac1;
            }

            uint32_t Pa[4][4];
            #pragma unroll
            for (int ks = 0; ks < 4; ks++) {
                const int j0 = 2 * ks, j1 = 2 * ks + 1;
                Pa[ks][0] = packh2(S[j0][0], S[j0][1]);
                Pa[ks][1] = packh2(S[j0][2], S[j0][3]);
                Pa[ks][2] = packh2(S[j1][0], S[j1][1]);
                Pa[ks][3] = packh2(S[j1][2], S[j1][3]);
            }
            #pragma unroll
            for (int ks = 0; ks < 4; ks++) {
                #pragma unroll
                for (int dp = 0; dp < 4; dp++) {
                    uint32_t Vb[4];
                    LDSM_X4_T(Vb[0], Vb[1], Vb[2], Vb[3],
                              stV + voff + (uint32_t)(ks * 16 * PL) + dp * 32);
                    mma_f16(O[2 * dp],     Pa[ks][0], Pa[ks][1], Pa[ks][2], Pa[ks][3],
                            Vb[0], Vb[1]);
                    mma_f16(O[2 * dp + 1], Pa[ks][0], Pa[ks][1], Pa[ks][2], Pa[ks][3],
                            Vb[2], Vb[3]);
                }
            }
        }
    }

    const float inv0 = 1.0f / l0, inv1 = 1.0f / l1;
    const int b_ = bh >> 4, h_ = bh & 15;
    __half* o0 = g_ha + (size_t)(b_ * TT + trow0) * DD + h_ * 64;
    __half* o1 = g_ha + (size_t)(b_ * TT + trow1) * DD + h_ * 64;
    #pragma unroll
    for (int j = 0; j < 8; j++) {
        const int col = j * 8 + tig * 2;
        *(__half2*)(o0 + col) = __floats2half2_rn(O[j][0] * inv0, O[j][1] * inv0);
        *(__half2*)(o1 + col) = __floats2half2_rn(O[j][2] * inv1, O[j][3] * inv1);
    }
}

// ---------------- loss: reduce per-block partials (8 MB instead of 524 MB) ----------------
__global__ __launch_bounds__(256)
void k_loss_rows(const float* __restrict__ logits, const int* __restrict__ targets)
{
    const int r = blockIdx.x;
    const int tid = threadIdx.x;
    __shared__ float sm[256], ss[256];

    float m = -INFINITY, s = 0.0f;
    if (tid < NBLK) {
        const float2 p = g_pml[(size_t)r * NBLK + tid];
        m = p.x; s = p.y;
    }
    sm[tid] = m; ss[tid] = s;
    __syncthreads();
    for (int k = 128; k > 0; k >>= 1) {
        if (tid < k) {
            float m1 = sm[tid], s1 = ss[tid];
            float m2 = sm[tid + k], s2 = ss[tid + k];
            float M = fmaxf(m1, m2);
            sm[tid] = M;
            ss[tid] = s1 * __expf(m1 - M) + s2 * __expf(m2 - M);
        }
        __syncthreads();
    }
    if (tid == 0) {
        int tgt = targets[r];
        float logp = logits[(size_t)r * VV + tgt] - sm[0] - __logf(ss[0]);
        g_rowloss[r] = -logp;
    }
}

__global__ void k_loss_final(float* out)
{
    const int tid = threadIdx.x;
    __shared__ float red[256];
    float s = 0.0f;
    for (int i = tid; i < BT; i += 256) s += g_rowloss[i];
    red[tid] = s; __syncthreads();
    for (int k = 128; k > 0; k >>= 1) {
        if (tid < k) red[tid] += red[tid + k];
        __syncthreads();
    }
    if (tid == 0) out[0] = red[0] * (1.0f / BT);
}

// ---------------- launch ----------------
extern "C" void kernel_launch(void* const* d_in, const int* in_sizes, int n_in,
                              void* d_out, int out_size)
{
    const int*   ids     = (const int*)  d_in[0];
    const int*   targets = (const int*)  d_in[1];
    const float* tok_emb = (const float*)d_in[2];
    const float* pos_emb = (const float*)d_in[3];
    const float* Wq      = (const float*)d_in[4];
    const float* bq      = (const float*)d_in[5];
    const float* Wk      = (const float*)d_in[6];
    const float* bk      = (const float*)d_in[7];
    const float* Wv      = (const float*)d_in[8];
    const float* bv      = (const float*)d_in[9];
    const float* Wo      = (const float*)d_in[10];
    const float* bo      = (const float*)d_in[11];
    float* out = (float*)d_out;

    float* pb3;
    __half *px16, *pw16, *pha, *phb;
    cudaGetSymbolAddress((void**)&pb3,  g_b3);
    cudaGetSymbolAddress((void**)&px16, g_x16);
    cudaGetSymbolAddress((void**)&pw16, g_w16);
    cudaGetSymbolAddress((void**)&pha,  g_ha);
    cudaGetSymbolAddress((void**)&phb,  g_hb);

    cudaFuncSetAttribute(k_gemm_qkv16, cudaFuncAttributeMaxDynamicSharedMemorySize, FSMEM);
    cudaFuncSetAttribute(k_gemm_f16,   cudaFuncAttributeMaxDynamicSharedMemorySize, FSMEM);
    cudaFuncSetAttribute(k_flash_tc,   cudaFuncAttributeMaxDynamicSharedMemorySize, FL2_SMEM);

    // 1. embed + weight repacks (all fp16)
    k_embed16<<<BT, 256>>>(ids, tok_emb, pos_emb);
    k_repack_wqkvT<<<dim3(48, 32, 2), dim3(32, 8)>>>(Wq, Wk, Wv);
    k_repack_b<<<(N3 + 255) / 256, 256>>>(bq, bk, bv);
    k_woT<<<dim3(VV / 32, DD / 32), dim3(32, 8)>>>(Wo);

    // 2. QKV projection (fp16) -> fp16 head-major q/k/v
    k_gemm_qkv16<<<dim3(BT / 128, N3 / 128), 256, FSMEM>>>(px16, pw16, pb3);

    // 3. tensor-core flash attention (emits fp16 A for the logits GEMM)
    k_flash_tc<<<dim3(8, BHN), 256, FL2_SMEM>>>();

    // 4. logits (fp16) + fused loss partials
    k_gemm_f16<<<dim3(BT / 128, VV / 128), 256, FSMEM>>>(pha, phb, out, bo);

    // 5. loss (partials reduce + mean)
    if ((long long)out_size > BTV) {
        k_loss_rows<<<BT, 256>>>(out, targets);
        k_loss_final<<<1, 256>>>(out + BTV);
    }
}

// round 14
// speedup vs baseline: 9.1471x; 1.0618x over previous
#include <cuda_runtime.h>
#include <cuda_bf16.h>
#include <cuda_fp16.h>
#include <math.h>
#include <stdint.h>

// Problem constants
#define BB 4
#define TT 1024
#define VV 32000
#define DD 1024
#define HH 16
#define DKK 64
#define BT 4096            // B*T
#define N3 3072            // 3*D (q|k|v)
#define BHN 64             // B*H
#define BTV 131072000LL    // BT*VV
#define NBLK 250           // VV / 128

// ---------------- scratch (device globals; no allocation) ----------------
__device__ float g_rowloss[BT];
__device__ float2 g_pml[(size_t)BT * NBLK];      // per (row, nblock) partial (max, sum)

__device__ __half g_x16[BT * DD];                // embedded input fp16 (QKV A)
__device__ __half g_w16[N3 * DD];                // Wqkv fp16 K-major [3072,1024]
__device__ __half g_q16[BHN * TT * DKK];         // q fp16 head-major [bh][t][dk]
__device__ __half g_k16[BHN * TT * DKK];         // k fp16
__device__ __half g_v16[BHN * TT * DKK];         // v fp16
__device__ __half g_ha[BT * DD];                 // attention-out fp16 (logits A)
__device__ __half g_hb[(size_t)VV * DD];         // Wo^T fp16 (K-major [32000,1024])

// ================= helpers =================
__device__ __forceinline__ uint32_t smem_to_u32(const void* p) {
    uint32_t a;
    asm("{ .reg .u64 t; cvta.to.shared.u64 t, %1; cvt.u32.u64 %0, t; }" : "=r"(a) : "l"(p));
    return a;
}
__device__ __forceinline__ void cp16(uint32_t saddr, const void* gptr) {
    asm volatile("cp.async.cg.shared.global [%0], [%1], 16;" :: "r"(saddr), "l"(gptr));
}
__device__ __forceinline__ void stg_cs_v2(float* p, float a, float b) {
    asm volatile("st.global.cs.v2.f32 [%0], {%1, %2};" :: "l"(p), "f"(a), "f"(b) : "memory");
}
#define LDSM_X4(R0, R1, R2, R3, addr) \
    asm volatile("ldmatrix.sync.aligned.m8n8.x4.shared.b16 {%0,%1,%2,%3}, [%4];" \
                 : "=r"(R0), "=r"(R1), "=r"(R2), "=r"(R3) : "r"(addr))
#define LDSM_X4_T(R0, R1, R2, R3, addr) \
    asm volatile("ldmatrix.sync.aligned.m8n8.x4.trans.shared.b16 {%0,%1,%2,%3}, [%4];" \
                 : "=r"(R0), "=r"(R1), "=r"(R2), "=r"(R3) : "r"(addr))

__device__ __forceinline__ void mma_f16(float* c,
                                        uint32_t a0, uint32_t a1, uint32_t a2, uint32_t a3,
                                        uint32_t b0, uint32_t b1)
{
    asm volatile(
        "mma.sync.aligned.m16n8k16.row.col.f32.f16.f16.f32 "
        "{%0,%1,%2,%3}, {%4,%5,%6,%7}, {%8,%9}, {%0,%1,%2,%3};"
        : "+f"(c[0]), "+f"(c[1]), "+f"(c[2]), "+f"(c[3])
        : "r"(a0), "r"(a1), "r"(a2), "r"(a3), "r"(b0), "r"(b1));
}
__device__ __forceinline__ uint32_t packh2(float a, float b) {
    __half2 h = __floats2half2_rn(a, b);
    return *(uint32_t*)&h;
}
// merge partial logsumexp (m2,s2) into (m,s)
__device__ __forceinline__ void lse_merge(float& m, float& s, float m2, float s2) {
    const float M = fmaxf(m, m2);
    s = s * __expf(m - M) + s2 * __expf(m2 - M);
    m = M;
}

// ============ fp16 GEMM core: 128x128 tile, BK=64, 3-stage, occupancy 2 ============
#define FPITCH 144
#define FARR (128 * FPITCH)          // 18432
#define FSTAGE (2 * FARR)            // 36864
#define FSMEM (3 * FSTAGE)           // 110592
#define FOFF_A 0
#define FOFF_B FARR

#define GEMM_F16_MAINLOOP(Aptr, Bptr, Kdim)                                        \
    const uint32_t aRow = (uint32_t)((wm + (lid & 15)) * FPITCH + ((lid >> 4) << 4)); \
    const uint32_t bRow = (uint32_t)((wn + (lid & 7) + ((lid >> 4) << 3)) * FPITCH    \
                                     + (((lid >> 3) & 1) << 4));                      \
    float acc[4][4][4];                                                            \
    _Pragma("unroll")                                                              \
    for (int i = 0; i < 4; i++)                                                    \
        _Pragma("unroll")                                                          \
        for (int j = 0; j < 4; j++)                                                \
            _Pragma("unroll")                                                      \
            for (int q = 0; q < 4; q++) acc[i][j][q] = 0.0f;                       \
    auto load_stage = [&](int slot, int chunk) {                                   \
        const int k0 = chunk << 6;                                                 \
        const uint32_t st = sbase + slot * FSTAGE;                                 \
        _Pragma("unroll")                                                          \
        for (int i = 0; i < 4; i++) {                                              \
            const int u = i * 256 + tid;                                           \
            const int r = u >> 3, cc = u & 7;                                      \
            const uint32_t sa = st + r * FPITCH + cc * 16;                         \
            cp16(sa + FOFF_A, (Aptr) + (size_t)(bm + r) * (Kdim) + k0 + cc * 8);   \
            cp16(sa + FOFF_B, (Bptr) + (size_t)(bn + r) * (Kdim) + k0 + cc * 8);   \
        }                                                                          \
    };                                                                             \
    load_stage(0, 0);                                                              \
    asm volatile("cp.async.commit_group;");                                        \
    load_stage(1, 1);                                                              \
    asm volatile("cp.async.commit_group;");                                        \
    const int nchunks = (Kdim) >> 6;                                               \
    for (int c = 0; c < nchunks; c++) {                                            \
        if (c < nchunks - 1) asm volatile("cp.async.wait_group 1;");               \
        else                 asm volatile("cp.async.wait_group 0;");               \
        __syncthreads();                                                           \
        if (c + 2 < nchunks) {                                                     \
            load_stage((c + 2) % 3, c + 2);                                        \
            asm volatile("cp.async.commit_group;");                                \
        }                                                                          \
        const uint32_t stg = sbase + (c % 3) * FSTAGE;                             \
        _Pragma("unroll")                                                          \
        for (int ks = 0; ks < 4; ks++) {                                           \
            const uint32_t ko = (uint32_t)(ks * 32);                               \
            uint32_t Af[4][4];                                                     \
            _Pragma("unroll")                                                      \
            for (int mt = 0; mt < 4; mt++) {                                       \
                const uint32_t ra = stg + FOFF_A + aRow + ko                       \
                                    + (uint32_t)(mt * 16 * FPITCH);                \
                LDSM_X4(Af[mt][0], Af[mt][1], Af[mt][2], Af[mt][3], ra);           \
            }                                                                      \
            uint32_t Bf[4][2];                                                     \
            {                                                                      \
                const uint32_t rb0 = stg + FOFF_B + bRow + ko;                     \
                const uint32_t rb1 = rb0 + (uint32_t)(16 * FPITCH);                \
                LDSM_X4(Bf[0][0], Bf[0][1], Bf[1][0], Bf[1][1], rb0);              \
                LDSM_X4(Bf[2][0], Bf[2][1], Bf[3][0], Bf[3][1], rb1);              \
            }                                                                      \
            _Pragma("unroll")                                                      \
            for (int mt = 0; mt < 4; mt++)                                         \
                _Pragma("unroll")                                                  \
                for (int nt = 0; nt < 4; nt++)                                     \
                    mma_f16(acc[mt][nt], Af[mt][0], Af[mt][1], Af[mt][2],          \
                            Af[mt][3], Bf[nt][0], Bf[nt][1]);                      \
        }                                                                          \
    }

// ---- QKV projection: C -> fp16 head-major q/k/v with direct bias ----
__global__ __launch_bounds__(256, 2)
void k_gemm_qkv16(const __half* __restrict__ A, const __half* __restrict__ B,
                  const float* __restrict__ bq, const float* __restrict__ bk,
                  const float* __restrict__ bv)
{
    extern __shared__ char smem[];
    const uint32_t sbase = smem_to_u32(smem);
    const int tid = threadIdx.x;
    const int wid = tid >> 5, lid = tid & 31;
    const int g = lid >> 2, tig = lid & 3;
    const int wm = (wid >> 2) * 64;
    const int wn = (wid & 3) * 32;
    const int bm = blockIdx.x * 128;
    const int bn = blockIdx.y * 128;

    GEMM_F16_MAINLOOP(A, B, DD)

    #pragma unroll
    for (int mt = 0; mt < 4; mt++) {
        const int row = bm + wm + mt * 16 + g;     // token
        const int b_ = row >> 10, t_ = row & 1023;
        #pragma unroll
        for (int nt = 0; nt < 4; nt++) {
            const int col = bn + wn + nt * 8 + tig * 2;
            const int sel = col >> 10, hc = col & 1023;
            const float* bsrc = (sel == 0) ? bq : (sel == 1) ? bk : bv;
            const float b0 = bsrc[hc], b1 = bsrc[hc + 1];
            const int h = hc >> 6, dk = hc & 63;
            __half* dst = (sel == 0) ? g_q16 : (sel == 1) ? g_k16 : g_v16;
            const size_t o0 = ((size_t)(b_ * HH + h) * TT + t_) * DKK + dk;
            *(__half2*)(dst + o0) =
                __floats2half2_rn(acc[mt][nt][0] + b0, acc[mt][nt][1] + b1);
            *(__half2*)(dst + o0 + 8 * DKK) =
                __floats2half2_rn(acc[mt][nt][2] + b0, acc[mt][nt][3] + b1);
        }
    }
}

// ---- Logits GEMM: C fp32 (+ streaming-store hint) + fused loss partials ----
__global__ __launch_bounds__(256, 2)
void k_gemm_f16(const __half* __restrict__ A, const __half* __restrict__ B,
                float* __restrict__ C, const float* __restrict__ bias)
{
    extern __shared__ char smem[];
    const uint32_t sbase = smem_to_u32(smem);
    const int tid = threadIdx.x;
    const int wid = tid >> 5, lid = tid & 31;
    const int g = lid >> 2, tig = lid & 3;
    const int wm = (wid >> 2) * 64;
    const int wn = (wid & 3) * 32;
    const int bm = blockIdx.x * 128;    // M fastest -> wave shares B tile
    const int bn = blockIdx.y * 128;

    GEMM_F16_MAINLOOP(A, B, DD)

    // epilogue: store logits (streaming) and accumulate per-row logsumexp partials
    __syncthreads();                    // smem stages are dead; reuse for partials
    float2* part = (float2*)smem;       // [4 col-parts][128 rows]
    const int cpart = wid & 3;

    #pragma unroll
    for (int mt = 0; mt < 4; mt++) {
        const int lr = wm + mt * 16 + g;         // CTA-local row
        const int row = bm + lr;
        float m0 = -INFINITY, s0 = 0.0f, m1 = -INFINITY, s1 = 0.0f;
        #pragma unroll
        for (int nt = 0; nt < 4; nt++) {
            const int col = bn + wn + nt * 8 + tig * 2;
            const float b0 = bias[col], b1 = bias[col + 1];
            const float v00 = acc[mt][nt][0] + b0, v01 = acc[mt][nt][1] + b1;
            const float v10 = acc[mt][nt][2] + b0, v11 = acc[mt][nt][3] + b1;
            stg_cs_v2(C + (size_t)row * VV + col, v00, v01);
            stg_cs_v2(C + (size_t)(row + 8) * VV + col, v10, v11);
            // online partials
            const float mx0 = fmaxf(v00, v01);
            if (mx0 > m0) { s0 *= __expf(m0 - mx0); m0 = mx0; }
            s0 += __expf(v00 - m0) + __expf(v01 - m0);
            const float mx1 = fmaxf(v10, v11);
            if (mx1 > m1) { s1 *= __expf(m1 - mx1); m1 = mx1; }
            s1 += __expf(v10 - m1) + __expf(v11 - m1);
        }
        // reduce over the 4 quad lanes (tig)
        #pragma unroll
        for (int w = 1; w < 4; w <<= 1) {
            lse_merge(m0, s0, __shfl_xor_sync(0xFFFFFFFF, m0, w),
                              __shfl_xor_sync(0xFFFFFFFF, s0, w));
            lse_merge(m1, s1, __shfl_xor_sync(0xFFFFFFFF, m1, w),
                              __shfl_xor_sync(0xFFFFFFFF, s1, w));
        }
        if (tig == 0) {
            part[cpart * 128 + lr]     = make_float2(m0, s0);
            part[cpart * 128 + lr + 8] = make_float2(m1, s1);
        }
    }
    __syncthreads();

    if (tid < 128) {                    // one thread per CTA row
        float2 p = part[tid];
        float m = p.x, s = p.y;
        #pragma unroll
        for (int cp = 1; cp < 4; cp++) {
            const float2 q = part[cp * 128 + tid];
            lse_merge(m, s, q.x, q.y);
        }
        g_pml[(size_t)(bm + tid) * NBLK + blockIdx.y] = make_float2(m, s);
    }
}

// ---------------- embed -> fp16 ----------------
__global__ void k_embed16(const int* __restrict__ ids,
                          const float* __restrict__ tok_emb,
                          const float* __restrict__ pos_emb)
{
    int tok = blockIdx.x;
    int t = tok & (TT - 1);
    int v = ids[tok];
    const float* te = tok_emb + (size_t)v * DD;
    const float* pe = pos_emb + (size_t)t * DD;
    __half* xo = g_x16 + (size_t)tok * DD;
    for (int d = threadIdx.x; d < DD; d += blockDim.x)
        xo[d] = __float2half(te[d] * 32.0f + pe[d]);
}

// ---------------- repack Wq/Wk/Wv via smem transpose -> K-major fp16 ----------------
__global__ void k_repack_wqkvT(const float* __restrict__ Wq,
                               const float* __restrict__ Wk,
                               const float* __restrict__ Wv)
{
    __shared__ float s[32][33];
    const int sh = blockIdx.x;
    const int sel = sh >> 4, h = sh & 15;
    const int d0 = blockIdx.y * 32;
    const int k0 = blockIdx.z * 32;
    const float* src = (sel == 0) ? Wq : (sel == 1) ? Wk : Wv;
    const float* base = src + (size_t)h * (DD * DKK);
    const int tx = threadIdx.x, ty = threadIdx.y;
    #pragma unroll
    for (int i = 0; i < 4; i++)
        s[ty + i * 8][tx] = base[(size_t)(d0 + ty + i * 8) * DKK + k0 + tx];
    __syncthreads();
    #pragma unroll
    for (int i = 0; i < 4; i++) {
        const int k = k0 + ty + i * 8;
        const int n = sel * 1024 + h * 64 + k;
        const int d = d0 + tx;
        g_w16[(size_t)n * DD + d] = __float2half(s[tx][ty + i * 8]);
    }
}

// ---------------- transpose Wo [1024, 32000] -> fp16 [32000, 1024] ----------------
__global__ void k_woT(const float* __restrict__ Wo)
{
    __shared__ float s[32][33];
    int v0 = blockIdx.x * 32, d0 = blockIdx.y * 32;
    int tx = threadIdx.x, ty = threadIdx.y;  // (32, 8)
    #pragma unroll
    for (int i = 0; i < 4; i++)
        s[ty + i * 8][tx] = Wo[(size_t)(d0 + ty + i * 8) * VV + v0 + tx];
    __syncthreads();
    #pragma unroll
    for (int i = 0; i < 4; i++) {
        int v = v0 + ty + i * 8;
        int d = d0 + tx;
        g_hb[(size_t)v * DD + d] = __float2half(s[tx][ty + i * 8]);
    }
}

// ---------------- tensor-core flash attention (4-stage KV pipeline) ----------------
#define PL 144
#define FLK_BYTES (64 * PL)                  // 9216
#define FLQ_BYTES (128 * PL)                 // 18432
#define FL2_STAGE (2 * FLK_BYTES)            // 18432
#define FL2_SMEM (FLQ_BYTES + 4 * FL2_STAGE) // 92160

__global__ __launch_bounds__(256, 2)
void k_flash_tc()
{
    extern __shared__ char smem[];
    const uint32_t sbase = smem_to_u32(smem);
    const int tid = threadIdx.x;
    const int w = tid >> 5, lid = tid & 31;
    const int g = lid >> 2, tig = lid & 3;
    const int tT = 7 - (int)blockIdx.x;      // heavy tiles first
    const int bh = blockIdx.y;
    const int t0 = tT * 128;
    const int wr = w * 16;
    const int nb = t0 / 64 + 2;

    const __half* gq = g_q16 + (size_t)bh * TT * DKK;
    const __half* gk = g_k16 + (size_t)bh * TT * DKK;
    const __half* gv = g_v16 + (size_t)bh * TT * DKK;

    auto load_kv = [&](int slot, int s0) {
        const uint32_t st = sbase + FLQ_BYTES + slot * FL2_STAGE;
        #pragma unroll
        for (int i = 0; i < 2; i++) {
            int u = i * 256 + tid;
            int r = u >> 3, cc = u & 7;
            uint32_t sa = st + r * PL + cc * 16;
            cp16(sa, gk + (size_t)(s0 + r) * DKK + cc * 8);
            cp16(sa + FLK_BYTES, gv + (size_t)(s0 + r) * DKK + cc * 8);
        }
    };

    // Q load (grouped with first KV block)
    #pragma unroll
    for (int i = 0; i < 4; i++) {
        int u = i * 256 + tid;
        int r = u >> 3, cc = u & 7;
        cp16(sbase + r * PL + cc * 16, gq + (size_t)(t0 + r) * DKK + cc * 8);
    }
    // prime up to 3 stages
    int P = (nb < 3) ? nb : 3;          // next block to prefetch
    for (int p = 0; p < P; p++) {
        load_kv(p, p * 64);
        asm volatile("cp.async.commit_group;");
    }

    const uint32_t aoff = (uint32_t)((lid & 15) * PL + ((lid >> 4) << 4));
    const uint32_t boff = (uint32_t)(((lid & 7) + ((lid >> 4) << 3)) * PL
                                     + (((lid >> 3) & 1) << 4));
    const uint32_t voff = aoff;

    float O[8][4];
    #pragma unroll
    for (int j = 0; j < 8; j++)
        #pragma unroll
        for (int q = 0; q < 4; q++) O[j][q] = 0.0f;
    float m0 = -INFINITY, m1 = -INFINITY, l0 = 0.0f, l1 = 0.0f;

    const int trow0 = t0 + wr + g;
    const int trow1 = trow0 + 8;

    for (int c = 0; c < nb; c++) {
        const int s0 = c * 64;
        const int out = P - c - 1;      // groups allowed to stay in flight
        if (out >= 2)      asm volatile("cp.async.wait_group 2;");
        else if (out == 1) asm volatile("cp.async.wait_group 1;");
        else               asm volatile("cp.async.wait_group 0;");
        __syncthreads();
        if (P < nb) {
            load_kv(P & 3, P * 64);
            asm volatile("cp.async.commit_group;");
            P++;
        }

        if (s0 <= t0 + wr + 15) {
            const uint32_t stK = sbase + FLQ_BYTES + (c & 3) * FL2_STAGE;
            const uint32_t stV = stK + FLK_BYTES;

            uint32_t Af[4][4];
            #pragma unroll
            for (int ks = 0; ks < 4; ks++)
                LDSM_X4(Af[ks][0], Af[ks][1], Af[ks][2], Af[ks][3],
                        sbase + (uint32_t)(wr * PL) + aoff + ks * 32);
            float S[8][4];
            #pragma unroll
            for (int j = 0; j < 8; j++)
                #pragma unroll
                for (int q = 0; q < 4; q++) S[j][q] = 0.0f;
            #pragma unroll
            for (int ks = 0; ks < 4; ks++) {
                uint32_t Bf[8][2];
                #pragma unroll
                for (int jp = 0; jp < 4; jp++)
                    LDSM_X4(Bf[2 * jp][0], Bf[2 * jp][1], Bf[2 * jp + 1][0], Bf[2 * jp + 1][1],
                            stK + boff + (uint32_t)(jp * 16 * PL) + ks * 32);
                #pragma unroll
                for (int j = 0; j < 8; j++)
                    mma_f16(S[j], Af[ks][0], Af[ks][1], Af[ks][2], Af[ks][3],
                            Bf[j][0], Bf[j][1]);
            }

            const bool domask = (s0 + 63 > t0 + wr);
            #pragma unroll
            for (int j = 0; j < 8; j++) {
                #pragma unroll
                for (int q = 0; q < 4; q++) S[j][q] *= 0.125f;
                if (domask) {
                    const int sc = s0 + j * 8 + tig * 2;
                    if (sc     > trow0) S[j][0] = -INFINITY;
                    if (sc + 1 > trow0) S[j][1] = -INFINITY;
                    if (sc     > trow1) S[j][2] = -INFINITY;
                    if (sc + 1 > trow1) S[j][3] = -INFINITY;
                }
            }

            float rm0 = -INFINITY, rm1 = -INFINITY;
            #pragma unroll
            for (int j = 0; j < 8; j++) {
                rm0 = fmaxf(rm0, fmaxf(S[j][0], S[j][1]));
                rm1 = fmaxf(rm1, fmaxf(S[j][2], S[j][3]));
            }
            rm0 = fmaxf(rm0, __shfl_xor_sync(0xFFFFFFFF, rm0, 1));
            rm0 = fmaxf(rm0, __shfl_xor_sync(0xFFFFFFFF, rm0, 2));
            rm1 = fmaxf(rm1, __shfl_xor_sync(0xFFFFFFFF, rm1, 1));
            rm1 = fmaxf(rm1, __shfl_xor_sync(0xFFFFFFFF, rm1, 2));
            const float mn0 = fmaxf(m0, rm0), mn1 = fmaxf(m1, rm1);
            const float fac0 = __expf(m0 - mn0), fac1 = __expf(m1 - mn1);
            float rs0 = 0.0f, rs1 = 0.0f;
            #pragma unroll
            for (int j = 0; j < 8; j++) {
                S[j][0] = __expf(S[j][0] - mn0);
                S[j][1] = __expf(S[j][1] - mn0);
                S[j][2] = __expf(S[j][2] - mn1);
                S[j][3] = __expf(S[j][3] - mn1);
                rs0 += S[j][0] + S[j][1];
                rs1 += S[j][2] + S[j][3];
            }
            rs0 += __shfl_xor_sync(0xFFFFFFFF, rs0, 1);
            rs0 += __shfl_xor_sync(0xFFFFFFFF, rs0, 2);
            rs1 += __shfl_xor_sync(0xFFFFFFFF, rs1, 1);
            rs1 += __shfl_xor_sync(0xFFFFFFFF, rs1, 2);
            l0 = l0 * fac0 + rs0;  m0 = mn0;
            l1 = l1 * fac1 + rs1;  m1 = mn1;
            #pragma unroll
            for (int j = 0; j < 8; j++) {
                O[j][0] *= fac0; O[j][1] *= fac0;
                O[j][2] *= fac1; O[j][3] *= fac1;
            }

            uint32_t Pa[4][4];
            #pragma unroll
            for (int ks = 0; ks < 4; ks++) {
                const int j0 = 2 * ks, j1 = 2 * ks + 1;
                Pa[ks][0] = packh2(S[j0][0], S[j0][1]);
                Pa[ks][1] = packh2(S[j0][2], S[j0][3]);
                Pa[ks][2] = packh2(S[j1][0], S[j1][1]);
                Pa[ks][3] = packh2(S[j1][2], S[j1][3]);
            }
            #pragma unroll
            for (int ks = 0; ks < 4; ks++) {
                #pragma unroll
                for (int dp = 0; dp < 4; dp++) {
                    uint32_t Vb[4];
                    LDSM_X4_T(Vb[0], Vb[1], Vb[2], Vb[3],
                              stV + voff + (uint32_t)(ks * 16 * PL) + dp * 32);
                    mma_f16(O[2 * dp],     Pa[ks][0], Pa[ks][1], Pa[ks][2], Pa[ks][3],
                            Vb[0], Vb[1]);
                    mma_f16(O[2 * dp + 1], Pa[ks][0], Pa[ks][1], Pa[ks][2], Pa[ks][3],
                            Vb[2], Vb[3]);
                }
            }
        }
    }

    const float inv0 = 1.0f / l0, inv1 = 1.0f / l1;
    const int b_ = bh >> 4, h_ = bh & 15;
    __half* o0 = g_ha + (size_t)(b_ * TT + trow0) * DD + h_ * 64;
    __half* o1 = g_ha + (size_t)(b_ * TT + trow1) * DD + h_ * 64;
    #pragma unroll
    for (int j = 0; j < 8; j++) {
        const int col = j * 8 + tig * 2;
        *(__half2*)(o0 + col) = __floats2half2_rn(O[j][0] * inv0, O[j][1] * inv0);
        *(__half2*)(o1 + col) = __floats2half2_rn(O[j][2] * inv1, O[j][3] * inv1);
    }
}

// ---------------- loss: reduce per-block partials (8 MB instead of 524 MB) ----------------
__global__ __launch_bounds__(256)
void k_loss_rows(const float* __restrict__ logits, const int* __restrict__ targets)
{
    const int r = blockIdx.x;
    const int tid = threadIdx.x;
    __shared__ float sm[256], ss[256];

    float m = -INFINITY, s = 0.0f;
    if (tid < NBLK) {
        const float2 p = g_pml[(size_t)r * NBLK + tid];
        m = p.x; s = p.y;
    }
    sm[tid] = m; ss[tid] = s;
    __syncthreads();
    for (int k = 128; k > 0; k >>= 1) {
        if (tid < k) {
            float m1 = sm[tid], s1 = ss[tid];
            float m2 = sm[tid + k], s2 = ss[tid + k];
            float M = fmaxf(m1, m2);
            sm[tid] = M;
            ss[tid] = s1 * __expf(m1 - M) + s2 * __expf(m2 - M);
        }
        __syncthreads();
    }
    if (tid == 0) {
        int tgt = targets[r];
        float logp = logits[(size_t)r * VV + tgt] - sm[0] - __logf(ss[0]);
        g_rowloss[r] = -logp;
    }
}

__global__ void k_loss_final(float* out)
{
    const int tid = threadIdx.x;
    __shared__ float red[256];
    float s = 0.0f;
    for (int i = tid; i < BT; i += 256) s += g_rowloss[i];
    red[tid] = s; __syncthreads();
    for (int k = 128; k > 0; k >>= 1) {
        if (tid < k) red[tid] += red[tid + k];
        __syncthreads();
    }
    if (tid == 0) out[0] = red[0] * (1.0f / BT);
}

// ---------------- launch ----------------
extern "C" void kernel_launch(void* const* d_in, const int* in_sizes, int n_in,
                              void* d_out, int out_size)
{
    const int*   ids     = (const int*)  d_in[0];
    const int*   targets = (const int*)  d_in[1];
    const float* tok_emb = (const float*)d_in[2];
    const float* pos_emb = (const float*)d_in[3];
    const float* Wq      = (const float*)d_in[4];
    const float* bq      = (const float*)d_in[5];
    const float* Wk      = (const float*)d_in[6];
    const float* bk      = (const float*)d_in[7];
    const float* Wv      = (const float*)d_in[8];
    const float* bv      = (const float*)d_in[9];
    const float* Wo      = (const float*)d_in[10];
    const float* bo      = (const float*)d_in[11];
    float* out = (float*)d_out;

    __half *px16, *pw16, *pha, *phb;
    cudaGetSymbolAddress((void**)&px16, g_x16);
    cudaGetSymbolAddress((void**)&pw16, g_w16);
    cudaGetSymbolAddress((void**)&pha,  g_ha);
    cudaGetSymbolAddress((void**)&phb,  g_hb);

    cudaFuncSetAttribute(k_gemm_qkv16, cudaFuncAttributeMaxDynamicSharedMemorySize, FSMEM);
    cudaFuncSetAttribute(k_gemm_f16,   cudaFuncAttributeMaxDynamicSharedMemorySize, FSMEM);
    cudaFuncSetAttribute(k_flash_tc,   cudaFuncAttributeMaxDynamicSharedMemorySize, FL2_SMEM);

    // 1. embed + weight repacks (all fp16)
    k_embed16<<<BT, 256>>>(ids, tok_emb, pos_emb);
    k_repack_wqkvT<<<dim3(48, 32, 2), dim3(32, 8)>>>(Wq, Wk, Wv);
    k_woT<<<dim3(VV / 32, DD / 32), dim3(32, 8)>>>(Wo);

    // 2. QKV projection (fp16) -> fp16 head-major q/k/v (direct bias)
    k_gemm_qkv16<<<dim3(BT / 128, N3 / 128), 256, FSMEM>>>(px16, pw16, bq, bk, bv);

    // 3. tensor-core flash attention (emits fp16 A for the logits GEMM)
    k_flash_tc<<<dim3(8, BHN), 256, FL2_SMEM>>>();

    // 4. logits (fp16) + fused loss partials
    k_gemm_f16<<<dim3(BT / 128, VV / 128), 256, FSMEM>>>(pha, phb, out, bo);

    // 5. loss (partials reduce + mean)
    if ((long long)out_size > BTV) {
        k_loss_rows<<<BT, 256>>>(out, targets);
        k_loss_final<<<1, 256>>>(out + BTV);
    }
}